// round 9
// baseline (speedup 1.0000x reference)
#include <cuda_runtime.h>
#include <cuda_bf16.h>
#include <cstdint>
#include <math.h>

// ---------------------------------------------------------------------------
// Problem constants
// ---------------------------------------------------------------------------
#define S_LEN   2048
#define HIDDEN  3072
#define NH      32
#define NHK     8
#define GQ      4
#define HD      96
#define BLK     64
#define NB      32
#define GH      128
#define OP      4608
#define KOFF    3072
#define VOFF    3840
#define K2H     (HIDDEN / 2)

// ---------------------------------------------------------------------------
// Scratch (device globals; no allocation allowed)
// ---------------------------------------------------------------------------
__device__ float g_qkv [S_LEN * OP];
__device__ float g_q   [S_LEN * NH  * HD];
__device__ float g_k   [S_LEN * NHK * HD];
__device__ float g_qpool[NB * NHK * HD];
__device__ float g_kpool[NB * NHK * 2 * HD];
__device__ float g_qgate[NB * NHK * GH];
__device__ float g_kgate[NB * NHK * GH];
__device__ int   g_maskbuf[NHK * NB * NB];

// bf16 hi/lo packed operands (k-pairs packed into one uint32)
__device__ uint32_t g_ah [S_LEN * K2H];       // A hi (hs, then attn out)
__device__ uint32_t g_al [S_LEN * K2H];       // A lo
__device__ uint32_t g_wqh[K2H * OP];
__device__ uint32_t g_wql[K2H * OP];
__device__ uint32_t g_woh[K2H * HIDDEN];
__device__ uint32_t g_wol[K2H * HIDDEN];

// ---------------------------------------------------------------------------
// bf16 hi/lo split helpers
// ---------------------------------------------------------------------------
__device__ __forceinline__ void bsplit(float x, uint32_t& h, uint32_t& l)
{
    __nv_bfloat16 hb = __float2bfloat16(x);
    float hf = __bfloat162float(hb);
    __nv_bfloat16 lb = __float2bfloat16(x - hf);
    h = (uint32_t)__bfloat16_as_ushort(hb);
    l = (uint32_t)__bfloat16_as_ushort(lb);
}

__device__ __forceinline__ void split1(float x, uint16_t& h, uint16_t& l)
{
    __nv_bfloat16 hb = __float2bfloat16(x);
    h = __bfloat16_as_ushort(hb);
    l = __bfloat16_as_ushort(__float2bfloat16(x - __bfloat162float(hb)));
}

__device__ __forceinline__ uint32_t split2(float x, float y, uint32_t& lo)
{
    __nv_bfloat16 hx = __float2bfloat16(x), hy = __float2bfloat16(y);
    float rx = x - __bfloat162float(hx), ry = y - __bfloat162float(hy);
    __nv_bfloat16 lx = __float2bfloat16(rx), ly = __float2bfloat16(ry);
    lo = (uint32_t)__bfloat16_as_ushort(lx) | ((uint32_t)__bfloat16_as_ushort(ly) << 16);
    return (uint32_t)__bfloat16_as_ushort(hx) | ((uint32_t)__bfloat16_as_ushort(hy) << 16);
}

// Pack A (row-major M x K): word i = (x[2i], x[2i+1]) along k
__global__ void packA_kernel(const float* __restrict__ in,
                             uint32_t* __restrict__ hi, uint32_t* __restrict__ lo,
                             int total2)
{
    int i = blockIdx.x * blockDim.x + threadIdx.x;
    if (i >= total2) return;
    float2 v = ((const float2*)in)[i];
    uint32_t h0, l0, h1, l1;
    bsplit(v.x, h0, l0);
    bsplit(v.y, h1, l1);
    hi[i] = h0 | (h1 << 16);
    lo[i] = l0 | (l1 << 16);
}

// Pack B (row-major K x N): out[k2][n] = (B[2k2][n], B[2k2+1][n])
__global__ void packB_kernel(const float* __restrict__ in,
                             uint32_t* __restrict__ hi, uint32_t* __restrict__ lo,
                             int N, int total)
{
    int i = blockIdx.x * blockDim.x + threadIdx.x;
    if (i >= total) return;
    int k2 = i / N, n = i - k2 * N;
    float x0 = in[(size_t)(2 * k2) * N + n];
    float x1 = in[(size_t)(2 * k2 + 1) * N + n];
    uint32_t h0, l0, h1, l1;
    bsplit(x0, h0, l0);
    bsplit(x1, h1, l1);
    hi[i] = h0 | (h1 << 16);
    lo[i] = l0 | (l1 << 16);
}

// ---------------------------------------------------------------------------
// bf16x3 tensor-core GEMM, fat-tile edition.
// Block tile 256(M) x 128(N), BK=16 (8 packed words), 256 threads,
// warp grid 4(m) x 2(n), warp tile 64x64 -> 2.67 B smem traffic per MMA
// (vs 4 B for the 64x32 tile). 3 MMAs per k16 (hi*hi + hi*lo + lo*hi).
// Requires M%256==0, N%128==0, K%16==0.
// ---------------------------------------------------------------------------
#define PADA 264   // A smem row stride in words (256 + 8)
#define PADB 136   // B smem row stride in words (128 + 8)

#define MMA_BF16(CC, A0, A1, A2, A3, B0, B1)                                   \
    asm volatile(                                                              \
        "mma.sync.aligned.m16n8k16.row.col.f32.bf16.bf16.f32 "                 \
        "{%0,%1,%2,%3}, {%4,%5,%6,%7}, {%8,%9}, {%0,%1,%2,%3};"                \
        : "+f"(CC[0]), "+f"(CC[1]), "+f"(CC[2]), "+f"(CC[3])                   \
        : "r"(A0), "r"(A1), "r"(A2), "r"(A3), "r"(B0), "r"(B1))

__global__ __launch_bounds__(256, 1)
void bf16x3_gemm(const uint32_t* __restrict__ Agh, const uint32_t* __restrict__ Agl,
                 const uint32_t* __restrict__ Bgh, const uint32_t* __restrict__ Bgl,
                 float* __restrict__ C, int M, int N, int K2)
{
    __shared__ __align__(16) uint32_t Ah[2][8][PADA], Al[2][8][PADA];
    __shared__ __align__(16) uint32_t Bh[2][8][PADB], Bl[2][8][PADB];

    const int tid  = threadIdx.x;
    const int bn   = blockIdx.x, bm = blockIdx.y;
    const int warp = tid >> 5,  lane = tid & 31;
    const int wm   = warp >> 1, wn   = warp & 1;    // 4 x 2 warp grid
    const int gid  = lane >> 2, tig  = lane & 3;

    // Global load mapping: A 256 rows x 8 words (one row per thread),
    // B 8 rows x 128 words.
    const int a_r = tid;
    const int b_r = tid >> 5, b_c = (tid & 31) * 4;

    const uint32_t* Aph = Agh + (size_t)(bm * 256 + a_r) * K2;
    const uint32_t* Apl = Agl + (size_t)(bm * 256 + a_r) * K2;
    const uint32_t* Bph = Bgh + (size_t)b_r * N + bn * 128 + b_c;
    const uint32_t* Bpl = Bgl + (size_t)b_r * N + bn * 128 + b_c;

    uint4 rah0 = *(const uint4*)Aph;
    uint4 rah1 = *(const uint4*)(Aph + 4);
    uint4 ral0 = *(const uint4*)Apl;
    uint4 ral1 = *(const uint4*)(Apl + 4);
    uint4 rbh  = *(const uint4*)Bph;
    uint4 rbl  = *(const uint4*)Bpl;

    Ah[0][0][a_r] = rah0.x; Ah[0][1][a_r] = rah0.y;
    Ah[0][2][a_r] = rah0.z; Ah[0][3][a_r] = rah0.w;
    Ah[0][4][a_r] = rah1.x; Ah[0][5][a_r] = rah1.y;
    Ah[0][6][a_r] = rah1.z; Ah[0][7][a_r] = rah1.w;
    Al[0][0][a_r] = ral0.x; Al[0][1][a_r] = ral0.y;
    Al[0][2][a_r] = ral0.z; Al[0][3][a_r] = ral0.w;
    Al[0][4][a_r] = ral1.x; Al[0][5][a_r] = ral1.y;
    Al[0][6][a_r] = ral1.z; Al[0][7][a_r] = ral1.w;
    *(uint4*)&Bh[0][b_r][b_c] = rbh;
    *(uint4*)&Bl[0][b_r][b_c] = rbl;
    __syncthreads();

    float acc[4][8][4];
#pragma unroll
    for (int mt = 0; mt < 4; mt++)
#pragma unroll
        for (int nt = 0; nt < 8; nt++)
#pragma unroll
            for (int r = 0; r < 4; r++) acc[mt][nt][r] = 0.f;

    const int nst = K2 >> 3;
    for (int st = 0; st < nst; st++) {
        const int cur = st & 1;
        const bool more = (st + 1 < nst);
        if (more) {
            const uint32_t* Ap2h = Aph + (st + 1) * 8;
            const uint32_t* Ap2l = Apl + (st + 1) * 8;
            rah0 = *(const uint4*)Ap2h;
            rah1 = *(const uint4*)(Ap2h + 4);
            ral0 = *(const uint4*)Ap2l;
            ral1 = *(const uint4*)(Ap2l + 4);
            rbh  = *(const uint4*)(Bph + (size_t)(st + 1) * 8 * N);
            rbl  = *(const uint4*)(Bpl + (size_t)(st + 1) * 8 * N);
        }

#pragma unroll
        for (int ks = 0; ks < 2; ks++) {
            const int k0 = ks * 4;   // packed-word row base (4 words = k8)
            uint32_t bhf[8][2], blf[8][2];
#pragma unroll
            for (int nt = 0; nt < 8; nt++) {
                const int n0 = wn * 64 + nt * 8;
                bhf[nt][0] = Bh[cur][k0 + (tig >> 1) * 0 + tig][n0 + gid];
                bhf[nt][1] = Bh[cur][k0 + tig + 0][n0 + gid];   // placeholder, fixed below
            }
            // NOTE: correct fragment rows are k0+tig (first k8) and k0+4+tig is
            // out of range for ks=1; the packed layout is 8 rows of k-pairs:
            // k16 step ks uses rows [ks*4 .. ks*4+3] for k8 group 0 and ... 
            // -- rewritten explicitly below.
            (void)bhf; (void)blf;
            break;
        }

        // ---- fragment math (explicit, 8 packed rows = k16 x ... ) ----
        // Packed rows 0..7 hold k-pairs: row r covers k = {2r, 2r+1}.
        // m16n8k16 needs k16 = rows 0..7 split as: frag pair (row tig, row tig+4).
#pragma unroll
        for (int dummy = 0; dummy < 1; dummy++) {
            uint32_t bhf[8][2], blf[8][2];
#pragma unroll
            for (int nt = 0; nt < 8; nt++) {
                const int n0 = wn * 64 + nt * 8;
                bhf[nt][0] = Bh[cur][tig][n0 + gid];
                bhf[nt][1] = Bh[cur][tig + 4][n0 + gid];
                blf[nt][0] = Bl[cur][tig][n0 + gid];
                blf[nt][1] = Bl[cur][tig + 4][n0 + gid];
            }
#pragma unroll
            for (int mt = 0; mt < 4; mt++) {
                const int m0 = wm * 64 + mt * 16;
                uint32_t ah0 = Ah[cur][tig][m0 + gid];
                uint32_t ah1 = Ah[cur][tig][m0 + gid + 8];
                uint32_t ah2 = Ah[cur][tig + 4][m0 + gid];
                uint32_t ah3 = Ah[cur][tig + 4][m0 + gid + 8];
                uint32_t al0 = Al[cur][tig][m0 + gid];
                uint32_t al1 = Al[cur][tig][m0 + gid + 8];
                uint32_t al2 = Al[cur][tig + 4][m0 + gid];
                uint32_t al3 = Al[cur][tig + 4][m0 + gid + 8];
#pragma unroll
                for (int nt = 0; nt < 8; nt++) {
                    MMA_BF16(acc[mt][nt], ah0, ah1, ah2, ah3, bhf[nt][0], bhf[nt][1]);
                    MMA_BF16(acc[mt][nt], ah0, ah1, ah2, ah3, blf[nt][0], blf[nt][1]);
                    MMA_BF16(acc[mt][nt], al0, al1, al2, al3, bhf[nt][0], bhf[nt][1]);
                }
            }
        }

        if (more) {
            const int nxt = cur ^ 1;
            Ah[nxt][0][a_r] = rah0.x; Ah[nxt][1][a_r] = rah0.y;
            Ah[nxt][2][a_r] = rah0.z; Ah[nxt][3][a_r] = rah0.w;
            Ah[nxt][4][a_r] = rah1.x; Ah[nxt][5][a_r] = rah1.y;
            Ah[nxt][6][a_r] = rah1.z; Ah[nxt][7][a_r] = rah1.w;
            Al[nxt][0][a_r] = ral0.x; Al[nxt][1][a_r] = ral0.y;
            Al[nxt][2][a_r] = ral0.z; Al[nxt][3][a_r] = ral0.w;
            Al[nxt][4][a_r] = ral1.x; Al[nxt][5][a_r] = ral1.y;
            Al[nxt][6][a_r] = ral1.z; Al[nxt][7][a_r] = ral1.w;
            *(uint4*)&Bh[nxt][b_r][b_c] = rbh;
            *(uint4*)&Bl[nxt][b_r][b_c] = rbl;
            __syncthreads();
        }
    }

    // Epilogue
#pragma unroll
    for (int mt = 0; mt < 4; mt++) {
        const int row = bm * 256 + wm * 64 + mt * 16 + gid;
#pragma unroll
        for (int nt = 0; nt < 8; nt++) {
            const int col = bn * 128 + wn * 64 + nt * 8 + tig * 2;
            *(float2*)&C[(size_t)row * N + col] =
                make_float2(acc[mt][nt][0], acc[mt][nt][1]);
            *(float2*)&C[(size_t)(row + 8) * N + col] =
                make_float2(acc[mt][nt][2], acc[mt][nt][3]);
        }
    }
}

// ---------------------------------------------------------------------------
// RoPE
// ---------------------------------------------------------------------------
__global__ void rope_kernel(const float* __restrict__ cosb,
                            const float* __restrict__ sinb)
{
    const int total = S_LEN * (NH + NHK) * HD;
    int idx = blockIdx.x * blockDim.x + threadIdx.x;
    if (idx >= total) return;
    int d = idx % HD;
    int h = (idx / HD) % (NH + NHK);
    int s = idx / (HD * (NH + NHK));
    const float* row = g_qkv + (size_t)s * OP;
    float c  = cosb[s * HD + d];
    float sn = sinb[s * HD + d];
    if (h < NH) {
        int base = h * HD;
        float x = row[base + d];
        float r = (d < HD / 2) ? -row[base + d + HD / 2] : row[base + d - HD / 2];
        g_q[(size_t)s * (NH * HD) + h * HD + d] = x * c + r * sn;
    } else {
        int hk = h - NH;
        int base = KOFF + hk * HD;
        float x = row[base + d];
        float r = (d < HD / 2) ? -row[base + d + HD / 2] : row[base + d - HD / 2];
        g_k[(size_t)s * (NHK * HD) + hk * HD + d] = x * c + r * sn;
    }
}

// ---------------------------------------------------------------------------
// Pooling / gates / mask (unchanged)
// ---------------------------------------------------------------------------
__global__ void pool_kernel()
{
    int nb = blockIdx.x, hk = blockIdx.y, d = threadIdx.x;
    float ksum = 0.f, kmax = -3.0e38f, qsum = 0.f;
#pragma unroll 4
    for (int t = 0; t < BLK; t++) {
        const float* row = g_qkv + (size_t)(nb * BLK + t) * OP;
        float kv = row[KOFF + hk * HD + d];
        ksum += kv;
        kmax = fmaxf(kmax, kv);
#pragma unroll
        for (int g = 0; g < GQ; g++) qsum += row[(hk * GQ + g) * HD + d];
    }
    int bh = nb * NHK + hk;
    g_kpool[bh * (2 * HD) + d]      = ksum * (1.f / BLK);
    g_kpool[bh * (2 * HD) + HD + d] = kmax;
    g_qpool[bh * HD + d]            = qsum * (1.f / (BLK * GQ));
}

__global__ void gate_kernel(const float* __restrict__ gate_wq,
                            const float* __restrict__ gate_wk)
{
    int nb = blockIdx.x, hk = blockIdx.y, g = threadIdx.x;
    int bh = nb * NHK + hk;
    float qa = 0.f;
#pragma unroll 8
    for (int d = 0; d < HD; d++)
        qa += g_qpool[bh * HD + d] * gate_wq[d * GH + g];
    float ka = 0.f;
#pragma unroll 8
    for (int e = 0; e < 2 * HD; e++)
        ka += g_kpool[bh * (2 * HD) + e] * gate_wk[e * GH + g];
    g_qgate[bh * GH + g] = qa;
    g_kgate[bh * GH + g] = ka;
}

__global__ void mask_kernel()
{
    int qb = blockIdx.x, hk = blockIdx.y, kb = threadIdx.x;
    float l = -1e30f;
    if (kb <= qb) {
        float dot = 0.f;
#pragma unroll 8
        for (int g = 0; g < GH; g++)
            dot += g_qgate[(size_t)(qb * NHK + hk) * GH + g]
                 * g_kgate[(size_t)(kb * NHK + hk) * GH + g];
        l = dot * rsqrtf((float)GH);
    }
    float mx = l;
#pragma unroll
    for (int o = 16; o > 0; o >>= 1) mx = fmaxf(mx, __shfl_xor_sync(0xffffffffu, mx, o));
    float e = expf(l - mx);
    float sm = e;
#pragma unroll
    for (int o = 16; o > 0; o >>= 1) sm += __shfl_xor_sync(0xffffffffu, sm, o);
    float p = e / sm;
    int keep = ((p >= 0.03f) && (kb <= qb)) || (kb == qb);
    g_maskbuf[(hk * NB + qb) * NB + kb] = keep;
}

// ---------------------------------------------------------------------------
// Tensor-core block-sparse flash attention (unchanged from R7; fused epilogue
// writes the packed bf16 hi/lo A operand for the O projection).
// ---------------------------------------------------------------------------
#define QSTR 104
#define VSTR 72

#define OFF_QH  0
#define OFF_QL  13312
#define OFF_KH(b) (26624  + (b) * 13312)
#define OFF_KL(b) (53248  + (b) * 13312)
#define OFF_VH(b) (79872  + (b) * 13824)
#define OFF_VL(b) (107520 + (b) * 13824)
#define OFF_BL  135168
#define ATTN_SMEM 135304

#define LDSM4(R0, R1, R2, R3, ADDR)                                            \
    asm volatile("ldmatrix.sync.aligned.m8n8.x4.shared.b16 {%0,%1,%2,%3}, [%4];" \
                 : "=r"(R0), "=r"(R1), "=r"(R2), "=r"(R3) : "r"(ADDR))

#define MMAB(CC, A, B0, B1)                                                    \
    asm volatile(                                                              \
        "mma.sync.aligned.m16n8k16.row.col.f32.bf16.bf16.f32 "                 \
        "{%0,%1,%2,%3}, {%4,%5,%6,%7}, {%8,%9}, {%0,%1,%2,%3};"                \
        : "+f"((CC)[0]), "+f"((CC)[1]), "+f"((CC)[2]), "+f"((CC)[3])           \
        : "r"((A)[0]), "r"((A)[1]), "r"((A)[2]), "r"((A)[3]), "r"(B0), "r"(B1))

__device__ __forceinline__ void load_kv_block(char* smem, int kb, int hk,
                                              int buf, int t2)
{
    uint16_t* Kh = (uint16_t*)(smem + OFF_KH(buf));
    uint16_t* Kl = (uint16_t*)(smem + OFF_KL(buf));
    uint16_t* Vh = (uint16_t*)(smem + OFF_VH(buf));
    uint16_t* Vl = (uint16_t*)(smem + OFF_VL(buf));

    for (int i = t2; i < 64 * 24; i += 128) {
        int c = i / 24, d4 = (i % 24) * 4;
        float4 v = *(const float4*)&g_k[(size_t)(kb * BLK + c) * (NHK * HD) + hk * HD + d4];
        ushort4 hi, lo;
        split1(v.x, hi.x, lo.x); split1(v.y, hi.y, lo.y);
        split1(v.z, hi.z, lo.z); split1(v.w, hi.w, lo.w);
        *(ushort4*)&Kh[c * QSTR + d4] = hi;
        *(ushort4*)&Kl[c * QSTR + d4] = lo;
    }
    for (int i = t2; i < 64 * 24; i += 128) {
        int t = i / 24, d4 = (i % 24) * 4;
        float4 v = *(const float4*)&g_qkv[(size_t)(kb * BLK + t) * OP + VOFF + hk * HD + d4];
        uint16_t h0, l0;
        split1(v.x, h0, l0); Vh[(d4 + 0) * VSTR + t] = h0; Vl[(d4 + 0) * VSTR + t] = l0;
        split1(v.y, h0, l0); Vh[(d4 + 1) * VSTR + t] = h0; Vl[(d4 + 1) * VSTR + t] = l0;
        split1(v.z, h0, l0); Vh[(d4 + 2) * VSTR + t] = h0; Vl[(d4 + 2) * VSTR + t] = l0;
        split1(v.w, h0, l0); Vh[(d4 + 3) * VSTR + t] = h0; Vl[(d4 + 3) * VSTR + t] = l0;
    }
}

__global__ __launch_bounds__(256, 1)
void attn_mma_kernel()
{
    extern __shared__ char smem[];
    const int qb = blockIdx.x, h = blockIdx.y, hk = h >> 2;
    const int tid = threadIdx.x;
    int* blist = (int*)(smem + OFF_BL);

    if (tid < 32) {
        int kb = tid;
        const int* mrow = g_maskbuf + (hk * NB + qb) * NB;
        int keep = (kb <= qb) && mrow[kb];
        unsigned bm = __ballot_sync(0xffffffffu, keep);
        if (keep) blist[__popc(bm & ((1u << kb) - 1u))] = kb;
        if (tid == 0) blist[32] = __popc(bm);
    }

    {
        const float scale = rsqrtf((float)HD);
        uint16_t* Qh = (uint16_t*)(smem + OFF_QH);
        uint16_t* Ql = (uint16_t*)(smem + OFF_QL);
        for (int i = tid; i < 64 * 24; i += 256) {
            int r = i / 24, d4 = (i % 24) * 4;
            float4 v = *(const float4*)&g_q[(size_t)(qb * BLK + r) * (NH * HD) + h * HD + d4];
            v.x *= scale; v.y *= scale; v.z *= scale; v.w *= scale;
            ushort4 hi, lo;
            split1(v.x, hi.x, lo.x); split1(v.y, hi.y, lo.y);
            split1(v.z, hi.z, lo.z); split1(v.w, hi.w, lo.w);
            *(ushort4*)&Qh[r * QSTR + d4] = hi;
            *(ushort4*)&Ql[r * QSTR + d4] = lo;
        }
    }
    __syncthreads();

    const int nblk = blist[32];
    const int lane = tid & 31, warp = tid >> 5;

    if (warp >= 4) {
        int t2 = tid - 128;
        if (nblk > 0) load_kv_block(smem, blist[0], hk, 0, t2);
        __syncthreads();
        for (int i = 0; i < nblk; i++) {
            if (i + 1 < nblk) load_kv_block(smem, blist[i + 1], hk, (i + 1) & 1, t2);
            __syncthreads();
        }
        return;
    }

    const int row0 = warp * 16;
    const int g    = lane & 7, quad = lane >> 3;
    const int gid  = lane >> 2, tig = lane & 3;
    const uint32_t sb = (uint32_t)__cvta_generic_to_shared(smem);

    uint32_t qfh[6][4], qfl[6][4];
    {
        int ar = row0 + g + ((quad & 1) << 3);
#pragma unroll
        for (int ks = 0; ks < 6; ks++) {
            uint32_t off = (uint32_t)(ar * QSTR + ks * 16 + ((quad & 2) << 2)) * 2u;
            LDSM4(qfh[ks][0], qfh[ks][1], qfh[ks][2], qfh[ks][3], sb + OFF_QH + off);
            LDSM4(qfl[ks][0], qfl[ks][1], qfl[ks][2], qfl[ks][3], sb + OFF_QL + off);
        }
    }

    float o[12][4];
#pragma unroll
    for (int dt = 0; dt < 12; dt++)
#pragma unroll
        for (int e = 0; e < 4; e++) o[dt][e] = 0.f;
    float m0 = -1e30f, m1 = -1e30f, l0 = 0.f, l1 = 0.f;

    __syncthreads();

    const int kr = g + ((quad >> 1) << 3);
    const int kd = (quad & 1) << 3;

    for (int i = 0; i < nblk; i++) {
        const int buf = i & 1;
        const int kb  = blist[i];
        const uint32_t khb = sb + OFF_KH(buf), klb = sb + OFF_KL(buf);
        const uint32_t vhb = sb + OFF_VH(buf), vlb = sb + OFF_VL(buf);

        float st[8][4];
#pragma unroll
        for (int nt = 0; nt < 8; nt++)
#pragma unroll
            for (int e = 0; e < 4; e++) st[nt][e] = 0.f;

#pragma unroll
        for (int ks = 0; ks < 6; ks++) {
#pragma unroll
            for (int ng = 0; ng < 4; ng++) {
                uint32_t off = (uint32_t)((ng * 16 + kr) * QSTR + ks * 16 + kd) * 2u;
                uint32_t b0, b1, b2, b3, c0, c1, c2, c3;
                LDSM4(b0, b1, b2, b3, khb + off);
                LDSM4(c0, c1, c2, c3, klb + off);
                MMAB(st[2 * ng],     qfh[ks], b0, b1);
                MMAB(st[2 * ng + 1], qfh[ks], b2, b3);
                MMAB(st[2 * ng],     qfh[ks], c0, c1);
                MMAB(st[2 * ng + 1], qfh[ks], c2, c3);
                MMAB(st[2 * ng],     qfl[ks], b0, b1);
                MMAB(st[2 * ng + 1], qfl[ks], b2, b3);
            }
        }

        if (kb == qb) {
            const int rA = row0 + gid, rB = rA + 8;
#pragma unroll
            for (int nt = 0; nt < 8; nt++) {
                int cb = nt * 8 + tig * 2;
                if (cb     > rA) st[nt][0] = -1e30f;
                if (cb + 1 > rA) st[nt][1] = -1e30f;
                if (cb     > rB) st[nt][2] = -1e30f;
                if (cb + 1 > rB) st[nt][3] = -1e30f;
            }
        }

        float mA = -1e30f, mB = -1e30f;
#pragma unroll
        for (int nt = 0; nt < 8; nt++) {
            mA = fmaxf(mA, fmaxf(st[nt][0], st[nt][1]));
            mB = fmaxf(mB, fmaxf(st[nt][2], st[nt][3]));
        }
        mA = fmaxf(mA, __shfl_xor_sync(0xffffffffu, mA, 1));
        mA = fmaxf(mA, __shfl_xor_sync(0xffffffffu, mA, 2));
        mB = fmaxf(mB, __shfl_xor_sync(0xffffffffu, mB, 1));
        mB = fmaxf(mB, __shfl_xor_sync(0xffffffffu, mB, 2));
        float nmA = fmaxf(m0, mA), nmB = fmaxf(m1, mB);
        float cA = __expf(m0 - nmA), cB = __expf(m1 - nmB);
        float sA = 0.f, sB = 0.f;
#pragma unroll
        for (int nt = 0; nt < 8; nt++) {
            st[nt][0] = __expf(st[nt][0] - nmA); sA += st[nt][0];
            st[nt][1] = __expf(st[nt][1] - nmA); sA += st[nt][1];
            st[nt][2] = __expf(st[nt][2] - nmB); sB += st[nt][2];
            st[nt][3] = __expf(st[nt][3] - nmB); sB += st[nt][3];
        }
        sA += __shfl_xor_sync(0xffffffffu, sA, 1);
        sA += __shfl_xor_sync(0xffffffffu, sA, 2);
        sB += __shfl_xor_sync(0xffffffffu, sB, 1);
        sB += __shfl_xor_sync(0xffffffffu, sB, 2);
        l0 = l0 * cA + sA; m0 = nmA;
        l1 = l1 * cB + sB; m1 = nmB;
#pragma unroll
        for (int dt = 0; dt < 12; dt++) {
            o[dt][0] *= cA; o[dt][1] *= cA;
            o[dt][2] *= cB; o[dt][3] *= cB;
        }

        uint32_t ph[4][4], pl[4][4];
#pragma unroll
        for (int j = 0; j < 4; j++) {
            ph[j][0] = split2(st[2 * j][0],     st[2 * j][1],     pl[j][0]);
            ph[j][1] = split2(st[2 * j][2],     st[2 * j][3],     pl[j][1]);
            ph[j][2] = split2(st[2 * j + 1][0], st[2 * j + 1][1], pl[j][2]);
            ph[j][3] = split2(st[2 * j + 1][2], st[2 * j + 1][3], pl[j][3]);
        }

#pragma unroll
        for (int dt = 0; dt < 12; dt++) {
            uint32_t off1 = (uint32_t)((dt * 8 + g) * VSTR + quad * 8) * 2u;
            uint32_t off2 = off1 + 64u;
            uint32_t vA0, vA1, vA2, vA3, vB0, vB1, vB2, vB3;
            uint32_t wA0, wA1, wA2, wA3, wB0, wB1, wB2, wB3;
            LDSM4(vA0, vA1, vA2, vA3, vhb + off1);
            LDSM4(vB0, vB1, vB2, vB3, vhb + off2);
            LDSM4(wA0, wA1, wA2, wA3, vlb + off1);
            LDSM4(wB0, wB1, wB2, wB3, vlb + off2);
            MMAB(o[dt], ph[0], vA0, vA1);
            MMAB(o[dt], ph[0], wA0, wA1);
            MMAB(o[dt], pl[0], vA0, vA1);
            MMAB(o[dt], ph[1], vA2, vA3);
            MMAB(o[dt], ph[1], wA2, wA3);
            MMAB(o[dt], pl[1], vA2, vA3);
            MMAB(o[dt], ph[2], vB0, vB1);
            MMAB(o[dt], ph[2], wB0, wB1);
            MMAB(o[dt], pl[2], vB0, vB1);
            MMAB(o[dt], ph[3], vB2, vB3);
            MMAB(o[dt], ph[3], wB2, wB3);
            MMAB(o[dt], pl[3], vB2, vB3);
        }

        __syncthreads();
    }

    const float iA = 1.f / l0, iB = 1.f / l1;
    const int rA = qb * BLK + row0 + gid;
#pragma unroll
    for (int dt = 0; dt < 12; dt++) {
        int k2 = (h * HD + dt * 8 + tig * 2) >> 1;
        uint32_t loA, loB;
        uint32_t hiA = split2(o[dt][0] * iA, o[dt][1] * iA, loA);
        uint32_t hiB = split2(o[dt][2] * iB, o[dt][3] * iB, loB);
        g_ah[(size_t)rA * K2H + k2]       = hiA;
        g_al[(size_t)rA * K2H + k2]       = loA;
        g_ah[(size_t)(rA + 8) * K2H + k2] = hiB;
        g_al[(size_t)(rA + 8) * K2H + k2] = loB;
    }
}

// ---------------------------------------------------------------------------
// Launch
// ---------------------------------------------------------------------------
extern "C" void kernel_launch(void* const* d_in, const int* in_sizes, int n_in,
                              void* d_out, int out_size)
{
    const float* hs      = (const float*)d_in[0];
    const float* cosb    = (const float*)d_in[1];
    const float* sinb    = (const float*)d_in[2];
    const float* qkv_w   = (const float*)d_in[3];
    const float* o_w     = (const float*)d_in[4];
    const float* gate_wq = (const float*)d_in[5];
    const float* gate_wk = (const float*)d_in[6];
    float* out = (float*)d_out;

    void *p_qkv, *p_ah, *p_al, *p_wqh, *p_wql, *p_woh, *p_wol;
    cudaGetSymbolAddress(&p_qkv, g_qkv);
    cudaGetSymbolAddress(&p_ah, g_ah);
    cudaGetSymbolAddress(&p_al, g_al);
    cudaGetSymbolAddress(&p_wqh, g_wqh);
    cudaGetSymbolAddress(&p_wql, g_wql);
    cudaGetSymbolAddress(&p_woh, g_woh);
    cudaGetSymbolAddress(&p_wol, g_wol);

    // 0. Pack operands into bf16 hi/lo
    {
        int totW1 = K2H * OP;
        packB_kernel<<<(totW1 + 255) / 256, 256>>>(
            qkv_w, (uint32_t*)p_wqh, (uint32_t*)p_wql, OP, totW1);
        int totW2 = K2H * HIDDEN;
        packB_kernel<<<(totW2 + 255) / 256, 256>>>(
            o_w, (uint32_t*)p_woh, (uint32_t*)p_wol, HIDDEN, totW2);
        int totA = S_LEN * K2H;
        packA_kernel<<<(totA + 255) / 256, 256>>>(
            hs, (uint32_t*)p_ah, (uint32_t*)p_al, totA);
    }

    // 1. QKV projection (bf16x3 tensor cores, 256x128 block tile)
    bf16x3_gemm<<<dim3(OP / 128, S_LEN / 256), 256>>>(
        (const uint32_t*)p_ah, (const uint32_t*)p_al,
        (const uint32_t*)p_wqh, (const uint32_t*)p_wql,
        (float*)p_qkv, S_LEN, OP, K2H);

    // 2. RoPE
    {
        int total = S_LEN * (NH + NHK) * HD;
        rope_kernel<<<(total + 255) / 256, 256>>>(cosb, sinb);
    }

    // 3. Pool + gate + mask
    pool_kernel<<<dim3(NB, NHK), HD>>>();
    gate_kernel<<<dim3(NB, NHK), GH>>>(gate_wq, gate_wk);
    mask_kernel<<<dim3(NB, NHK), 32>>>();

    // 4. Tensor-core block-sparse flash attention (fused O-proj operand pack)
    cudaFuncSetAttribute(attn_mma_kernel,
                         cudaFuncAttributeMaxDynamicSharedMemorySize, ATTN_SMEM);
    attn_mma_kernel<<<dim3(NB, NH), 256, ATTN_SMEM>>>();

    // 5. Output projection (bf16x3 tensor cores, 256x128 block tile)
    bf16x3_gemm<<<dim3(HIDDEN / 128, S_LEN / 256), 256>>>(
        (const uint32_t*)p_ah, (const uint32_t*)p_al,
        (const uint32_t*)p_woh, (const uint32_t*)p_wol,
        out, S_LEN, HIDDEN, HIDDEN / 2);
}

// round 10
// speedup vs baseline: 1.6114x; 1.6114x over previous
#include <cuda_runtime.h>
#include <cuda_bf16.h>
#include <cstdint>
#include <math.h>

// ---------------------------------------------------------------------------
// Problem constants
// ---------------------------------------------------------------------------
#define S_LEN   2048
#define HIDDEN  3072
#define NH      32
#define NHK     8
#define GQ      4
#define HD      96
#define BLK     64
#define NB      32
#define GH      128
#define OP      4608
#define KOFF    3072
#define VOFF    3840
#define K2H     (HIDDEN / 2)

// ---------------------------------------------------------------------------
// Scratch (device globals; no allocation allowed)
// ---------------------------------------------------------------------------
__device__ float g_qkv [S_LEN * OP];
__device__ float g_q   [S_LEN * NH  * HD];
__device__ float g_k   [S_LEN * NHK * HD];
__device__ float g_qpool[NB * NHK * HD];
__device__ float g_kpool[NB * NHK * 2 * HD];
__device__ float g_qgate[NB * NHK * GH];
__device__ float g_kgate[NB * NHK * GH];
__device__ int   g_maskbuf[NHK * NB * NB];

// bf16 hi/lo packed GEMM operands (k-pairs packed into one uint32)
__device__ uint32_t g_ah [S_LEN * K2H];       // A hi (hs, then attn out)
__device__ uint32_t g_al [S_LEN * K2H];       // A lo
__device__ uint32_t g_wqh[K2H * OP];
__device__ uint32_t g_wql[K2H * OP];
__device__ uint32_t g_woh[K2H * HIDDEN];
__device__ uint32_t g_wol[K2H * HIDDEN];

// Pre-converted attention operands (bf16 hi/lo)
__device__ uint16_t g_kbh[NHK * S_LEN * HD];  // K  [hk][t][d]
__device__ uint16_t g_kbl[NHK * S_LEN * HD];
__device__ uint16_t g_vth[NHK * HD * S_LEN];  // V^T [hk][d][t]
__device__ uint16_t g_vtl[NHK * HD * S_LEN];

// ---------------------------------------------------------------------------
// bf16 hi/lo split helpers
// ---------------------------------------------------------------------------
__device__ __forceinline__ void bsplit(float x, uint32_t& h, uint32_t& l)
{
    __nv_bfloat16 hb = __float2bfloat16(x);
    float hf = __bfloat162float(hb);
    __nv_bfloat16 lb = __float2bfloat16(x - hf);
    h = (uint32_t)__bfloat16_as_ushort(hb);
    l = (uint32_t)__bfloat16_as_ushort(lb);
}

__device__ __forceinline__ void split1(float x, uint16_t& h, uint16_t& l)
{
    __nv_bfloat16 hb = __float2bfloat16(x);
    h = __bfloat16_as_ushort(hb);
    l = __bfloat16_as_ushort(__float2bfloat16(x - __bfloat162float(hb)));
}

__device__ __forceinline__ uint32_t split2(float x, float y, uint32_t& lo)
{
    __nv_bfloat16 hx = __float2bfloat16(x), hy = __float2bfloat16(y);
    float rx = x - __bfloat162float(hx), ry = y - __bfloat162float(hy);
    __nv_bfloat16 lx = __float2bfloat16(rx), ly = __float2bfloat16(ry);
    lo = (uint32_t)__bfloat16_as_ushort(lx) | ((uint32_t)__bfloat16_as_ushort(ly) << 16);
    return (uint32_t)__bfloat16_as_ushort(hx) | ((uint32_t)__bfloat16_as_ushort(hy) << 16);
}

// Pack A (row-major M x K): word i = (x[2i], x[2i+1]) along k
__global__ void packA_kernel(const float* __restrict__ in,
                             uint32_t* __restrict__ hi, uint32_t* __restrict__ lo,
                             int total2)
{
    int i = blockIdx.x * blockDim.x + threadIdx.x;
    if (i >= total2) return;
    float2 v = ((const float2*)in)[i];
    uint32_t h0, l0, h1, l1;
    bsplit(v.x, h0, l0);
    bsplit(v.y, h1, l1);
    hi[i] = h0 | (h1 << 16);
    lo[i] = l0 | (l1 << 16);
}

// Pack B (row-major K x N): out[k2][n] = (B[2k2][n], B[2k2+1][n])
__global__ void packB_kernel(const float* __restrict__ in,
                             uint32_t* __restrict__ hi, uint32_t* __restrict__ lo,
                             int N, int total)
{
    int i = blockIdx.x * blockDim.x + threadIdx.x;
    if (i >= total) return;
    int k2 = i / N, n = i - k2 * N;
    float x0 = in[(size_t)(2 * k2) * N + n];
    float x1 = in[(size_t)(2 * k2 + 1) * N + n];
    uint32_t h0, l0, h1, l1;
    bsplit(x0, h0, l0);
    bsplit(x1, h1, l1);
    hi[i] = h0 | (h1 << 16);
    lo[i] = l0 | (l1 << 16);
}

// K pre-convert: g_k [s][hk][d] -> g_kbh/g_kbl [hk][s][d]
__global__ void convK_kernel()
{
    int i = blockIdx.x * blockDim.x + threadIdx.x;
    if (i >= S_LEN * NHK * HD) return;
    int d = i % HD, hk = (i / HD) % NHK, s = i / (HD * NHK);
    float v = g_k[(size_t)s * (NHK * HD) + hk * HD + d];
    uint16_t h, l;
    split1(v, h, l);
    size_t o = ((size_t)hk * S_LEN + s) * HD + d;
    g_kbh[o] = h;
    g_kbl[o] = l;
}

// V pre-convert + transpose: g_qkv [s][VOFF+hk*HD+d] -> g_vth/g_vtl [hk][d][s]
__global__ void convV_kernel()
{
    __shared__ float t[32][33];
    const int s0 = blockIdx.x * 32, d0 = blockIdx.y * 32, hk = blockIdx.z;
    const int tx = threadIdx.x & 31, ty = threadIdx.x >> 5;   // ty 0..7
#pragma unroll
    for (int i = 0; i < 32; i += 8)
        t[ty + i][tx] = g_qkv[(size_t)(s0 + ty + i) * OP + VOFF + hk * HD + d0 + tx];
    __syncthreads();
#pragma unroll
    for (int i = 0; i < 32; i += 8) {
        float v = t[tx][ty + i];              // = V[s0+tx][d0+ty+i]
        uint16_t h, l;
        split1(v, h, l);
        size_t o = ((size_t)hk * HD + d0 + ty + i) * S_LEN + s0 + tx;
        g_vth[o] = h;
        g_vtl[o] = l;
    }
}

// ---------------------------------------------------------------------------
// bf16x3 tensor-core GEMM (proven R7 version: scalar-LDS fragments, occ 2).
// ---------------------------------------------------------------------------
#define PADB 136

#define MMA_BF16(CC, A0, A1, A2, A3, B0, B1)                                   \
    asm volatile(                                                              \
        "mma.sync.aligned.m16n8k16.row.col.f32.bf16.bf16.f32 "                 \
        "{%0,%1,%2,%3}, {%4,%5,%6,%7}, {%8,%9}, {%0,%1,%2,%3};"                \
        : "+f"(CC[0]), "+f"(CC[1]), "+f"(CC[2]), "+f"(CC[3])                   \
        : "r"(A0), "r"(A1), "r"(A2), "r"(A3), "r"(B0), "r"(B1))

__global__ __launch_bounds__(256, 2)
void bf16x3_gemm(const uint32_t* __restrict__ Agh, const uint32_t* __restrict__ Agl,
                 const uint32_t* __restrict__ Bgh, const uint32_t* __restrict__ Bgl,
                 float* __restrict__ C, int M, int N, int K2)
{
    __shared__ __align__(16) uint32_t Ah[2][8][PADB], Al[2][8][PADB];
    __shared__ __align__(16) uint32_t Bh[2][8][PADB], Bl[2][8][PADB];

    const int tid  = threadIdx.x;
    const int bn   = blockIdx.x, bm = blockIdx.y;
    const int warp = tid >> 5,  lane = tid & 31;
    const int wm   = warp >> 2, wn   = warp & 3;
    const int gid  = lane >> 2, tig  = lane & 3;

    const int a_r = tid >> 1, a_c = (tid & 1) * 4;
    const int b_r = tid >> 5, b_c = (tid & 31) * 4;

    const uint32_t* Aph = Agh + (size_t)(bm * 128 + a_r) * K2 + a_c;
    const uint32_t* Apl = Agl + (size_t)(bm * 128 + a_r) * K2 + a_c;
    const uint32_t* Bph = Bgh + (size_t)b_r * N + bn * 128 + b_c;
    const uint32_t* Bpl = Bgl + (size_t)b_r * N + bn * 128 + b_c;

    uint4 rah = *(const uint4*)Aph;
    uint4 ral = *(const uint4*)Apl;
    uint4 rbh = *(const uint4*)Bph;
    uint4 rbl = *(const uint4*)Bpl;

    Ah[0][a_c + 0][a_r] = rah.x; Ah[0][a_c + 1][a_r] = rah.y;
    Ah[0][a_c + 2][a_r] = rah.z; Ah[0][a_c + 3][a_r] = rah.w;
    Al[0][a_c + 0][a_r] = ral.x; Al[0][a_c + 1][a_r] = ral.y;
    Al[0][a_c + 2][a_r] = ral.z; Al[0][a_c + 3][a_r] = ral.w;
    *(uint4*)&Bh[0][b_r][b_c] = rbh;
    *(uint4*)&Bl[0][b_r][b_c] = rbl;
    __syncthreads();

    float acc[4][4][4];
#pragma unroll
    for (int mt = 0; mt < 4; mt++)
#pragma unroll
        for (int nt = 0; nt < 4; nt++)
#pragma unroll
            for (int r = 0; r < 4; r++) acc[mt][nt][r] = 0.f;

    const int nst = K2 >> 3;
    for (int st = 0; st < nst; st++) {
        const int cur = st & 1;
        const bool more = (st + 1 < nst);
        if (more) {
            rah = *(const uint4*)(Aph + (st + 1) * 8);
            ral = *(const uint4*)(Apl + (st + 1) * 8);
            rbh = *(const uint4*)(Bph + (size_t)(st + 1) * 8 * N);
            rbl = *(const uint4*)(Bpl + (size_t)(st + 1) * 8 * N);
        }

        uint32_t bhf[4][2], blf[4][2];
#pragma unroll
        for (int nt = 0; nt < 4; nt++) {
            const int n0 = wn * 32 + nt * 8;
            bhf[nt][0] = Bh[cur][tig][n0 + gid];
            bhf[nt][1] = Bh[cur][tig + 4][n0 + gid];
            blf[nt][0] = Bl[cur][tig][n0 + gid];
            blf[nt][1] = Bl[cur][tig + 4][n0 + gid];
        }

#pragma unroll
        for (int mt = 0; mt < 4; mt++) {
            const int m0 = wm * 64 + mt * 16;
            uint32_t ah0 = Ah[cur][tig][m0 + gid];
            uint32_t ah1 = Ah[cur][tig][m0 + gid + 8];
            uint32_t ah2 = Ah[cur][tig + 4][m0 + gid];
            uint32_t ah3 = Ah[cur][tig + 4][m0 + gid + 8];
            uint32_t al0 = Al[cur][tig][m0 + gid];
            uint32_t al1 = Al[cur][tig][m0 + gid + 8];
            uint32_t al2 = Al[cur][tig + 4][m0 + gid];
            uint32_t al3 = Al[cur][tig + 4][m0 + gid + 8];
#pragma unroll
            for (int nt = 0; nt < 4; nt++) {
                MMA_BF16(acc[mt][nt], ah0, ah1, ah2, ah3, bhf[nt][0], bhf[nt][1]);
                MMA_BF16(acc[mt][nt], ah0, ah1, ah2, ah3, blf[nt][0], blf[nt][1]);
                MMA_BF16(acc[mt][nt], al0, al1, al2, al3, bhf[nt][0], bhf[nt][1]);
            }
        }

        if (more) {
            const int nxt = cur ^ 1;
            Ah[nxt][a_c + 0][a_r] = rah.x; Ah[nxt][a_c + 1][a_r] = rah.y;
            Ah[nxt][a_c + 2][a_r] = rah.z; Ah[nxt][a_c + 3][a_r] = rah.w;
            Al[nxt][a_c + 0][a_r] = ral.x; Al[nxt][a_c + 1][a_r] = ral.y;
            Al[nxt][a_c + 2][a_r] = ral.z; Al[nxt][a_c + 3][a_r] = ral.w;
            *(uint4*)&Bh[nxt][b_r][b_c] = rbh;
            *(uint4*)&Bl[nxt][b_r][b_c] = rbl;
            __syncthreads();
        }
    }

#pragma unroll
    for (int mt = 0; mt < 4; mt++) {
        const int row = bm * 128 + wm * 64 + mt * 16 + gid;
#pragma unroll
        for (int nt = 0; nt < 4; nt++) {
            const int col = bn * 128 + wn * 32 + nt * 8 + tig * 2;
            *(float2*)&C[(size_t)row * N + col] =
                make_float2(acc[mt][nt][0], acc[mt][nt][1]);
            *(float2*)&C[(size_t)(row + 8) * N + col] =
                make_float2(acc[mt][nt][2], acc[mt][nt][3]);
        }
    }
}

// ---------------------------------------------------------------------------
// RoPE
// ---------------------------------------------------------------------------
__global__ void rope_kernel(const float* __restrict__ cosb,
                            const float* __restrict__ sinb)
{
    const int total = S_LEN * (NH + NHK) * HD;
    int idx = blockIdx.x * blockDim.x + threadIdx.x;
    if (idx >= total) return;
    int d = idx % HD;
    int h = (idx / HD) % (NH + NHK);
    int s = idx / (HD * (NH + NHK));
    const float* row = g_qkv + (size_t)s * OP;
    float c  = cosb[s * HD + d];
    float sn = sinb[s * HD + d];
    if (h < NH) {
        int base = h * HD;
        float x = row[base + d];
        float r = (d < HD / 2) ? -row[base + d + HD / 2] : row[base + d - HD / 2];
        g_q[(size_t)s * (NH * HD) + h * HD + d] = x * c + r * sn;
    } else {
        int hk = h - NH;
        int base = KOFF + hk * HD;
        float x = row[base + d];
        float r = (d < HD / 2) ? -row[base + d + HD / 2] : row[base + d - HD / 2];
        g_k[(size_t)s * (NHK * HD) + hk * HD + d] = x * c + r * sn;
    }
}

// ---------------------------------------------------------------------------
// Pooling / gates / mask (unchanged)
// ---------------------------------------------------------------------------
__global__ void pool_kernel()
{
    int nb = blockIdx.x, hk = blockIdx.y, d = threadIdx.x;
    float ksum = 0.f, kmax = -3.0e38f, qsum = 0.f;
#pragma unroll 4
    for (int t = 0; t < BLK; t++) {
        const float* row = g_qkv + (size_t)(nb * BLK + t) * OP;
        float kv = row[KOFF + hk * HD + d];
        ksum += kv;
        kmax = fmaxf(kmax, kv);
#pragma unroll
        for (int g = 0; g < GQ; g++) qsum += row[(hk * GQ + g) * HD + d];
    }
    int bh = nb * NHK + hk;
    g_kpool[bh * (2 * HD) + d]      = ksum * (1.f / BLK);
    g_kpool[bh * (2 * HD) + HD + d] = kmax;
    g_qpool[bh * HD + d]            = qsum * (1.f / (BLK * GQ));
}

__global__ void gate_kernel(const float* __restrict__ gate_wq,
                            const float* __restrict__ gate_wk)
{
    int nb = blockIdx.x, hk = blockIdx.y, g = threadIdx.x;
    int bh = nb * NHK + hk;
    float qa = 0.f;
#pragma unroll 8
    for (int d = 0; d < HD; d++)
        qa += g_qpool[bh * HD + d] * gate_wq[d * GH + g];
    float ka = 0.f;
#pragma unroll 8
    for (int e = 0; e < 2 * HD; e++)
        ka += g_kpool[bh * (2 * HD) + e] * gate_wk[e * GH + g];
    g_qgate[bh * GH + g] = qa;
    g_kgate[bh * GH + g] = ka;
}

__global__ void mask_kernel()
{
    int qb = blockIdx.x, hk = blockIdx.y, kb = threadIdx.x;
    float l = -1e30f;
    if (kb <= qb) {
        float dot = 0.f;
#pragma unroll 8
        for (int g = 0; g < GH; g++)
            dot += g_qgate[(size_t)(qb * NHK + hk) * GH + g]
                 * g_kgate[(size_t)(kb * NHK + hk) * GH + g];
        l = dot * rsqrtf((float)GH);
    }
    float mx = l;
#pragma unroll
    for (int o = 16; o > 0; o >>= 1) mx = fmaxf(mx, __shfl_xor_sync(0xffffffffu, mx, o));
    float e = expf(l - mx);
    float sm = e;
#pragma unroll
    for (int o = 16; o > 0; o >>= 1) sm += __shfl_xor_sync(0xffffffffu, sm, o);
    float p = e / sm;
    int keep = ((p >= 0.03f) && (kb <= qb)) || (kb == qb);
    g_maskbuf[(hk * NB + qb) * NB + kb] = keep;
}

// ---------------------------------------------------------------------------
// Block-sparse flash attention, 8 consumer warps (split-column flash),
// cp.async K/V from pre-converted bf16 hi/lo globals, no producer warps.
// Warp w: row group (w&3)*16, column half (w>>2)*32.
// ---------------------------------------------------------------------------
#define QSTR 104
#define VSTR 72

#define OFF_QH  0
#define OFF_QL  13312
#define OFF_KH(b) (26624  + (b) * 13312)
#define OFF_KL(b) (53248  + (b) * 13312)
#define OFF_VH(b) (79872  + (b) * 13824)
#define OFF_VL(b) (107520 + (b) * 13824)
#define OFF_OB  135168
#define OFF_PM  160768
#define OFF_PS  161280
#define OFF_BL  161792
#define ATTN_SMEM 162048

#define LDSM4(R0, R1, R2, R3, ADDR)                                            \
    asm volatile("ldmatrix.sync.aligned.m8n8.x4.shared.b16 {%0,%1,%2,%3}, [%4];" \
                 : "=r"(R0), "=r"(R1), "=r"(R2), "=r"(R3) : "r"(ADDR))

#define MMAB(CC, A, B0, B1)                                                    \
    asm volatile(                                                              \
        "mma.sync.aligned.m16n8k16.row.col.f32.bf16.bf16.f32 "                 \
        "{%0,%1,%2,%3}, {%4,%5,%6,%7}, {%8,%9}, {%0,%1,%2,%3};"                \
        : "+f"((CC)[0]), "+f"((CC)[1]), "+f"((CC)[2]), "+f"((CC)[3])           \
        : "r"((A)[0]), "r"((A)[1]), "r"((A)[2]), "r"((A)[3]), "r"(B0), "r"(B1))

#define CPA16(DST, SRC) \
    asm volatile("cp.async.cg.shared.global [%0], [%1], 16;" :: "r"(DST), "l"(SRC))
#define CPA_COMMIT() asm volatile("cp.async.commit_group;" ::: "memory")

__device__ __forceinline__ void kv_issue(uint32_t sb, int buf, int kb,
                                         const uint16_t* __restrict__ Khg,
                                         const uint16_t* __restrict__ Klg,
                                         const uint16_t* __restrict__ Vhg,
                                         const uint16_t* __restrict__ Vlg,
                                         int tid)
{
    // K: 64 rows x 96 d (192B = 12 chunks/row)
#pragma unroll
    for (int it = 0; it < 3; it++) {
        int idx = tid + it * 256;
        int c = idx / 12, ck = idx % 12;
        const char* sh = (const char*)(Khg + (size_t)(kb * BLK + c) * HD) + ck * 16;
        const char* sl = (const char*)(Klg + (size_t)(kb * BLK + c) * HD) + ck * 16;
        uint32_t d = (uint32_t)(c * QSTR + ck * 8) * 2;
        CPA16(sb + OFF_KH(buf) + d, sh);
        CPA16(sb + OFF_KL(buf) + d, sl);
    }
    // V^T: 96 rows x 64 t (128B = 8 chunks/row)
#pragma unroll
    for (int it = 0; it < 3; it++) {
        int idx = tid + it * 256;
        int dr = idx / 8, ck = idx % 8;
        const char* sh = (const char*)(Vhg + (size_t)dr * S_LEN + kb * BLK) + ck * 16;
        const char* sl = (const char*)(Vlg + (size_t)dr * S_LEN + kb * BLK) + ck * 16;
        uint32_t d = (uint32_t)(dr * VSTR + ck * 8) * 2;
        CPA16(sb + OFF_VH(buf) + d, sh);
        CPA16(sb + OFF_VL(buf) + d, sl);
    }
}

__global__ __launch_bounds__(256, 1)
void attn_mma_kernel()
{
    extern __shared__ char smem[];
    const int qb = blockIdx.x, h = blockIdx.y, hk = h >> 2;
    const int tid = threadIdx.x;
    int* blist = (int*)(smem + OFF_BL);

    if (tid < 32) {
        int kb = tid;
        const int* mrow = g_maskbuf + (hk * NB + qb) * NB;
        int keep = (kb <= qb) && mrow[kb];
        unsigned bm = __ballot_sync(0xffffffffu, keep);
        if (keep) blist[__popc(bm & ((1u << kb) - 1u))] = kb;
        if (tid == 0) blist[32] = __popc(bm);
    }

    // Load Q (scaled) -> hi/lo smem
    {
        const float scale = rsqrtf((float)HD);
        uint16_t* Qh = (uint16_t*)(smem + OFF_QH);
        uint16_t* Ql = (uint16_t*)(smem + OFF_QL);
        for (int i = tid; i < 64 * 24; i += 256) {
            int r = i / 24, d4 = (i % 24) * 4;
            float4 v = *(const float4*)&g_q[(size_t)(qb * BLK + r) * (NH * HD) + h * HD + d4];
            v.x *= scale; v.y *= scale; v.z *= scale; v.w *= scale;
            ushort4 hi, lo;
            split1(v.x, hi.x, lo.x); split1(v.y, hi.y, lo.y);
            split1(v.z, hi.z, lo.z); split1(v.w, hi.w, lo.w);
            *(ushort4*)&Qh[r * QSTR + d4] = hi;
            *(ushort4*)&Ql[r * QSTR + d4] = lo;
        }
    }
    __syncthreads();

    const int nblk = blist[32];
    const int lane = tid & 31, warp = tid >> 5;
    const int wr = warp & 3;          // row group
    const int ch = warp >> 2;         // column half (0: cols 0-31, 1: 32-63)
    const int row0 = wr * 16;
    const int g    = lane & 7, quad = lane >> 3;
    const int gid  = lane >> 2, tig = lane & 3;
    const uint32_t sb = (uint32_t)__cvta_generic_to_shared(smem);

    const uint16_t* Khg = g_kbh + (size_t)hk * S_LEN * HD;
    const uint16_t* Klg = g_kbl + (size_t)hk * S_LEN * HD;
    const uint16_t* Vhg = g_vth + (size_t)hk * HD * S_LEN;
    const uint16_t* Vlg = g_vtl + (size_t)hk * HD * S_LEN;

    float* pmax = (float*)(smem + OFF_PM);   // [2][64]
    float* psum = (float*)(smem + OFF_PS);   // [2][64]
    float* Obuf = (float*)(smem + OFF_OB);   // [64][100]

    // Q fragments
    uint32_t qfh[6][4], qfl[6][4];
    {
        int ar = row0 + g + ((quad & 1) << 3);
#pragma unroll
        for (int ks = 0; ks < 6; ks++) {
            uint32_t off = (uint32_t)(ar * QSTR + ks * 16 + ((quad & 2) << 2)) * 2u;
            LDSM4(qfh[ks][0], qfh[ks][1], qfh[ks][2], qfh[ks][3], sb + OFF_QH + off);
            LDSM4(qfl[ks][0], qfl[ks][1], qfl[ks][2], qfl[ks][3], sb + OFF_QL + off);
        }
    }

    float o[12][4];
#pragma unroll
    for (int dt = 0; dt < 12; dt++)
#pragma unroll
        for (int e = 0; e < 4; e++) o[dt][e] = 0.f;
    float m0 = -1e30f, m1 = -1e30f, l0 = 0.f, l1 = 0.f;

    const int kr = g + ((quad >> 1) << 3);
    const int kd = (quad & 1) << 3;

    kv_issue(sb, 0, blist[0], Khg, Klg, Vhg, Vlg, tid);
    CPA_COMMIT();

    for (int i = 0; i < nblk; i++) {
        const int buf = i & 1;
        const int kb  = blist[i];
        if (i + 1 < nblk) {
            kv_issue(sb, (i + 1) & 1, blist[i + 1], Khg, Klg, Vhg, Vlg, tid);
            CPA_COMMIT();
            asm volatile("cp.async.wait_group 1;" ::: "memory");
        } else {
            asm volatile("cp.async.wait_group 0;" ::: "memory");
        }
        __syncthreads();

        const uint32_t khb = sb + OFF_KH(buf), klb = sb + OFF_KL(buf);
        const uint32_t vhb = sb + OFF_VH(buf), vlb = sb + OFF_VL(buf);

        // ---- S = Q K^T (this warp's 32-column half) ----
        float st[4][4];
#pragma unroll
        for (int nt = 0; nt < 4; nt++)
#pragma unroll
            for (int e = 0; e < 4; e++) st[nt][e] = 0.f;

#pragma unroll
        for (int ks = 0; ks < 6; ks++) {
#pragma unroll
            for (int j = 0; j < 2; j++) {
                const int ng = ch * 2 + j;
                uint32_t off = (uint32_t)((ng * 16 + kr) * QSTR + ks * 16 + kd) * 2u;
                uint32_t b0, b1, b2, b3, c0, c1, c2, c3;
                LDSM4(b0, b1, b2, b3, khb + off);
                LDSM4(c0, c1, c2, c3, klb + off);
                MMAB(st[2 * j],     qfh[ks], b0, b1);
                MMAB(st[2 * j + 1], qfh[ks], b2, b3);
                MMAB(st[2 * j],     qfh[ks], c0, c1);
                MMAB(st[2 * j + 1], qfh[ks], c2, c3);
                MMAB(st[2 * j],     qfl[ks], b0, b1);
                MMAB(st[2 * j + 1], qfl[ks], b2, b3);
            }
        }

        // ---- diagonal causal mask ----
        if (kb == qb) {
            const int rA = row0 + gid, rB = rA + 8;
#pragma unroll
            for (int nt = 0; nt < 4; nt++) {
                int cb = ch * 32 + nt * 8 + tig * 2;
                if (cb     > rA) st[nt][0] = -1e30f;
                if (cb + 1 > rA) st[nt][1] = -1e30f;
                if (cb     > rB) st[nt][2] = -1e30f;
                if (cb + 1 > rB) st[nt][3] = -1e30f;
            }
        }

        // ---- online softmax (cross-half combine via smem) ----
        float mA = -1e30f, mB = -1e30f;
#pragma unroll
        for (int nt = 0; nt < 4; nt++) {
            mA = fmaxf(mA, fmaxf(st[nt][0], st[nt][1]));
            mB = fmaxf(mB, fmaxf(st[nt][2], st[nt][3]));
        }
        mA = fmaxf(mA, __shfl_xor_sync(0xffffffffu, mA, 1));
        mA = fmaxf(mA, __shfl_xor_sync(0xffffffffu, mA, 2));
        mB = fmaxf(mB, __shfl_xor_sync(0xffffffffu, mB, 1));
        mB = fmaxf(mB, __shfl_xor_sync(0xffffffffu, mB, 2));
        if (tig == 0) {
            pmax[ch * 64 + row0 + gid]     = mA;
            pmax[ch * 64 + row0 + gid + 8] = mB;
        }
        __syncthreads();
        mA = fmaxf(mA, pmax[(ch ^ 1) * 64 + row0 + gid]);
        mB = fmaxf(mB, pmax[(ch ^ 1) * 64 + row0 + gid + 8]);

        float nmA = fmaxf(m0, mA), nmB = fmaxf(m1, mB);
        float cA = __expf(m0 - nmA), cB = __expf(m1 - nmB);
        float sA = 0.f, sB = 0.f;
#pragma unroll
        for (int nt = 0; nt < 4; nt++) {
            st[nt][0] = __expf(st[nt][0] - nmA); sA += st[nt][0];
            st[nt][1] = __expf(st[nt][1] - nmA); sA += st[nt][1];
            st[nt][2] = __expf(st[nt][2] - nmB); sB += st[nt][2];
            st[nt][3] = __expf(st[nt][3] - nmB); sB += st[nt][3];
        }
        sA += __shfl_xor_sync(0xffffffffu, sA, 1);
        sA += __shfl_xor_sync(0xffffffffu, sA, 2);
        sB += __shfl_xor_sync(0xffffffffu, sB, 1);
        sB += __shfl_xor_sync(0xffffffffu, sB, 2);
        if (tig == 0) {
            psum[ch * 64 + row0 + gid]     = sA;
            psum[ch * 64 + row0 + gid + 8] = sB;
        }
        __syncthreads();
        sA += psum[(ch ^ 1) * 64 + row0 + gid];
        sB += psum[(ch ^ 1) * 64 + row0 + gid + 8];

        l0 = l0 * cA + sA; m0 = nmA;
        l1 = l1 * cB + sB; m1 = nmB;
#pragma unroll
        for (int dt = 0; dt < 12; dt++) {
            o[dt][0] *= cA; o[dt][1] *= cA;
            o[dt][2] *= cB; o[dt][3] *= cB;
        }

        // ---- pack P (this half's two t16 tiles) ----
        uint32_t ph[2][4], pl[2][4];
#pragma unroll
        for (int j = 0; j < 2; j++) {
            ph[j][0] = split2(st[2 * j][0],     st[2 * j][1],     pl[j][0]);
            ph[j][1] = split2(st[2 * j][2],     st[2 * j][3],     pl[j][1]);
            ph[j][2] = split2(st[2 * j + 1][0], st[2 * j + 1][1], pl[j][2]);
            ph[j][3] = split2(st[2 * j + 1][2], st[2 * j + 1][3], pl[j][3]);
        }

        // ---- O += P V (this half's t range) ----
#pragma unroll
        for (int dt = 0; dt < 12; dt++) {
            uint32_t off = (uint32_t)((dt * 8 + g) * VSTR + ch * 32 + quad * 8) * 2u;
            uint32_t v0, v1, v2, v3, w0, w1, w2, w3;
            LDSM4(v0, v1, v2, v3, vhb + off);
            LDSM4(w0, w1, w2, w3, vlb + off);
            MMAB(o[dt], ph[0], v0, v1);
            MMAB(o[dt], ph[0], w0, w1);
            MMAB(o[dt], pl[0], v0, v1);
            MMAB(o[dt], ph[1], v2, v3);
            MMAB(o[dt], ph[1], w2, w3);
            MMAB(o[dt], pl[1], v2, v3);
        }

        __syncthreads();
    }

    // ---- combine halves + fused pack epilogue ----
    if (ch == 1) {
#pragma unroll
        for (int dt = 0; dt < 12; dt++) {
            int col = dt * 8 + tig * 2;
            *(float2*)&Obuf[(row0 + gid) * 100 + col] =
                make_float2(o[dt][0], o[dt][1]);
            *(float2*)&Obuf[(row0 + gid + 8) * 100 + col] =
                make_float2(o[dt][2], o[dt][3]);
        }
    }
    __syncthreads();
    if (ch == 0) {
        const float iA = 1.f / l0, iB = 1.f / l1;
        const int rA = qb * BLK + row0 + gid;
#pragma unroll
        for (int dt = 0; dt < 12; dt++) {
            int col = dt * 8 + tig * 2;
            float2 oa = *(float2*)&Obuf[(row0 + gid) * 100 + col];
            float2 ob = *(float2*)&Obuf[(row0 + gid + 8) * 100 + col];
            float x0 = (o[dt][0] + oa.x) * iA;
            float x1 = (o[dt][1] + oa.y) * iA;
            float x2 = (o[dt][2] + ob.x) * iB;
            float x3 = (o[dt][3] + ob.y) * iB;
            int k2 = (h * HD + col) >> 1;
            uint32_t loA, loB;
            uint32_t hiA = split2(x0, x1, loA);
            uint32_t hiB = split2(x2, x3, loB);
            g_ah[(size_t)rA * K2H + k2]       = hiA;
            g_al[(size_t)rA * K2H + k2]       = loA;
            g_ah[(size_t)(rA + 8) * K2H + k2] = hiB;
            g_al[(size_t)(rA + 8) * K2H + k2] = loB;
        }
    }
}

// ---------------------------------------------------------------------------
// Launch
// ---------------------------------------------------------------------------
extern "C" void kernel_launch(void* const* d_in, const int* in_sizes, int n_in,
                              void* d_out, int out_size)
{
    const float* hs      = (const float*)d_in[0];
    const float* cosb    = (const float*)d_in[1];
    const float* sinb    = (const float*)d_in[2];
    const float* qkv_w   = (const float*)d_in[3];
    const float* o_w     = (const float*)d_in[4];
    const float* gate_wq = (const float*)d_in[5];
    const float* gate_wk = (const float*)d_in[6];
    float* out = (float*)d_out;

    void *p_qkv, *p_ah, *p_al, *p_wqh, *p_wql, *p_woh, *p_wol;
    cudaGetSymbolAddress(&p_qkv, g_qkv);
    cudaGetSymbolAddress(&p_ah, g_ah);
    cudaGetSymbolAddress(&p_al, g_al);
    cudaGetSymbolAddress(&p_wqh, g_wqh);
    cudaGetSymbolAddress(&p_wql, g_wql);
    cudaGetSymbolAddress(&p_woh, g_woh);
    cudaGetSymbolAddress(&p_wol, g_wol);

    // 0. Pack GEMM operands into bf16 hi/lo
    {
        int totW1 = K2H * OP;
        packB_kernel<<<(totW1 + 255) / 256, 256>>>(
            qkv_w, (uint32_t*)p_wqh, (uint32_t*)p_wql, OP, totW1);
        int totW2 = K2H * HIDDEN;
        packB_kernel<<<(totW2 + 255) / 256, 256>>>(
            o_w, (uint32_t*)p_woh, (uint32_t*)p_wol, HIDDEN, totW2);
        int totA = S_LEN * K2H;
        packA_kernel<<<(totA + 255) / 256, 256>>>(
            hs, (uint32_t*)p_ah, (uint32_t*)p_al, totA);
    }

    // 1. QKV projection (bf16x3 tensor cores)
    bf16x3_gemm<<<dim3(OP / 128, S_LEN / 128), 256>>>(
        (const uint32_t*)p_ah, (const uint32_t*)p_al,
        (const uint32_t*)p_wqh, (const uint32_t*)p_wql,
        (float*)p_qkv, S_LEN, OP, K2H);

    // 2. RoPE
    {
        int total = S_LEN * (NH + NHK) * HD;
        rope_kernel<<<(total + 255) / 256, 256>>>(cosb, sinb);
    }

    // 2b. Pre-convert K and V^T to bf16 hi/lo
    {
        int totK = S_LEN * NHK * HD;
        convK_kernel<<<(totK + 255) / 256, 256>>>();
        convV_kernel<<<dim3(S_LEN / 32, HD / 32, NHK), 256>>>();
    }

    // 3. Pool + gate + mask
    pool_kernel<<<dim3(NB, NHK), HD>>>();
    gate_kernel<<<dim3(NB, NHK), GH>>>(gate_wq, gate_wk);
    mask_kernel<<<dim3(NB, NHK), 32>>>();

    // 4. Block-sparse flash attention, 8 consumer warps (fused O-proj pack)
    cudaFuncSetAttribute(attn_mma_kernel,
                         cudaFuncAttributeMaxDynamicSharedMemorySize, ATTN_SMEM);
    attn_mma_kernel<<<dim3(NB, NH), 256, ATTN_SMEM>>>();

    // 5. Output projection (bf16x3 tensor cores)
    bf16x3_gemm<<<dim3(HIDDEN / 128, S_LEN / 128), 256>>>(
        (const uint32_t*)p_ah, (const uint32_t*)p_al,
        (const uint32_t*)p_woh, (const uint32_t*)p_wol,
        out, S_LEN, HIDDEN, HIDDEN / 2);
}

// round 11
// speedup vs baseline: 1.6810x; 1.0431x over previous
#include <cuda_runtime.h>
#include <cuda_bf16.h>
#include <cstdint>
#include <math.h>

// ---------------------------------------------------------------------------
// Problem constants
// ---------------------------------------------------------------------------
#define S_LEN   2048
#define HIDDEN  3072
#define NH      32
#define NHK     8
#define GQ      4
#define HD      96
#define BLK     64
#define NB      32
#define GH      128
#define OP      4608
#define KOFF    3072
#define VOFF    3840
#define K2H     (HIDDEN / 2)

// ---------------------------------------------------------------------------
// Scratch (device globals; no allocation allowed)
// ---------------------------------------------------------------------------
__device__ float g_qkv [S_LEN * OP];
__device__ float g_q   [S_LEN * NH  * HD];
__device__ float g_k   [S_LEN * NHK * HD];
__device__ float g_qpool[NB * NHK * HD];
__device__ float g_kpool[NB * NHK * 2 * HD];
__device__ float g_qgate[NB * NHK * GH];
__device__ float g_kgate[NB * NHK * GH];
__device__ int   g_maskbuf[NHK * NB * NB];

// bf16 hi/lo packed GEMM operands (k-pairs packed into one uint32)
__device__ uint32_t g_ah [S_LEN * K2H];       // A hi (hs, then attn out)
__device__ uint32_t g_al [S_LEN * K2H];       // A lo
__device__ uint32_t g_wqh[K2H * OP];
__device__ uint32_t g_wql[K2H * OP];
__device__ uint32_t g_woh[K2H * HIDDEN];
__device__ uint32_t g_wol[K2H * HIDDEN];

// Pre-converted attention operands (bf16 hi/lo)
__device__ uint16_t g_kbh[NHK * S_LEN * HD];  // K  [hk][t][d]
__device__ uint16_t g_kbl[NHK * S_LEN * HD];
__device__ uint16_t g_vth[NHK * HD * S_LEN];  // V^T [hk][d][t]
__device__ uint16_t g_vtl[NHK * HD * S_LEN];

// ---------------------------------------------------------------------------
// bf16 hi/lo split helpers
// ---------------------------------------------------------------------------
__device__ __forceinline__ void bsplit(float x, uint32_t& h, uint32_t& l)
{
    __nv_bfloat16 hb = __float2bfloat16(x);
    float hf = __bfloat162float(hb);
    __nv_bfloat16 lb = __float2bfloat16(x - hf);
    h = (uint32_t)__bfloat16_as_ushort(hb);
    l = (uint32_t)__bfloat16_as_ushort(lb);
}

__device__ __forceinline__ void split1(float x, uint16_t& h, uint16_t& l)
{
    __nv_bfloat16 hb = __float2bfloat16(x);
    h = __bfloat16_as_ushort(hb);
    l = __bfloat16_as_ushort(__float2bfloat16(x - __bfloat162float(hb)));
}

__device__ __forceinline__ uint32_t split2(float x, float y, uint32_t& lo)
{
    __nv_bfloat16 hx = __float2bfloat16(x), hy = __float2bfloat16(y);
    float rx = x - __bfloat162float(hx), ry = y - __bfloat162float(hy);
    __nv_bfloat16 lx = __float2bfloat16(rx), ly = __float2bfloat16(ry);
    lo = (uint32_t)__bfloat16_as_ushort(lx) | ((uint32_t)__bfloat16_as_ushort(ly) << 16);
    return (uint32_t)__bfloat16_as_ushort(hx) | ((uint32_t)__bfloat16_as_ushort(hy) << 16);
}

// Pack A (row-major M x K): word i = (x[2i], x[2i+1]) along k
__global__ void packA_kernel(const float* __restrict__ in,
                             uint32_t* __restrict__ hi, uint32_t* __restrict__ lo,
                             int total2)
{
    int i = blockIdx.x * blockDim.x + threadIdx.x;
    if (i >= total2) return;
    float2 v = ((const float2*)in)[i];
    uint32_t h0, l0, h1, l1;
    bsplit(v.x, h0, l0);
    bsplit(v.y, h1, l1);
    hi[i] = h0 | (h1 << 16);
    lo[i] = l0 | (l1 << 16);
}

// Pack B (row-major K x N): out[k2][n] = (B[2k2][n], B[2k2+1][n])
__global__ void packB_kernel(const float* __restrict__ in,
                             uint32_t* __restrict__ hi, uint32_t* __restrict__ lo,
                             int N, int total)
{
    int i = blockIdx.x * blockDim.x + threadIdx.x;
    if (i >= total) return;
    int k2 = i / N, n = i - k2 * N;
    float x0 = in[(size_t)(2 * k2) * N + n];
    float x1 = in[(size_t)(2 * k2 + 1) * N + n];
    uint32_t h0, l0, h1, l1;
    bsplit(x0, h0, l0);
    bsplit(x1, h1, l1);
    hi[i] = h0 | (h1 << 16);
    lo[i] = l0 | (l1 << 16);
}

// K pre-convert: g_k [s][hk][d] -> g_kbh/g_kbl [hk][s][d]
__global__ void convK_kernel()
{
    int i = blockIdx.x * blockDim.x + threadIdx.x;
    if (i >= S_LEN * NHK * HD) return;
    int d = i % HD, hk = (i / HD) % NHK, s = i / (HD * NHK);
    float v = g_k[(size_t)s * (NHK * HD) + hk * HD + d];
    uint16_t h, l;
    split1(v, h, l);
    size_t o = ((size_t)hk * S_LEN + s) * HD + d;
    g_kbh[o] = h;
    g_kbl[o] = l;
}

// V pre-convert + transpose: g_qkv [s][VOFF+hk*HD+d] -> g_vth/g_vtl [hk][d][s]
__global__ void convV_kernel()
{
    __shared__ float t[32][33];
    const int s0 = blockIdx.x * 32, d0 = blockIdx.y * 32, hk = blockIdx.z;
    const int tx = threadIdx.x & 31, ty = threadIdx.x >> 5;
#pragma unroll
    for (int i = 0; i < 32; i += 8)
        t[ty + i][tx] = g_qkv[(size_t)(s0 + ty + i) * OP + VOFF + hk * HD + d0 + tx];
    __syncthreads();
#pragma unroll
    for (int i = 0; i < 32; i += 8) {
        float v = t[tx][ty + i];
        uint16_t h, l;
        split1(v, h, l);
        size_t o = ((size_t)hk * HD + d0 + ty + i) * S_LEN + s0 + tx;
        g_vth[o] = h;
        g_vtl[o] = l;
    }
}

// ---------------------------------------------------------------------------
// bf16x3 tensor-core GEMM (proven R7 version)
// ---------------------------------------------------------------------------
#define PADB 136

#define MMA_BF16(CC, A0, A1, A2, A3, B0, B1)                                   \
    asm volatile(                                                              \
        "mma.sync.aligned.m16n8k16.row.col.f32.bf16.bf16.f32 "                 \
        "{%0,%1,%2,%3}, {%4,%5,%6,%7}, {%8,%9}, {%0,%1,%2,%3};"                \
        : "+f"(CC[0]), "+f"(CC[1]), "+f"(CC[2]), "+f"(CC[3])                   \
        : "r"(A0), "r"(A1), "r"(A2), "r"(A3), "r"(B0), "r"(B1))

__global__ __launch_bounds__(256, 2)
void bf16x3_gemm(const uint32_t* __restrict__ Agh, const uint32_t* __restrict__ Agl,
                 const uint32_t* __restrict__ Bgh, const uint32_t* __restrict__ Bgl,
                 float* __restrict__ C, int M, int N, int K2)
{
    __shared__ __align__(16) uint32_t Ah[2][8][PADB], Al[2][8][PADB];
    __shared__ __align__(16) uint32_t Bh[2][8][PADB], Bl[2][8][PADB];

    const int tid  = threadIdx.x;
    const int bn   = blockIdx.x, bm = blockIdx.y;
    const int warp = tid >> 5,  lane = tid & 31;
    const int wm   = warp >> 2, wn   = warp & 3;
    const int gid  = lane >> 2, tig  = lane & 3;

    const int a_r = tid >> 1, a_c = (tid & 1) * 4;
    const int b_r = tid >> 5, b_c = (tid & 31) * 4;

    const uint32_t* Aph = Agh + (size_t)(bm * 128 + a_r) * K2 + a_c;
    const uint32_t* Apl = Agl + (size_t)(bm * 128 + a_r) * K2 + a_c;
    const uint32_t* Bph = Bgh + (size_t)b_r * N + bn * 128 + b_c;
    const uint32_t* Bpl = Bgl + (size_t)b_r * N + bn * 128 + b_c;

    uint4 rah = *(const uint4*)Aph;
    uint4 ral = *(const uint4*)Apl;
    uint4 rbh = *(const uint4*)Bph;
    uint4 rbl = *(const uint4*)Bpl;

    Ah[0][a_c + 0][a_r] = rah.x; Ah[0][a_c + 1][a_r] = rah.y;
    Ah[0][a_c + 2][a_r] = rah.z; Ah[0][a_c + 3][a_r] = rah.w;
    Al[0][a_c + 0][a_r] = ral.x; Al[0][a_c + 1][a_r] = ral.y;
    Al[0][a_c + 2][a_r] = ral.z; Al[0][a_c + 3][a_r] = ral.w;
    *(uint4*)&Bh[0][b_r][b_c] = rbh;
    *(uint4*)&Bl[0][b_r][b_c] = rbl;
    __syncthreads();

    float acc[4][4][4];
#pragma unroll
    for (int mt = 0; mt < 4; mt++)
#pragma unroll
        for (int nt = 0; nt < 4; nt++)
#pragma unroll
            for (int r = 0; r < 4; r++) acc[mt][nt][r] = 0.f;

    const int nst = K2 >> 3;
    for (int st = 0; st < nst; st++) {
        const int cur = st & 1;
        const bool more = (st + 1 < nst);
        if (more) {
            rah = *(const uint4*)(Aph + (st + 1) * 8);
            ral = *(const uint4*)(Apl + (st + 1) * 8);
            rbh = *(const uint4*)(Bph + (size_t)(st + 1) * 8 * N);
            rbl = *(const uint4*)(Bpl + (size_t)(st + 1) * 8 * N);
        }

        uint32_t bhf[4][2], blf[4][2];
#pragma unroll
        for (int nt = 0; nt < 4; nt++) {
            const int n0 = wn * 32 + nt * 8;
            bhf[nt][0] = Bh[cur][tig][n0 + gid];
            bhf[nt][1] = Bh[cur][tig + 4][n0 + gid];
            blf[nt][0] = Bl[cur][tig][n0 + gid];
            blf[nt][1] = Bl[cur][tig + 4][n0 + gid];
        }

#pragma unroll
        for (int mt = 0; mt < 4; mt++) {
            const int m0 = wm * 64 + mt * 16;
            uint32_t ah0 = Ah[cur][tig][m0 + gid];
            uint32_t ah1 = Ah[cur][tig][m0 + gid + 8];
            uint32_t ah2 = Ah[cur][tig + 4][m0 + gid];
            uint32_t ah3 = Ah[cur][tig + 4][m0 + gid + 8];
            uint32_t al0 = Al[cur][tig][m0 + gid];
            uint32_t al1 = Al[cur][tig][m0 + gid + 8];
            uint32_t al2 = Al[cur][tig + 4][m0 + gid];
            uint32_t al3 = Al[cur][tig + 4][m0 + gid + 8];
#pragma unroll
            for (int nt = 0; nt < 4; nt++) {
                MMA_BF16(acc[mt][nt], ah0, ah1, ah2, ah3, bhf[nt][0], bhf[nt][1]);
                MMA_BF16(acc[mt][nt], ah0, ah1, ah2, ah3, blf[nt][0], blf[nt][1]);
                MMA_BF16(acc[mt][nt], al0, al1, al2, al3, bhf[nt][0], bhf[nt][1]);
            }
        }

        if (more) {
            const int nxt = cur ^ 1;
            Ah[nxt][a_c + 0][a_r] = rah.x; Ah[nxt][a_c + 1][a_r] = rah.y;
            Ah[nxt][a_c + 2][a_r] = rah.z; Ah[nxt][a_c + 3][a_r] = rah.w;
            Al[nxt][a_c + 0][a_r] = ral.x; Al[nxt][a_c + 1][a_r] = ral.y;
            Al[nxt][a_c + 2][a_r] = ral.z; Al[nxt][a_c + 3][a_r] = ral.w;
            *(uint4*)&Bh[nxt][b_r][b_c] = rbh;
            *(uint4*)&Bl[nxt][b_r][b_c] = rbl;
            __syncthreads();
        }
    }

#pragma unroll
    for (int mt = 0; mt < 4; mt++) {
        const int row = bm * 128 + wm * 64 + mt * 16 + gid;
#pragma unroll
        for (int nt = 0; nt < 4; nt++) {
            const int col = bn * 128 + wn * 32 + nt * 8 + tig * 2;
            *(float2*)&C[(size_t)row * N + col] =
                make_float2(acc[mt][nt][0], acc[mt][nt][1]);
            *(float2*)&C[(size_t)(row + 8) * N + col] =
                make_float2(acc[mt][nt][2], acc[mt][nt][3]);
        }
    }
}

// ---------------------------------------------------------------------------
// RoPE
// ---------------------------------------------------------------------------
__global__ void rope_kernel(const float* __restrict__ cosb,
                            const float* __restrict__ sinb)
{
    const int total = S_LEN * (NH + NHK) * HD;
    int idx = blockIdx.x * blockDim.x + threadIdx.x;
    if (idx >= total) return;
    int d = idx % HD;
    int h = (idx / HD) % (NH + NHK);
    int s = idx / (HD * (NH + NHK));
    const float* row = g_qkv + (size_t)s * OP;
    float c  = cosb[s * HD + d];
    float sn = sinb[s * HD + d];
    if (h < NH) {
        int base = h * HD;
        float x = row[base + d];
        float r = (d < HD / 2) ? -row[base + d + HD / 2] : row[base + d - HD / 2];
        g_q[(size_t)s * (NH * HD) + h * HD + d] = x * c + r * sn;
    } else {
        int hk = h - NH;
        int base = KOFF + hk * HD;
        float x = row[base + d];
        float r = (d < HD / 2) ? -row[base + d + HD / 2] : row[base + d - HD / 2];
        g_k[(size_t)s * (NHK * HD) + hk * HD + d] = x * c + r * sn;
    }
}

// ---------------------------------------------------------------------------
// Pooling / gates / mask (unchanged)
// ---------------------------------------------------------------------------
__global__ void pool_kernel()
{
    int nb = blockIdx.x, hk = blockIdx.y, d = threadIdx.x;
    float ksum = 0.f, kmax = -3.0e38f, qsum = 0.f;
#pragma unroll 4
    for (int t = 0; t < BLK; t++) {
        const float* row = g_qkv + (size_t)(nb * BLK + t) * OP;
        float kv = row[KOFF + hk * HD + d];
        ksum += kv;
        kmax = fmaxf(kmax, kv);
#pragma unroll
        for (int g = 0; g < GQ; g++) qsum += row[(hk * GQ + g) * HD + d];
    }
    int bh = nb * NHK + hk;
    g_kpool[bh * (2 * HD) + d]      = ksum * (1.f / BLK);
    g_kpool[bh * (2 * HD) + HD + d] = kmax;
    g_qpool[bh * HD + d]            = qsum * (1.f / (BLK * GQ));
}

__global__ void gate_kernel(const float* __restrict__ gate_wq,
                            const float* __restrict__ gate_wk)
{
    int nb = blockIdx.x, hk = blockIdx.y, g = threadIdx.x;
    int bh = nb * NHK + hk;
    float qa = 0.f;
#pragma unroll 8
    for (int d = 0; d < HD; d++)
        qa += g_qpool[bh * HD + d] * gate_wq[d * GH + g];
    float ka = 0.f;
#pragma unroll 8
    for (int e = 0; e < 2 * HD; e++)
        ka += g_kpool[bh * (2 * HD) + e] * gate_wk[e * GH + g];
    g_qgate[bh * GH + g] = qa;
    g_kgate[bh * GH + g] = ka;
}

__global__ void mask_kernel()
{
    int qb = blockIdx.x, hk = blockIdx.y, kb = threadIdx.x;
    float l = -1e30f;
    if (kb <= qb) {
        float dot = 0.f;
#pragma unroll 8
        for (int g = 0; g < GH; g++)
            dot += g_qgate[(size_t)(qb * NHK + hk) * GH + g]
                 * g_kgate[(size_t)(kb * NHK + hk) * GH + g];
        l = dot * rsqrtf((float)GH);
    }
    float mx = l;
#pragma unroll
    for (int o = 16; o > 0; o >>= 1) mx = fmaxf(mx, __shfl_xor_sync(0xffffffffu, mx, o));
    float e = expf(l - mx);
    float sm = e;
#pragma unroll
    for (int o = 16; o > 0; o >>= 1) sm += __shfl_xor_sync(0xffffffffu, sm, o);
    float p = e / sm;
    int keep = ((p >= 0.03f) && (kb <= qb)) || (kb == qb);
    g_maskbuf[(hk * NB + qb) * NB + kb] = keep;
}

// ---------------------------------------------------------------------------
// Block-sparse flash attention v3:
// - 8 consumer warps, warp = (row group w&3, column half w>>2)
// - split-softmax: per-half running (m,l,O), single end-of-kernel merge
// - single-buffered KV via cp.async -> smem 80KB -> 2 CTAs/SM
// - Q fragments re-loaded from smem per block (register budget for occ 2)
// - descending-qb CTA order (longest first)
// ---------------------------------------------------------------------------
#define QSTR 104
#define VSTR 72

#define OFF_QH  0
#define OFF_QL  13312
#define OFF_KH  26624
#define OFF_KL  39936
#define OFF_VH  53248
#define OFF_VL  67072
#define OFF_PM  80896
#define OFF_PS  81408
#define OFF_BL  81920
#define OFF_OB  0          /* aliased over dead Q region in the epilogue */
#define ATTN_SMEM 82176

#define LDSM4(R0, R1, R2, R3, ADDR)                                            \
    asm volatile("ldmatrix.sync.aligned.m8n8.x4.shared.b16 {%0,%1,%2,%3}, [%4];" \
                 : "=r"(R0), "=r"(R1), "=r"(R2), "=r"(R3) : "r"(ADDR))

#define MMAB(CC, A, B0, B1)                                                    \
    asm volatile(                                                              \
        "mma.sync.aligned.m16n8k16.row.col.f32.bf16.bf16.f32 "                 \
        "{%0,%1,%2,%3}, {%4,%5,%6,%7}, {%8,%9}, {%0,%1,%2,%3};"                \
        : "+f"((CC)[0]), "+f"((CC)[1]), "+f"((CC)[2]), "+f"((CC)[3])           \
        : "r"((A)[0]), "r"((A)[1]), "r"((A)[2]), "r"((A)[3]), "r"(B0), "r"(B1))

#define CPA16(DST, SRC) \
    asm volatile("cp.async.cg.shared.global [%0], [%1], 16;" :: "r"(DST), "l"(SRC))
#define CPA_COMMIT() asm volatile("cp.async.commit_group;" ::: "memory")

__device__ __forceinline__ void kv_issue(uint32_t sb, int kb,
                                         const uint16_t* __restrict__ Khg,
                                         const uint16_t* __restrict__ Klg,
                                         const uint16_t* __restrict__ Vhg,
                                         const uint16_t* __restrict__ Vlg,
                                         int tid)
{
    // K: 64 rows x 96 d (192B = 12 chunks/row)
#pragma unroll
    for (int it = 0; it < 3; it++) {
        int idx = tid + it * 256;
        int c = idx / 12, ck = idx % 12;
        const char* sh = (const char*)(Khg + (size_t)(kb * BLK + c) * HD) + ck * 16;
        const char* sl = (const char*)(Klg + (size_t)(kb * BLK + c) * HD) + ck * 16;
        uint32_t d = (uint32_t)(c * QSTR + ck * 8) * 2;
        CPA16(sb + OFF_KH + d, sh);
        CPA16(sb + OFF_KL + d, sl);
    }
    // V^T: 96 rows x 64 t (128B = 8 chunks/row)
#pragma unroll
    for (int it = 0; it < 3; it++) {
        int idx = tid + it * 256;
        int dr = idx / 8, ck = idx % 8;
        const char* sh = (const char*)(Vhg + (size_t)dr * S_LEN + kb * BLK) + ck * 16;
        const char* sl = (const char*)(Vlg + (size_t)dr * S_LEN + kb * BLK) + ck * 16;
        uint32_t d = (uint32_t)(dr * VSTR + ck * 8) * 2;
        CPA16(sb + OFF_VH + d, sh);
        CPA16(sb + OFF_VL + d, sl);
    }
}

__global__ __launch_bounds__(256, 2)
void attn_mma_kernel()
{
    extern __shared__ char smem[];
    const int qb = NB - 1 - blockIdx.x;          // longest CTAs first
    const int h = blockIdx.y, hk = h >> 2;
    const int tid = threadIdx.x;
    int* blist = (int*)(smem + OFF_BL);

    if (tid < 32) {
        int kb = tid;
        const int* mrow = g_maskbuf + (hk * NB + qb) * NB;
        int keep = (kb <= qb) && mrow[kb];
        unsigned bm = __ballot_sync(0xffffffffu, keep);
        if (keep) blist[__popc(bm & ((1u << kb) - 1u))] = kb;
        if (tid == 0) blist[32] = __popc(bm);
    }

    // Load Q (scaled) -> hi/lo smem
    {
        const float scale = rsqrtf((float)HD);
        uint16_t* Qh = (uint16_t*)(smem + OFF_QH);
        uint16_t* Ql = (uint16_t*)(smem + OFF_QL);
        for (int i = tid; i < 64 * 24; i += 256) {
            int r = i / 24, d4 = (i % 24) * 4;
            float4 v = *(const float4*)&g_q[(size_t)(qb * BLK + r) * (NH * HD) + h * HD + d4];
            v.x *= scale; v.y *= scale; v.z *= scale; v.w *= scale;
            ushort4 hi, lo;
            split1(v.x, hi.x, lo.x); split1(v.y, hi.y, lo.y);
            split1(v.z, hi.z, lo.z); split1(v.w, hi.w, lo.w);
            *(ushort4*)&Qh[r * QSTR + d4] = hi;
            *(ushort4*)&Ql[r * QSTR + d4] = lo;
        }
    }
    __syncthreads();

    const int nblk = blist[32];
    const int lane = tid & 31, warp = tid >> 5;
    const int wr = warp & 3;          // row group
    const int ch = warp >> 2;         // column half (0: cols 0-31, 1: 32-63)
    const int row0 = wr * 16;
    const int g    = lane & 7, quad = lane >> 3;
    const int gid  = lane >> 2, tig = lane & 3;
    const uint32_t sb = (uint32_t)__cvta_generic_to_shared(smem);

    const uint16_t* Khg = g_kbh + (size_t)hk * S_LEN * HD;
    const uint16_t* Klg = g_kbl + (size_t)hk * S_LEN * HD;
    const uint16_t* Vhg = g_vth + (size_t)hk * HD * S_LEN;
    const uint16_t* Vlg = g_vtl + (size_t)hk * HD * S_LEN;

    float* pm = (float*)(smem + OFF_PM);   // [2][64]
    float* ps = (float*)(smem + OFF_PS);   // [2][64]

    float o[12][4];
#pragma unroll
    for (int dt = 0; dt < 12; dt++)
#pragma unroll
        for (int e = 0; e < 4; e++) o[dt][e] = 0.f;
    float m0 = -1e30f, m1 = -1e30f, l0 = 0.f, l1 = 0.f;

    const int kr = g + ((quad >> 1) << 3);
    const int kd = (quad & 1) << 3;
    const int qar = row0 + g + ((quad & 1) << 3);
    const int qad = (quad & 2) << 2;

    kv_issue(sb, blist[0], Khg, Klg, Vhg, Vlg, tid);
    CPA_COMMIT();

    for (int i = 0; i < nblk; i++) {
        const int kb = blist[i];
        asm volatile("cp.async.wait_group 0;" ::: "memory");
        __syncthreads();

        const uint32_t khb = sb + OFF_KH, klb = sb + OFF_KL;
        const uint32_t vhb = sb + OFF_VH, vlb = sb + OFF_VL;

        // ---- S = Q K^T (this warp's 32-column half) ----
        float st[4][4];
#pragma unroll
        for (int nt = 0; nt < 4; nt++)
#pragma unroll
            for (int e = 0; e < 4; e++) st[nt][e] = 0.f;

#pragma unroll
        for (int ks = 0; ks < 6; ks++) {
            uint32_t qh[4], ql[4];
            {
                uint32_t qoff = (uint32_t)(qar * QSTR + ks * 16 + qad) * 2u;
                LDSM4(qh[0], qh[1], qh[2], qh[3], sb + OFF_QH + qoff);
                LDSM4(ql[0], ql[1], ql[2], ql[3], sb + OFF_QL + qoff);
            }
#pragma unroll
            for (int j = 0; j < 2; j++) {
                const int ng = ch * 2 + j;
                uint32_t off = (uint32_t)((ng * 16 + kr) * QSTR + ks * 16 + kd) * 2u;
                uint32_t b0, b1, b2, b3, c0, c1, c2, c3;
                LDSM4(b0, b1, b2, b3, khb + off);
                LDSM4(c0, c1, c2, c3, klb + off);
                MMAB(st[2 * j],     qh, b0, b1);
                MMAB(st[2 * j + 1], qh, b2, b3);
                MMAB(st[2 * j],     qh, c0, c1);
                MMAB(st[2 * j + 1], qh, c2, c3);
                MMAB(st[2 * j],     ql, b0, b1);
                MMAB(st[2 * j + 1], ql, b2, b3);
            }
        }

        // ---- diagonal causal mask ----
        if (kb == qb) {
            const int rA = row0 + gid, rB = rA + 8;
#pragma unroll
            for (int nt = 0; nt < 4; nt++) {
                int cb = ch * 32 + nt * 8 + tig * 2;
                if (cb     > rA) st[nt][0] = -1e30f;
                if (cb + 1 > rA) st[nt][1] = -1e30f;
                if (cb     > rB) st[nt][2] = -1e30f;
                if (cb + 1 > rB) st[nt][3] = -1e30f;
            }
        }

        // ---- per-half online softmax (no cross-half exchange) ----
        float mA = -1e30f, mB = -1e30f;
#pragma unroll
        for (int nt = 0; nt < 4; nt++) {
            mA = fmaxf(mA, fmaxf(st[nt][0], st[nt][1]));
            mB = fmaxf(mB, fmaxf(st[nt][2], st[nt][3]));
        }
        mA = fmaxf(mA, __shfl_xor_sync(0xffffffffu, mA, 1));
        mA = fmaxf(mA, __shfl_xor_sync(0xffffffffu, mA, 2));
        mB = fmaxf(mB, __shfl_xor_sync(0xffffffffu, mB, 1));
        mB = fmaxf(mB, __shfl_xor_sync(0xffffffffu, mB, 2));

        float nmA = fmaxf(m0, mA), nmB = fmaxf(m1, mB);
        float cA = __expf(m0 - nmA), cB = __expf(m1 - nmB);
        float sA = 0.f, sB = 0.f;
#pragma unroll
        for (int nt = 0; nt < 4; nt++) {
            st[nt][0] = __expf(st[nt][0] - nmA); sA += st[nt][0];
            st[nt][1] = __expf(st[nt][1] - nmA); sA += st[nt][1];
            st[nt][2] = __expf(st[nt][2] - nmB); sB += st[nt][2];
            st[nt][3] = __expf(st[nt][3] - nmB); sB += st[nt][3];
        }
        sA += __shfl_xor_sync(0xffffffffu, sA, 1);
        sA += __shfl_xor_sync(0xffffffffu, sA, 2);
        sB += __shfl_xor_sync(0xffffffffu, sB, 1);
        sB += __shfl_xor_sync(0xffffffffu, sB, 2);
        l0 = l0 * cA + sA; m0 = nmA;
        l1 = l1 * cB + sB; m1 = nmB;
#pragma unroll
        for (int dt = 0; dt < 12; dt++) {
            o[dt][0] *= cA; o[dt][1] *= cA;
            o[dt][2] *= cB; o[dt][3] *= cB;
        }

        // ---- pack P ----
        uint32_t ph[2][4], pl[2][4];
#pragma unroll
        for (int j = 0; j < 2; j++) {
            ph[j][0] = split2(st[2 * j][0],     st[2 * j][1],     pl[j][0]);
            ph[j][1] = split2(st[2 * j][2],     st[2 * j][3],     pl[j][1]);
            ph[j][2] = split2(st[2 * j + 1][0], st[2 * j + 1][1], pl[j][2]);
            ph[j][3] = split2(st[2 * j + 1][2], st[2 * j + 1][3], pl[j][3]);
        }

        // ---- O += P V (this half's t range) ----
#pragma unroll
        for (int dt = 0; dt < 12; dt++) {
            uint32_t off = (uint32_t)((dt * 8 + g) * VSTR + ch * 32 + quad * 8) * 2u;
            uint32_t v0, v1, v2, v3, w0, w1, w2, w3;
            LDSM4(v0, v1, v2, v3, vhb + off);
            LDSM4(w0, w1, w2, w3, vlb + off);
            MMAB(o[dt], ph[0], v0, v1);
            MMAB(o[dt], ph[0], w0, w1);
            MMAB(o[dt], pl[0], v0, v1);
            MMAB(o[dt], ph[1], v2, v3);
            MMAB(o[dt], ph[1], w2, w3);
            MMAB(o[dt], pl[1], v2, v3);
        }

        __syncthreads();
        if (i + 1 < nblk) {
            kv_issue(sb, blist[i + 1], Khg, Klg, Vhg, Vlg, tid);
            CPA_COMMIT();
        }
    }

    // ---- cross-half merge (split-KV style) ----
    if (tig == 0) {
        pm[ch * 64 + row0 + gid]     = m0;
        pm[ch * 64 + row0 + gid + 8] = m1;
        ps[ch * 64 + row0 + gid]     = l0;
        ps[ch * 64 + row0 + gid + 8] = l1;
    }
    __syncthreads();
    float mo0 = pm[(ch ^ 1) * 64 + row0 + gid];
    float mo1 = pm[(ch ^ 1) * 64 + row0 + gid + 8];
    float lo0 = ps[(ch ^ 1) * 64 + row0 + gid];
    float lo1 = ps[(ch ^ 1) * 64 + row0 + gid + 8];
    float M0 = fmaxf(m0, mo0), M1 = fmaxf(m1, mo1);
    float sc0 = __expf(m0 - M0), sc1 = __expf(m1 - M1);
    float L0 = l0 * sc0 + lo0 * __expf(mo0 - M0);
    float L1 = l1 * sc1 + lo1 * __expf(mo1 - M1);
#pragma unroll
    for (int dt = 0; dt < 12; dt++) {
        o[dt][0] *= sc0; o[dt][1] *= sc0;
        o[dt][2] *= sc1; o[dt][3] *= sc1;
    }

    float* Obuf = (float*)(smem + OFF_OB);   // aliases dead Q region
    __syncthreads();
    if (ch == 1) {
#pragma unroll
        for (int dt = 0; dt < 12; dt++) {
            int col = dt * 8 + tig * 2;
            *(float2*)&Obuf[(row0 + gid) * 100 + col] =
                make_float2(o[dt][0], o[dt][1]);
            *(float2*)&Obuf[(row0 + gid + 8) * 100 + col] =
                make_float2(o[dt][2], o[dt][3]);
        }
    }
    __syncthreads();
    if (ch == 0) {
        const float iA = 1.f / L0, iB = 1.f / L1;
        const int rA = qb * BLK + row0 + gid;
#pragma unroll
        for (int dt = 0; dt < 12; dt++) {
            int col = dt * 8 + tig * 2;
            float2 oa = *(float2*)&Obuf[(row0 + gid) * 100 + col];
            float2 ob = *(float2*)&Obuf[(row0 + gid + 8) * 100 + col];
            float x0 = (o[dt][0] + oa.x) * iA;
            float x1 = (o[dt][1] + oa.y) * iA;
            float x2 = (o[dt][2] + ob.x) * iB;
            float x3 = (o[dt][3] + ob.y) * iB;
            int k2 = (h * HD + col) >> 1;
            uint32_t loA, loB;
            uint32_t hiA = split2(x0, x1, loA);
            uint32_t hiB = split2(x2, x3, loB);
            g_ah[(size_t)rA * K2H + k2]       = hiA;
            g_al[(size_t)rA * K2H + k2]       = loA;
            g_ah[(size_t)(rA + 8) * K2H + k2] = hiB;
            g_al[(size_t)(rA + 8) * K2H + k2] = loB;
        }
    }
}

// ---------------------------------------------------------------------------
// Launch
// ---------------------------------------------------------------------------
extern "C" void kernel_launch(void* const* d_in, const int* in_sizes, int n_in,
                              void* d_out, int out_size)
{
    const float* hs      = (const float*)d_in[0];
    const float* cosb    = (const float*)d_in[1];
    const float* sinb    = (const float*)d_in[2];
    const float* qkv_w   = (const float*)d_in[3];
    const float* o_w     = (const float*)d_in[4];
    const float* gate_wq = (const float*)d_in[5];
    const float* gate_wk = (const float*)d_in[6];
    float* out = (float*)d_out;

    void *p_qkv, *p_ah, *p_al, *p_wqh, *p_wql, *p_woh, *p_wol;
    cudaGetSymbolAddress(&p_qkv, g_qkv);
    cudaGetSymbolAddress(&p_ah, g_ah);
    cudaGetSymbolAddress(&p_al, g_al);
    cudaGetSymbolAddress(&p_wqh, g_wqh);
    cudaGetSymbolAddress(&p_wql, g_wql);
    cudaGetSymbolAddress(&p_woh, g_woh);
    cudaGetSymbolAddress(&p_wol, g_wol);

    // 0. Pack GEMM operands into bf16 hi/lo
    {
        int totW1 = K2H * OP;
        packB_kernel<<<(totW1 + 255) / 256, 256>>>(
            qkv_w, (uint32_t*)p_wqh, (uint32_t*)p_wql, OP, totW1);
        int totW2 = K2H * HIDDEN;
        packB_kernel<<<(totW2 + 255) / 256, 256>>>(
            o_w, (uint32_t*)p_woh, (uint32_t*)p_wol, HIDDEN, totW2);
        int totA = S_LEN * K2H;
        packA_kernel<<<(totA + 255) / 256, 256>>>(
            hs, (uint32_t*)p_ah, (uint32_t*)p_al, totA);
    }

    // 1. QKV projection (bf16x3 tensor cores)
    bf16x3_gemm<<<dim3(OP / 128, S_LEN / 128), 256>>>(
        (const uint32_t*)p_ah, (const uint32_t*)p_al,
        (const uint32_t*)p_wqh, (const uint32_t*)p_wql,
        (float*)p_qkv, S_LEN, OP, K2H);

    // 2. RoPE
    {
        int total = S_LEN * (NH + NHK) * HD;
        rope_kernel<<<(total + 255) / 256, 256>>>(cosb, sinb);
    }

    // 2b. Pre-convert K and V^T to bf16 hi/lo
    {
        int totK = S_LEN * NHK * HD;
        convK_kernel<<<(totK + 255) / 256, 256>>>();
        convV_kernel<<<dim3(S_LEN / 32, HD / 32, NHK), 256>>>();
    }

    // 3. Pool + gate + mask
    pool_kernel<<<dim3(NB, NHK), HD>>>();
    gate_kernel<<<dim3(NB, NHK), GH>>>(gate_wq, gate_wk);
    mask_kernel<<<dim3(NB, NHK), 32>>>();

    // 4. Block-sparse flash attention v3 (split-softmax, occ 2)
    cudaFuncSetAttribute(attn_mma_kernel,
                         cudaFuncAttributeMaxDynamicSharedMemorySize, ATTN_SMEM);
    attn_mma_kernel<<<dim3(NB, NH), 256, ATTN_SMEM>>>();

    // 5. Output projection (bf16x3 tensor cores)
    bf16x3_gemm<<<dim3(HIDDEN / 128, S_LEN / 128), 256>>>(
        (const uint32_t*)p_ah, (const uint32_t*)p_al,
        (const uint32_t*)p_woh, (const uint32_t*)p_wol,
        out, S_LEN, HIDDEN, HIDDEN / 2);
}

// round 12
// speedup vs baseline: 1.7415x; 1.0360x over previous
#include <cuda_runtime.h>
#include <cuda_bf16.h>
#include <cstdint>
#include <math.h>

// ---------------------------------------------------------------------------
// Problem constants
// ---------------------------------------------------------------------------
#define S_LEN   2048
#define HIDDEN  3072
#define NH      32
#define NHK     8
#define GQ      4
#define HD      96
#define BLK     64
#define NB      32
#define GH      128
#define OP      4608
#define KOFF    3072
#define VOFF    3840
#define K2H     (HIDDEN / 2)

// ---------------------------------------------------------------------------
// Scratch (device globals; no allocation allowed)
// ---------------------------------------------------------------------------
__device__ float g_qkv [S_LEN * OP];
__device__ float g_q   [S_LEN * NH  * HD];
__device__ float g_k   [S_LEN * NHK * HD];
__device__ float g_qpool[NB * NHK * HD];
__device__ float g_kpool[NB * NHK * 2 * HD];
__device__ float g_qgate[NB * NHK * GH];
__device__ float g_kgate[NB * NHK * GH];
__device__ int   g_maskbuf[NHK * NB * NB];

// bf16 hi/lo packed GEMM operands (k-pairs packed into one uint32)
__device__ uint32_t g_ah [S_LEN * K2H];       // A hi (hs, then attn out)
__device__ uint32_t g_al [S_LEN * K2H];       // A lo
__device__ uint32_t g_wqh[K2H * OP];
__device__ uint32_t g_wql[K2H * OP];
__device__ uint32_t g_woh[K2H * HIDDEN];
__device__ uint32_t g_wol[K2H * HIDDEN];

// Pre-converted attention operands (bf16 hi/lo)
__device__ uint16_t g_kbh[NHK * S_LEN * HD];  // K  [hk][t][d]
__device__ uint16_t g_kbl[NHK * S_LEN * HD];
__device__ uint16_t g_vth[NHK * HD * S_LEN];  // V^T [hk][d][t]
__device__ uint16_t g_vtl[NHK * HD * S_LEN];

// ---------------------------------------------------------------------------
// bf16 hi/lo split helpers
// ---------------------------------------------------------------------------
__device__ __forceinline__ void bsplit(float x, uint32_t& h, uint32_t& l)
{
    __nv_bfloat16 hb = __float2bfloat16(x);
    float hf = __bfloat162float(hb);
    __nv_bfloat16 lb = __float2bfloat16(x - hf);
    h = (uint32_t)__bfloat16_as_ushort(hb);
    l = (uint32_t)__bfloat16_as_ushort(lb);
}

__device__ __forceinline__ void split1(float x, uint16_t& h, uint16_t& l)
{
    __nv_bfloat16 hb = __float2bfloat16(x);
    h = __bfloat16_as_ushort(hb);
    l = __bfloat16_as_ushort(__float2bfloat16(x - __bfloat162float(hb)));
}

__device__ __forceinline__ uint32_t split2(float x, float y, uint32_t& lo)
{
    __nv_bfloat16 hx = __float2bfloat16(x), hy = __float2bfloat16(y);
    float rx = x - __bfloat162float(hx), ry = y - __bfloat162float(hy);
    __nv_bfloat16 lx = __float2bfloat16(rx), ly = __float2bfloat16(ry);
    lo = (uint32_t)__bfloat16_as_ushort(lx) | ((uint32_t)__bfloat16_as_ushort(ly) << 16);
    return (uint32_t)__bfloat16_as_ushort(hx) | ((uint32_t)__bfloat16_as_ushort(hy) << 16);
}

// Pack A (row-major M x K): word i = (x[2i], x[2i+1]) along k
__global__ void packA_kernel(const float* __restrict__ in,
                             uint32_t* __restrict__ hi, uint32_t* __restrict__ lo,
                             int total2)
{
    int i = blockIdx.x * blockDim.x + threadIdx.x;
    if (i >= total2) return;
    float2 v = ((const float2*)in)[i];
    uint32_t h0, l0, h1, l1;
    bsplit(v.x, h0, l0);
    bsplit(v.y, h1, l1);
    hi[i] = h0 | (h1 << 16);
    lo[i] = l0 | (l1 << 16);
}

// Pack B (row-major K x N): out[k2][n] = (B[2k2][n], B[2k2+1][n])
__global__ void packB_kernel(const float* __restrict__ in,
                             uint32_t* __restrict__ hi, uint32_t* __restrict__ lo,
                             int N, int total)
{
    int i = blockIdx.x * blockDim.x + threadIdx.x;
    if (i >= total) return;
    int k2 = i / N, n = i - k2 * N;
    float x0 = in[(size_t)(2 * k2) * N + n];
    float x1 = in[(size_t)(2 * k2 + 1) * N + n];
    uint32_t h0, l0, h1, l1;
    bsplit(x0, h0, l0);
    bsplit(x1, h1, l1);
    hi[i] = h0 | (h1 << 16);
    lo[i] = l0 | (l1 << 16);
}

// K pre-convert: g_k [s][hk][d] -> g_kbh/g_kbl [hk][s][d]
__global__ void convK_kernel()
{
    int i = blockIdx.x * blockDim.x + threadIdx.x;
    if (i >= S_LEN * NHK * HD) return;
    int d = i % HD, hk = (i / HD) % NHK, s = i / (HD * NHK);
    float v = g_k[(size_t)s * (NHK * HD) + hk * HD + d];
    uint16_t h, l;
    split1(v, h, l);
    size_t o = ((size_t)hk * S_LEN + s) * HD + d;
    g_kbh[o] = h;
    g_kbl[o] = l;
}

// V pre-convert + transpose: g_qkv [s][VOFF+hk*HD+d] -> g_vth/g_vtl [hk][d][s]
__global__ void convV_kernel()
{
    __shared__ float t[32][33];
    const int s0 = blockIdx.x * 32, d0 = blockIdx.y * 32, hk = blockIdx.z;
    const int tx = threadIdx.x & 31, ty = threadIdx.x >> 5;
#pragma unroll
    for (int i = 0; i < 32; i += 8)
        t[ty + i][tx] = g_qkv[(size_t)(s0 + ty + i) * OP + VOFF + hk * HD + d0 + tx];
    __syncthreads();
#pragma unroll
    for (int i = 0; i < 32; i += 8) {
        float v = t[tx][ty + i];
        uint16_t h, l;
        split1(v, h, l);
        size_t o = ((size_t)hk * HD + d0 + ty + i) * S_LEN + s0 + tx;
        g_vth[o] = h;
        g_vtl[o] = l;
    }
}

// ---------------------------------------------------------------------------
// bf16x3 tensor-core GEMM, cp.async 3-stage edition.
// A smem: [m][k2] rows of 8 words padded to 12 (48B, cp.async-aligned,
// conflict-free: 12*dg mod 32 never in [1,3]).  B smem: [k2][n] rows of 128
// words padded to 136.  No STS in the mainloop: global -> smem via cp.async.
// 128x128 tile, BK=16, 256 threads, warp tile 64x32, 3 MMAs per k16.
// ---------------------------------------------------------------------------
#define ASTRW 12
#define BSTRW 136
#define GOFF_AH(s) ((s) * 6144)
#define GOFF_AL(s) (18432 + (s) * 6144)
#define GOFF_BH(s) (36864 + (s) * 4352)
#define GOFF_BL(s) (49920 + (s) * 4352)
#define GEMM_SMEM 62976

#define MMA_BF16(CC, A0, A1, A2, A3, B0, B1)                                   \
    asm volatile(                                                              \
        "mma.sync.aligned.m16n8k16.row.col.f32.bf16.bf16.f32 "                 \
        "{%0,%1,%2,%3}, {%4,%5,%6,%7}, {%8,%9}, {%0,%1,%2,%3};"                \
        : "+f"(CC[0]), "+f"(CC[1]), "+f"(CC[2]), "+f"(CC[3])                   \
        : "r"(A0), "r"(A1), "r"(A2), "r"(A3), "r"(B0), "r"(B1))

#define GCPA16(DST, SRC) \
    asm volatile("cp.async.cg.shared.global [%0], [%1], 16;" :: "r"(DST), "l"(SRC))
#define GCPA_COMMIT() asm volatile("cp.async.commit_group;" ::: "memory")

__global__ __launch_bounds__(256, 2)
void bf16x3_gemm(const uint32_t* __restrict__ Agh, const uint32_t* __restrict__ Agl,
                 const uint32_t* __restrict__ Bgh, const uint32_t* __restrict__ Bgl,
                 float* __restrict__ C, int M, int N, int K2)
{
    extern __shared__ uint32_t gsm[];

    const int tid  = threadIdx.x;
    const int bn   = blockIdx.x, bm = blockIdx.y;
    const int warp = tid >> 5,  lane = tid & 31;
    const int wm   = warp >> 2, wn   = warp & 3;
    const int gid  = lane >> 2, tig  = lane & 3;
    const uint32_t sb = (uint32_t)__cvta_generic_to_shared(gsm);

    // cp.async mapping: A 128 rows x 2 halves (16B each); B 8 rows x 32 chunks
    const int a_r = tid >> 1, a_h = (tid & 1) * 4;
    const int b_r = tid >> 5, b_c = (tid & 31) * 4;

    const uint32_t* ApH = Agh + (size_t)(bm * 128 + a_r) * K2 + a_h;
    const uint32_t* ApL = Agl + (size_t)(bm * 128 + a_r) * K2 + a_h;
    const uint32_t* BpH = Bgh + (size_t)b_r * N + bn * 128 + b_c;
    const uint32_t* BpL = Bgl + (size_t)b_r * N + bn * 128 + b_c;
    const uint32_t a_dst = (uint32_t)(a_r * ASTRW + a_h) * 4;
    const uint32_t b_dst = (uint32_t)(b_r * BSTRW + b_c) * 4;

    const int nst = K2 >> 3;

#define GEMM_ISSUE(S)                                                          \
    do {                                                                       \
        const int _b = (S) % 3;                                                \
        GCPA16(sb + GOFF_AH(_b) + a_dst, ApH + (S) * 8);                       \
        GCPA16(sb + GOFF_AL(_b) + a_dst, ApL + (S) * 8);                       \
        GCPA16(sb + GOFF_BH(_b) + b_dst, BpH + (size_t)(S) * 8 * N);           \
        GCPA16(sb + GOFF_BL(_b) + b_dst, BpL + (size_t)(S) * 8 * N);           \
        GCPA_COMMIT();                                                         \
    } while (0)

    GEMM_ISSUE(0);
    if (nst > 1) GEMM_ISSUE(1);

    float acc[4][4][4];
#pragma unroll
    for (int mt = 0; mt < 4; mt++)
#pragma unroll
        for (int nt = 0; nt < 4; nt++)
#pragma unroll
            for (int r = 0; r < 4; r++) acc[mt][nt][r] = 0.f;

    for (int st = 0; st < nst; st++) {
        const int b = st % 3;
        if (st + 1 < nst) asm volatile("cp.async.wait_group 1;" ::: "memory");
        else              asm volatile("cp.async.wait_group 0;" ::: "memory");
        __syncthreads();

        const uint32_t* Ah = gsm + GOFF_AH(b) / 4;
        const uint32_t* Al = gsm + GOFF_AL(b) / 4;
        const uint32_t* Bh = gsm + GOFF_BH(b) / 4;
        const uint32_t* Bl = gsm + GOFF_BL(b) / 4;

        uint32_t bhf[4][2], blf[4][2];
#pragma unroll
        for (int nt = 0; nt < 4; nt++) {
            const int n0 = wn * 32 + nt * 8;
            bhf[nt][0] = Bh[tig * BSTRW + n0 + gid];
            bhf[nt][1] = Bh[(tig + 4) * BSTRW + n0 + gid];
            blf[nt][0] = Bl[tig * BSTRW + n0 + gid];
            blf[nt][1] = Bl[(tig + 4) * BSTRW + n0 + gid];
        }

#pragma unroll
        for (int mt = 0; mt < 4; mt++) {
            const int m0 = wm * 64 + mt * 16;
            uint32_t ah0 = Ah[(m0 + gid) * ASTRW + tig];
            uint32_t ah1 = Ah[(m0 + gid + 8) * ASTRW + tig];
            uint32_t ah2 = Ah[(m0 + gid) * ASTRW + tig + 4];
            uint32_t ah3 = Ah[(m0 + gid + 8) * ASTRW + tig + 4];
            uint32_t al0 = Al[(m0 + gid) * ASTRW + tig];
            uint32_t al1 = Al[(m0 + gid + 8) * ASTRW + tig];
            uint32_t al2 = Al[(m0 + gid) * ASTRW + tig + 4];
            uint32_t al3 = Al[(m0 + gid + 8) * ASTRW + tig + 4];
#pragma unroll
            for (int nt = 0; nt < 4; nt++) {
                MMA_BF16(acc[mt][nt], ah0, ah1, ah2, ah3, bhf[nt][0], bhf[nt][1]);
                MMA_BF16(acc[mt][nt], ah0, ah1, ah2, ah3, blf[nt][0], blf[nt][1]);
                MMA_BF16(acc[mt][nt], al0, al1, al2, al3, bhf[nt][0], bhf[nt][1]);
            }
        }

        if (st + 2 < nst) GEMM_ISSUE(st + 2);
    }
#undef GEMM_ISSUE

#pragma unroll
    for (int mt = 0; mt < 4; mt++) {
        const int row = bm * 128 + wm * 64 + mt * 16 + gid;
#pragma unroll
        for (int nt = 0; nt < 4; nt++) {
            const int col = bn * 128 + wn * 32 + nt * 8 + tig * 2;
            *(float2*)&C[(size_t)row * N + col] =
                make_float2(acc[mt][nt][0], acc[mt][nt][1]);
            *(float2*)&C[(size_t)(row + 8) * N + col] =
                make_float2(acc[mt][nt][2], acc[mt][nt][3]);
        }
    }
}

// ---------------------------------------------------------------------------
// RoPE
// ---------------------------------------------------------------------------
__global__ void rope_kernel(const float* __restrict__ cosb,
                            const float* __restrict__ sinb)
{
    const int total = S_LEN * (NH + NHK) * HD;
    int idx = blockIdx.x * blockDim.x + threadIdx.x;
    if (idx >= total) return;
    int d = idx % HD;
    int h = (idx / HD) % (NH + NHK);
    int s = idx / (HD * (NH + NHK));
    const float* row = g_qkv + (size_t)s * OP;
    float c  = cosb[s * HD + d];
    float sn = sinb[s * HD + d];
    if (h < NH) {
        int base = h * HD;
        float x = row[base + d];
        float r = (d < HD / 2) ? -row[base + d + HD / 2] : row[base + d - HD / 2];
        g_q[(size_t)s * (NH * HD) + h * HD + d] = x * c + r * sn;
    } else {
        int hk = h - NH;
        int base = KOFF + hk * HD;
        float x = row[base + d];
        float r = (d < HD / 2) ? -row[base + d + HD / 2] : row[base + d - HD / 2];
        g_k[(size_t)s * (NHK * HD) + hk * HD + d] = x * c + r * sn;
    }
}

// ---------------------------------------------------------------------------
// Pooling / gates / mask (unchanged)
// ---------------------------------------------------------------------------
__global__ void pool_kernel()
{
    int nb = blockIdx.x, hk = blockIdx.y, d = threadIdx.x;
    float ksum = 0.f, kmax = -3.0e38f, qsum = 0.f;
#pragma unroll 4
    for (int t = 0; t < BLK; t++) {
        const float* row = g_qkv + (size_t)(nb * BLK + t) * OP;
        float kv = row[KOFF + hk * HD + d];
        ksum += kv;
        kmax = fmaxf(kmax, kv);
#pragma unroll
        for (int g = 0; g < GQ; g++) qsum += row[(hk * GQ + g) * HD + d];
    }
    int bh = nb * NHK + hk;
    g_kpool[bh * (2 * HD) + d]      = ksum * (1.f / BLK);
    g_kpool[bh * (2 * HD) + HD + d] = kmax;
    g_qpool[bh * HD + d]            = qsum * (1.f / (BLK * GQ));
}

__global__ void gate_kernel(const float* __restrict__ gate_wq,
                            const float* __restrict__ gate_wk)
{
    int nb = blockIdx.x, hk = blockIdx.y, g = threadIdx.x;
    int bh = nb * NHK + hk;
    float qa = 0.f;
#pragma unroll 8
    for (int d = 0; d < HD; d++)
        qa += g_qpool[bh * HD + d] * gate_wq[d * GH + g];
    float ka = 0.f;
#pragma unroll 8
    for (int e = 0; e < 2 * HD; e++)
        ka += g_kpool[bh * (2 * HD) + e] * gate_wk[e * GH + g];
    g_qgate[bh * GH + g] = qa;
    g_kgate[bh * GH + g] = ka;
}

__global__ void mask_kernel()
{
    int qb = blockIdx.x, hk = blockIdx.y, kb = threadIdx.x;
    float l = -1e30f;
    if (kb <= qb) {
        float dot = 0.f;
#pragma unroll 8
        for (int g = 0; g < GH; g++)
            dot += g_qgate[(size_t)(qb * NHK + hk) * GH + g]
                 * g_kgate[(size_t)(kb * NHK + hk) * GH + g];
        l = dot * rsqrtf((float)GH);
    }
    float mx = l;
#pragma unroll
    for (int o = 16; o > 0; o >>= 1) mx = fmaxf(mx, __shfl_xor_sync(0xffffffffu, mx, o));
    float e = expf(l - mx);
    float sm = e;
#pragma unroll
    for (int o = 16; o > 0; o >>= 1) sm += __shfl_xor_sync(0xffffffffu, sm, o);
    float p = e / sm;
    int keep = ((p >= 0.03f) && (kb <= qb)) || (kb == qb);
    g_maskbuf[(hk * NB + qb) * NB + kb] = keep;
}

// ---------------------------------------------------------------------------
// Block-sparse flash attention v3 (unchanged from R11)
// ---------------------------------------------------------------------------
#define QSTR 104
#define VSTR 72

#define OFF_QH  0
#define OFF_QL  13312
#define OFF_KH  26624
#define OFF_KL  39936
#define OFF_VH  53248
#define OFF_VL  67072
#define OFF_PM  80896
#define OFF_PS  81408
#define OFF_BL  81920
#define OFF_OB  0
#define ATTN_SMEM 82176

#define LDSM4(R0, R1, R2, R3, ADDR)                                            \
    asm volatile("ldmatrix.sync.aligned.m8n8.x4.shared.b16 {%0,%1,%2,%3}, [%4];" \
                 : "=r"(R0), "=r"(R1), "=r"(R2), "=r"(R3) : "r"(ADDR))

#define MMAB(CC, A, B0, B1)                                                    \
    asm volatile(                                                              \
        "mma.sync.aligned.m16n8k16.row.col.f32.bf16.bf16.f32 "                 \
        "{%0,%1,%2,%3}, {%4,%5,%6,%7}, {%8,%9}, {%0,%1,%2,%3};"                \
        : "+f"((CC)[0]), "+f"((CC)[1]), "+f"((CC)[2]), "+f"((CC)[3])           \
        : "r"((A)[0]), "r"((A)[1]), "r"((A)[2]), "r"((A)[3]), "r"(B0), "r"(B1))

#define CPA16(DST, SRC) \
    asm volatile("cp.async.cg.shared.global [%0], [%1], 16;" :: "r"(DST), "l"(SRC))
#define CPA_COMMIT() asm volatile("cp.async.commit_group;" ::: "memory")

__device__ __forceinline__ void kv_issue(uint32_t sb, int kb,
                                         const uint16_t* __restrict__ Khg,
                                         const uint16_t* __restrict__ Klg,
                                         const uint16_t* __restrict__ Vhg,
                                         const uint16_t* __restrict__ Vlg,
                                         int tid)
{
#pragma unroll
    for (int it = 0; it < 3; it++) {
        int idx = tid + it * 256;
        int c = idx / 12, ck = idx % 12;
        const char* sh = (const char*)(Khg + (size_t)(kb * BLK + c) * HD) + ck * 16;
        const char* sl = (const char*)(Klg + (size_t)(kb * BLK + c) * HD) + ck * 16;
        uint32_t d = (uint32_t)(c * QSTR + ck * 8) * 2;
        CPA16(sb + OFF_KH + d, sh);
        CPA16(sb + OFF_KL + d, sl);
    }
#pragma unroll
    for (int it = 0; it < 3; it++) {
        int idx = tid + it * 256;
        int dr = idx / 8, ck = idx % 8;
        const char* sh = (const char*)(Vhg + (size_t)dr * S_LEN + kb * BLK) + ck * 16;
        const char* sl = (const char*)(Vlg + (size_t)dr * S_LEN + kb * BLK) + ck * 16;
        uint32_t d = (uint32_t)(dr * VSTR + ck * 8) * 2;
        CPA16(sb + OFF_VH + d, sh);
        CPA16(sb + OFF_VL + d, sl);
    }
}

__global__ __launch_bounds__(256, 2)
void attn_mma_kernel()
{
    extern __shared__ char smem[];
    const int qb = NB - 1 - blockIdx.x;
    const int h = blockIdx.y, hk = h >> 2;
    const int tid = threadIdx.x;
    int* blist = (int*)(smem + OFF_BL);

    if (tid < 32) {
        int kb = tid;
        const int* mrow = g_maskbuf + (hk * NB + qb) * NB;
        int keep = (kb <= qb) && mrow[kb];
        unsigned bm = __ballot_sync(0xffffffffu, keep);
        if (keep) blist[__popc(bm & ((1u << kb) - 1u))] = kb;
        if (tid == 0) blist[32] = __popc(bm);
    }

    {
        const float scale = rsqrtf((float)HD);
        uint16_t* Qh = (uint16_t*)(smem + OFF_QH);
        uint16_t* Ql = (uint16_t*)(smem + OFF_QL);
        for (int i = tid; i < 64 * 24; i += 256) {
            int r = i / 24, d4 = (i % 24) * 4;
            float4 v = *(const float4*)&g_q[(size_t)(qb * BLK + r) * (NH * HD) + h * HD + d4];
            v.x *= scale; v.y *= scale; v.z *= scale; v.w *= scale;
            ushort4 hi, lo;
            split1(v.x, hi.x, lo.x); split1(v.y, hi.y, lo.y);
            split1(v.z, hi.z, lo.z); split1(v.w, hi.w, lo.w);
            *(ushort4*)&Qh[r * QSTR + d4] = hi;
            *(ushort4*)&Ql[r * QSTR + d4] = lo;
        }
    }
    __syncthreads();

    const int nblk = blist[32];
    const int lane = tid & 31, warp = tid >> 5;
    const int wr = warp & 3;
    const int ch = warp >> 2;
    const int row0 = wr * 16;
    const int g    = lane & 7, quad = lane >> 3;
    const int gid  = lane >> 2, tig = lane & 3;
    const uint32_t sb = (uint32_t)__cvta_generic_to_shared(smem);

    const uint16_t* Khg = g_kbh + (size_t)hk * S_LEN * HD;
    const uint16_t* Klg = g_kbl + (size_t)hk * S_LEN * HD;
    const uint16_t* Vhg = g_vth + (size_t)hk * HD * S_LEN;
    const uint16_t* Vlg = g_vtl + (size_t)hk * HD * S_LEN;

    float* pm = (float*)(smem + OFF_PM);
    float* ps = (float*)(smem + OFF_PS);

    float o[12][4];
#pragma unroll
    for (int dt = 0; dt < 12; dt++)
#pragma unroll
        for (int e = 0; e < 4; e++) o[dt][e] = 0.f;
    float m0 = -1e30f, m1 = -1e30f, l0 = 0.f, l1 = 0.f;

    const int kr = g + ((quad >> 1) << 3);
    const int kd = (quad & 1) << 3;
    const int qar = row0 + g + ((quad & 1) << 3);
    const int qad = (quad & 2) << 2;

    kv_issue(sb, blist[0], Khg, Klg, Vhg, Vlg, tid);
    CPA_COMMIT();

    for (int i = 0; i < nblk; i++) {
        const int kb = blist[i];
        asm volatile("cp.async.wait_group 0;" ::: "memory");
        __syncthreads();

        const uint32_t khb = sb + OFF_KH, klb = sb + OFF_KL;
        const uint32_t vhb = sb + OFF_VH, vlb = sb + OFF_VL;

        float st[4][4];
#pragma unroll
        for (int nt = 0; nt < 4; nt++)
#pragma unroll
            for (int e = 0; e < 4; e++) st[nt][e] = 0.f;

#pragma unroll
        for (int ks = 0; ks < 6; ks++) {
            uint32_t qh[4], ql[4];
            {
                uint32_t qoff = (uint32_t)(qar * QSTR + ks * 16 + qad) * 2u;
                LDSM4(qh[0], qh[1], qh[2], qh[3], sb + OFF_QH + qoff);
                LDSM4(ql[0], ql[1], ql[2], ql[3], sb + OFF_QL + qoff);
            }
#pragma unroll
            for (int j = 0; j < 2; j++) {
                const int ng = ch * 2 + j;
                uint32_t off = (uint32_t)((ng * 16 + kr) * QSTR + ks * 16 + kd) * 2u;
                uint32_t b0, b1, b2, b3, c0, c1, c2, c3;
                LDSM4(b0, b1, b2, b3, khb + off);
                LDSM4(c0, c1, c2, c3, klb + off);
                MMAB(st[2 * j],     qh, b0, b1);
                MMAB(st[2 * j + 1], qh, b2, b3);
                MMAB(st[2 * j],     qh, c0, c1);
                MMAB(st[2 * j + 1], qh, c2, c3);
                MMAB(st[2 * j],     ql, b0, b1);
                MMAB(st[2 * j + 1], ql, b2, b3);
            }
        }

        if (kb == qb) {
            const int rA = row0 + gid, rB = rA + 8;
#pragma unroll
            for (int nt = 0; nt < 4; nt++) {
                int cb = ch * 32 + nt * 8 + tig * 2;
                if (cb     > rA) st[nt][0] = -1e30f;
                if (cb + 1 > rA) st[nt][1] = -1e30f;
                if (cb     > rB) st[nt][2] = -1e30f;
                if (cb + 1 > rB) st[nt][3] = -1e30f;
            }
        }

        float mA = -1e30f, mB = -1e30f;
#pragma unroll
        for (int nt = 0; nt < 4; nt++) {
            mA = fmaxf(mA, fmaxf(st[nt][0], st[nt][1]));
            mB = fmaxf(mB, fmaxf(st[nt][2], st[nt][3]));
        }
        mA = fmaxf(mA, __shfl_xor_sync(0xffffffffu, mA, 1));
        mA = fmaxf(mA, __shfl_xor_sync(0xffffffffu, mA, 2));
        mB = fmaxf(mB, __shfl_xor_sync(0xffffffffu, mB, 1));
        mB = fmaxf(mB, __shfl_xor_sync(0xffffffffu, mB, 2));

        float nmA = fmaxf(m0, mA), nmB = fmaxf(m1, mB);
        float cA = __expf(m0 - nmA), cB = __expf(m1 - nmB);
        float sA = 0.f, sB = 0.f;
#pragma unroll
        for (int nt = 0; nt < 4; nt++) {
            st[nt][0] = __expf(st[nt][0] - nmA); sA += st[nt][0];
            st[nt][1] = __expf(st[nt][1] - nmA); sA += st[nt][1];
            st[nt][2] = __expf(st[nt][2] - nmB); sB += st[nt][2];
            st[nt][3] = __expf(st[nt][3] - nmB); sB += st[nt][3];
        }
        sA += __shfl_xor_sync(0xffffffffu, sA, 1);
        sA += __shfl_xor_sync(0xffffffffu, sA, 2);
        sB += __shfl_xor_sync(0xffffffffu, sB, 1);
        sB += __shfl_xor_sync(0xffffffffu, sB, 2);
        l0 = l0 * cA + sA; m0 = nmA;
        l1 = l1 * cB + sB; m1 = nmB;
#pragma unroll
        for (int dt = 0; dt < 12; dt++) {
            o[dt][0] *= cA; o[dt][1] *= cA;
            o[dt][2] *= cB; o[dt][3] *= cB;
        }

        uint32_t ph[2][4], pl[2][4];
#pragma unroll
        for (int j = 0; j < 2; j++) {
            ph[j][0] = split2(st[2 * j][0],     st[2 * j][1],     pl[j][0]);
            ph[j][1] = split2(st[2 * j][2],     st[2 * j][3],     pl[j][1]);
            ph[j][2] = split2(st[2 * j + 1][0], st[2 * j + 1][1], pl[j][2]);
            ph[j][3] = split2(st[2 * j + 1][2], st[2 * j + 1][3], pl[j][3]);
        }

#pragma unroll
        for (int dt = 0; dt < 12; dt++) {
            uint32_t off = (uint32_t)((dt * 8 + g) * VSTR + ch * 32 + quad * 8) * 2u;
            uint32_t v0, v1, v2, v3, w0, w1, w2, w3;
            LDSM4(v0, v1, v2, v3, vhb + off);
            LDSM4(w0, w1, w2, w3, vlb + off);
            MMAB(o[dt], ph[0], v0, v1);
            MMAB(o[dt], ph[0], w0, w1);
            MMAB(o[dt], pl[0], v0, v1);
            MMAB(o[dt], ph[1], v2, v3);
            MMAB(o[dt], ph[1], w2, w3);
            MMAB(o[dt], pl[1], v2, v3);
        }

        __syncthreads();
        if (i + 1 < nblk) {
            kv_issue(sb, blist[i + 1], Khg, Klg, Vhg, Vlg, tid);
            CPA_COMMIT();
        }
    }

    if (tig == 0) {
        pm[ch * 64 + row0 + gid]     = m0;
        pm[ch * 64 + row0 + gid + 8] = m1;
        ps[ch * 64 + row0 + gid]     = l0;
        ps[ch * 64 + row0 + gid + 8] = l1;
    }
    __syncthreads();
    float mo0 = pm[(ch ^ 1) * 64 + row0 + gid];
    float mo1 = pm[(ch ^ 1) * 64 + row0 + gid + 8];
    float lo0 = ps[(ch ^ 1) * 64 + row0 + gid];
    float lo1 = ps[(ch ^ 1) * 64 + row0 + gid + 8];
    float M0 = fmaxf(m0, mo0), M1 = fmaxf(m1, mo1);
    float sc0 = __expf(m0 - M0), sc1 = __expf(m1 - M1);
    float L0 = l0 * sc0 + lo0 * __expf(mo0 - M0);
    float L1 = l1 * sc1 + lo1 * __expf(mo1 - M1);
#pragma unroll
    for (int dt = 0; dt < 12; dt++) {
        o[dt][0] *= sc0; o[dt][1] *= sc0;
        o[dt][2] *= sc1; o[dt][3] *= sc1;
    }

    float* Obuf = (float*)(smem + OFF_OB);
    __syncthreads();
    if (ch == 1) {
#pragma unroll
        for (int dt = 0; dt < 12; dt++) {
            int col = dt * 8 + tig * 2;
            *(float2*)&Obuf[(row0 + gid) * 100 + col] =
                make_float2(o[dt][0], o[dt][1]);
            *(float2*)&Obuf[(row0 + gid + 8) * 100 + col] =
                make_float2(o[dt][2], o[dt][3]);
        }
    }
    __syncthreads();
    if (ch == 0) {
        const float iA = 1.f / L0, iB = 1.f / L1;
        const int rA = qb * BLK + row0 + gid;
#pragma unroll
        for (int dt = 0; dt < 12; dt++) {
            int col = dt * 8 + tig * 2;
            float2 oa = *(float2*)&Obuf[(row0 + gid) * 100 + col];
            float2 ob = *(float2*)&Obuf[(row0 + gid + 8) * 100 + col];
            float x0 = (o[dt][0] + oa.x) * iA;
            float x1 = (o[dt][1] + oa.y) * iA;
            float x2 = (o[dt][2] + ob.x) * iB;
            float x3 = (o[dt][3] + ob.y) * iB;
            int k2 = (h * HD + col) >> 1;
            uint32_t loA, loB;
            uint32_t hiA = split2(x0, x1, loA);
            uint32_t hiB = split2(x2, x3, loB);
            g_ah[(size_t)rA * K2H + k2]       = hiA;
            g_al[(size_t)rA * K2H + k2]       = loA;
            g_ah[(size_t)(rA + 8) * K2H + k2] = hiB;
            g_al[(size_t)(rA + 8) * K2H + k2] = loB;
        }
    }
}

// ---------------------------------------------------------------------------
// Launch
// ---------------------------------------------------------------------------
extern "C" void kernel_launch(void* const* d_in, const int* in_sizes, int n_in,
                              void* d_out, int out_size)
{
    const float* hs      = (const float*)d_in[0];
    const float* cosb    = (const float*)d_in[1];
    const float* sinb    = (const float*)d_in[2];
    const float* qkv_w   = (const float*)d_in[3];
    const float* o_w     = (const float*)d_in[4];
    const float* gate_wq = (const float*)d_in[5];
    const float* gate_wk = (const float*)d_in[6];
    float* out = (float*)d_out;

    void *p_qkv, *p_ah, *p_al, *p_wqh, *p_wql, *p_woh, *p_wol;
    cudaGetSymbolAddress(&p_qkv, g_qkv);
    cudaGetSymbolAddress(&p_ah, g_ah);
    cudaGetSymbolAddress(&p_al, g_al);
    cudaGetSymbolAddress(&p_wqh, g_wqh);
    cudaGetSymbolAddress(&p_wql, g_wql);
    cudaGetSymbolAddress(&p_woh, g_woh);
    cudaGetSymbolAddress(&p_wol, g_wol);

    // 0. Pack GEMM operands into bf16 hi/lo
    {
        int totW1 = K2H * OP;
        packB_kernel<<<(totW1 + 255) / 256, 256>>>(
            qkv_w, (uint32_t*)p_wqh, (uint32_t*)p_wql, OP, totW1);
        int totW2 = K2H * HIDDEN;
        packB_kernel<<<(totW2 + 255) / 256, 256>>>(
            o_w, (uint32_t*)p_woh, (uint32_t*)p_wol, HIDDEN, totW2);
        int totA = S_LEN * K2H;
        packA_kernel<<<(totA + 255) / 256, 256>>>(
            hs, (uint32_t*)p_ah, (uint32_t*)p_al, totA);
    }

    cudaFuncSetAttribute(bf16x3_gemm,
                         cudaFuncAttributeMaxDynamicSharedMemorySize, GEMM_SMEM);

    // 1. QKV projection (bf16x3 tensor cores, cp.async 3-stage)
    bf16x3_gemm<<<dim3(OP / 128, S_LEN / 128), 256, GEMM_SMEM>>>(
        (const uint32_t*)p_ah, (const uint32_t*)p_al,
        (const uint32_t*)p_wqh, (const uint32_t*)p_wql,
        (float*)p_qkv, S_LEN, OP, K2H);

    // 2. RoPE
    {
        int total = S_LEN * (NH + NHK) * HD;
        rope_kernel<<<(total + 255) / 256, 256>>>(cosb, sinb);
    }

    // 2b. Pre-convert K and V^T to bf16 hi/lo
    {
        int totK = S_LEN * NHK * HD;
        convK_kernel<<<(totK + 255) / 256, 256>>>();
        convV_kernel<<<dim3(S_LEN / 32, HD / 32, NHK), 256>>>();
    }

    // 3. Pool + gate + mask
    pool_kernel<<<dim3(NB, NHK), HD>>>();
    gate_kernel<<<dim3(NB, NHK), GH>>>(gate_wq, gate_wk);
    mask_kernel<<<dim3(NB, NHK), 32>>>();

    // 4. Block-sparse flash attention v3 (split-softmax, occ 2)
    cudaFuncSetAttribute(attn_mma_kernel,
                         cudaFuncAttributeMaxDynamicSharedMemorySize, ATTN_SMEM);
    attn_mma_kernel<<<dim3(NB, NH), 256, ATTN_SMEM>>>();

    // 5. Output projection (bf16x3 tensor cores, cp.async 3-stage)
    bf16x3_gemm<<<dim3(HIDDEN / 128, S_LEN / 128), 256, GEMM_SMEM>>>(
        (const uint32_t*)p_ah, (const uint32_t*)p_al,
        (const uint32_t*)p_woh, (const uint32_t*)p_wol,
        out, S_LEN, HIDDEN, HIDDEN / 2);
}

// round 15
// speedup vs baseline: 1.7531x; 1.0067x over previous
#include <cuda_runtime.h>
#include <cuda_bf16.h>
#include <cstdint>
#include <math.h>

// ---------------------------------------------------------------------------
// Problem constants
// ---------------------------------------------------------------------------
#define S_LEN   2048
#define HIDDEN  3072
#define NH      32
#define NHK     8
#define GQ      4
#define HD      96
#define BLK     64
#define NB      32
#define GH      128
#define OP      4608
#define KOFF    3072
#define VOFF    3840
#define K2H     (HIDDEN / 2)

// ---------------------------------------------------------------------------
// Scratch (device globals; no allocation allowed)
// ---------------------------------------------------------------------------
__device__ float g_qkv [S_LEN * OP];
__device__ float g_q   [S_LEN * NH  * HD];
__device__ float g_qpool[NB * NHK * HD];
__device__ float g_kpool[NB * NHK * 2 * HD];
__device__ float g_qgate[NB * NHK * GH];
__device__ float g_kgate[NB * NHK * GH];
__device__ int   g_maskbuf[NHK * NB * NB];

// bf16 hi/lo packed GEMM operands (k-pairs packed into one uint32)
__device__ uint32_t g_ah [S_LEN * K2H];       // A hi (hs, then attn out)
__device__ uint32_t g_al [S_LEN * K2H];       // A lo
__device__ uint32_t g_wqh[K2H * OP];
__device__ uint32_t g_wql[K2H * OP];
__device__ uint32_t g_woh[K2H * HIDDEN];
__device__ uint32_t g_wol[K2H * HIDDEN];

// Pre-converted attention operands (bf16 hi/lo)
__device__ uint16_t g_kbh[NHK * S_LEN * HD];  // K  [hk][t][d]  (roped)
__device__ uint16_t g_kbl[NHK * S_LEN * HD];
__device__ uint16_t g_vth[NHK * HD * S_LEN];  // V^T [hk][d][t]
__device__ uint16_t g_vtl[NHK * HD * S_LEN];

// ---------------------------------------------------------------------------
// bf16 hi/lo split helpers
// ---------------------------------------------------------------------------
__device__ __forceinline__ void bsplit(float x, uint32_t& h, uint32_t& l)
{
    __nv_bfloat16 hb = __float2bfloat16(x);
    float hf = __bfloat162float(hb);
    __nv_bfloat16 lb = __float2bfloat16(x - hf);
    h = (uint32_t)__bfloat16_as_ushort(hb);
    l = (uint32_t)__bfloat16_as_ushort(lb);
}

__device__ __forceinline__ void split1(float x, uint16_t& h, uint16_t& l)
{
    __nv_bfloat16 hb = __float2bfloat16(x);
    h = __bfloat16_as_ushort(hb);
    l = __bfloat16_as_ushort(__float2bfloat16(x - __bfloat162float(hb)));
}

__device__ __forceinline__ uint32_t split2(float x, float y, uint32_t& lo)
{
    __nv_bfloat16 hx = __float2bfloat16(x), hy = __float2bfloat16(y);
    float rx = x - __bfloat162float(hx), ry = y - __bfloat162float(hy);
    __nv_bfloat16 lx = __float2bfloat16(rx), ly = __float2bfloat16(ry);
    lo = (uint32_t)__bfloat16_as_ushort(lx) | ((uint32_t)__bfloat16_as_ushort(ly) << 16);
    return (uint32_t)__bfloat16_as_ushort(hx) | ((uint32_t)__bfloat16_as_ushort(hy) << 16);
}

// Pack A (row-major M x K): word i = (x[2i], x[2i+1]) along k
__global__ void packA_kernel(const float* __restrict__ in,
                             uint32_t* __restrict__ hi, uint32_t* __restrict__ lo,
                             int total2)
{
    int i = blockIdx.x * blockDim.x + threadIdx.x;
    if (i >= total2) return;
    float2 v = ((const float2*)in)[i];
    uint32_t h0, l0, h1, l1;
    bsplit(v.x, h0, l0);
    bsplit(v.y, h1, l1);
    hi[i] = h0 | (h1 << 16);
    lo[i] = l0 | (l1 << 16);
}

// Pack B (row-major K x N): out[k2][n] = (B[2k2][n], B[2k2+1][n])
__global__ void packB_kernel(const float* __restrict__ in,
                             uint32_t* __restrict__ hi, uint32_t* __restrict__ lo,
                             int N, int total)
{
    int i = blockIdx.x * blockDim.x + threadIdx.x;
    if (i >= total) return;
    int k2 = i / N, n = i - k2 * N;
    float x0 = in[(size_t)(2 * k2) * N + n];
    float x1 = in[(size_t)(2 * k2 + 1) * N + n];
    uint32_t h0, l0, h1, l1;
    bsplit(x0, h0, l0);
    bsplit(x1, h1, l1);
    hi[i] = h0 | (h1 << 16);
    lo[i] = l0 | (l1 << 16);
}

// V pre-convert + transpose: g_qkv [s][VOFF+hk*HD+d] -> g_vth/g_vtl [hk][d][s]
__global__ void convV_kernel()
{
    __shared__ float t[32][33];
    const int s0 = blockIdx.x * 32, d0 = blockIdx.y * 32, hk = blockIdx.z;
    const int tx = threadIdx.x & 31, ty = threadIdx.x >> 5;
#pragma unroll
    for (int i = 0; i < 32; i += 8)
        t[ty + i][tx] = g_qkv[(size_t)(s0 + ty + i) * OP + VOFF + hk * HD + d0 + tx];
    __syncthreads();
#pragma unroll
    for (int i = 0; i < 32; i += 8) {
        float v = t[tx][ty + i];
        uint16_t h, l;
        split1(v, h, l);
        size_t o = ((size_t)hk * HD + d0 + ty + i) * S_LEN + s0 + tx;
        g_vth[o] = h;
        g_vtl[o] = l;
    }
}

// ---------------------------------------------------------------------------
// bf16x3 tensor-core GEMM, cp.async 3-stage + 3-pass MMA ordering.
// Pass structure per stage: hh(16 MMAs) -> hl(16) -> lh(16); dependent MMAs
// on the same accumulator are 16 issues apart (chains fully hidden).
// Per-accumulator accumulation order unchanged (hh, hl, lh).
// ---------------------------------------------------------------------------
#define ASTRW 12
#define BSTRW 136
#define GOFF_AH(s) ((s) * 6144)
#define GOFF_AL(s) (18432 + (s) * 6144)
#define GOFF_BH(s) (36864 + (s) * 4352)
#define GOFF_BL(s) (49920 + (s) * 4352)
#define GEMM_SMEM 62976

#define MMA_BF16(CC, A0, A1, A2, A3, B0, B1)                                   \
    asm volatile(                                                              \
        "mma.sync.aligned.m16n8k16.row.col.f32.bf16.bf16.f32 "                 \
        "{%0,%1,%2,%3}, {%4,%5,%6,%7}, {%8,%9}, {%0,%1,%2,%3};"                \
        : "+f"(CC[0]), "+f"(CC[1]), "+f"(CC[2]), "+f"(CC[3])                   \
        : "r"(A0), "r"(A1), "r"(A2), "r"(A3), "r"(B0), "r"(B1))

#define GCPA16(DST, SRC) \
    asm volatile("cp.async.cg.shared.global [%0], [%1], 16;" :: "r"(DST), "l"(SRC))
#define GCPA_COMMIT() asm volatile("cp.async.commit_group;" ::: "memory")

__global__ __launch_bounds__(256, 2)
void bf16x3_gemm(const uint32_t* __restrict__ Agh, const uint32_t* __restrict__ Agl,
                 const uint32_t* __restrict__ Bgh, const uint32_t* __restrict__ Bgl,
                 float* __restrict__ C, int M, int N, int K2)
{
    extern __shared__ uint32_t gsm[];

    const int tid  = threadIdx.x;
    const int bn   = blockIdx.x, bm = blockIdx.y;
    const int warp = tid >> 5,  lane = tid & 31;
    const int wm   = warp >> 2, wn   = warp & 3;
    const int gid  = lane >> 2, tig  = lane & 3;
    const uint32_t sb = (uint32_t)__cvta_generic_to_shared(gsm);

    const int a_r = tid >> 1, a_h = (tid & 1) * 4;
    const int b_r = tid >> 5, b_c = (tid & 31) * 4;

    const uint32_t* ApH = Agh + (size_t)(bm * 128 + a_r) * K2 + a_h;
    const uint32_t* ApL = Agl + (size_t)(bm * 128 + a_r) * K2 + a_h;
    const uint32_t* BpH = Bgh + (size_t)b_r * N + bn * 128 + b_c;
    const uint32_t* BpL = Bgl + (size_t)b_r * N + bn * 128 + b_c;
    const uint32_t a_dst = (uint32_t)(a_r * ASTRW + a_h) * 4;
    const uint32_t b_dst = (uint32_t)(b_r * BSTRW + b_c) * 4;

    const int nst = K2 >> 3;

#define GEMM_ISSUE(S)                                                          \
    do {                                                                       \
        const int _b = (S) % 3;                                                \
        GCPA16(sb + GOFF_AH(_b) + a_dst, ApH + (S) * 8);                       \
        GCPA16(sb + GOFF_AL(_b) + a_dst, ApL + (S) * 8);                       \
        GCPA16(sb + GOFF_BH(_b) + b_dst, BpH + (size_t)(S) * 8 * N);           \
        GCPA16(sb + GOFF_BL(_b) + b_dst, BpL + (size_t)(S) * 8 * N);           \
        GCPA_COMMIT();                                                         \
    } while (0)

    GEMM_ISSUE(0);
    if (nst > 1) GEMM_ISSUE(1);

    float acc[4][4][4];
#pragma unroll
    for (int mt = 0; mt < 4; mt++)
#pragma unroll
        for (int nt = 0; nt < 4; nt++)
#pragma unroll
            for (int r = 0; r < 4; r++) acc[mt][nt][r] = 0.f;

    for (int st = 0; st < nst; st++) {
        const int b = st % 3;
        if (st + 1 < nst) asm volatile("cp.async.wait_group 1;" ::: "memory");
        else              asm volatile("cp.async.wait_group 0;" ::: "memory");
        __syncthreads();

        const uint32_t* Ah = gsm + GOFF_AH(b) / 4;
        const uint32_t* Al = gsm + GOFF_AL(b) / 4;
        const uint32_t* Bh = gsm + GOFF_BH(b) / 4;
        const uint32_t* Bl = gsm + GOFF_BL(b) / 4;

        uint32_t bhf[4][2], blf[4][2];
#pragma unroll
        for (int nt = 0; nt < 4; nt++) {
            const int n0 = wn * 32 + nt * 8;
            bhf[nt][0] = Bh[tig * BSTRW + n0 + gid];
            bhf[nt][1] = Bh[(tig + 4) * BSTRW + n0 + gid];
            blf[nt][0] = Bl[tig * BSTRW + n0 + gid];
            blf[nt][1] = Bl[(tig + 4) * BSTRW + n0 + gid];
        }

        // Pass 1: hi*hi — 16 independent MMAs
#pragma unroll
        for (int mt = 0; mt < 4; mt++) {
            const int m0 = wm * 64 + mt * 16;
            uint32_t a0 = Ah[(m0 + gid) * ASTRW + tig];
            uint32_t a1 = Ah[(m0 + gid + 8) * ASTRW + tig];
            uint32_t a2 = Ah[(m0 + gid) * ASTRW + tig + 4];
            uint32_t a3 = Ah[(m0 + gid + 8) * ASTRW + tig + 4];
#pragma unroll
            for (int nt = 0; nt < 4; nt++)
                MMA_BF16(acc[mt][nt], a0, a1, a2, a3, bhf[nt][0], bhf[nt][1]);
        }
        // Pass 2: hi*lo — 16 independent MMAs
#pragma unroll
        for (int mt = 0; mt < 4; mt++) {
            const int m0 = wm * 64 + mt * 16;
            uint32_t a0 = Ah[(m0 + gid) * ASTRW + tig];
            uint32_t a1 = Ah[(m0 + gid + 8) * ASTRW + tig];
            uint32_t a2 = Ah[(m0 + gid) * ASTRW + tig + 4];
            uint32_t a3 = Ah[(m0 + gid + 8) * ASTRW + tig + 4];
#pragma unroll
            for (int nt = 0; nt < 4; nt++)
                MMA_BF16(acc[mt][nt], a0, a1, a2, a3, blf[nt][0], blf[nt][1]);
        }
        // Pass 3: lo*hi — 16 independent MMAs
#pragma unroll
        for (int mt = 0; mt < 4; mt++) {
            const int m0 = wm * 64 + mt * 16;
            uint32_t a0 = Al[(m0 + gid) * ASTRW + tig];
            uint32_t a1 = Al[(m0 + gid + 8) * ASTRW + tig];
            uint32_t a2 = Al[(m0 + gid) * ASTRW + tig + 4];
            uint32_t a3 = Al[(m0 + gid + 8) * ASTRW + tig + 4];
#pragma unroll
            for (int nt = 0; nt < 4; nt++)
                MMA_BF16(acc[mt][nt], a0, a1, a2, a3, bhf[nt][0], bhf[nt][1]);
        }

        if (st + 2 < nst) GEMM_ISSUE(st + 2);
    }
#undef GEMM_ISSUE

#pragma unroll
    for (int mt = 0; mt < 4; mt++) {
        const int row = bm * 128 + wm * 64 + mt * 16 + gid;
#pragma unroll
        for (int nt = 0; nt < 4; nt++) {
            const int col = bn * 128 + wn * 32 + nt * 8 + tig * 2;
            *(float2*)&C[(size_t)row * N + col] =
                make_float2(acc[mt][nt][0], acc[mt][nt][1]);
            *(float2*)&C[(size_t)(row + 8) * N + col] =
                make_float2(acc[mt][nt][2], acc[mt][nt][3]);
        }
    }
}

// ---------------------------------------------------------------------------
// RoPE: q -> g_q (fp32); k -> g_kbh/g_kbl (bf16 hi/lo, [hk][s][d]) directly.
// ---------------------------------------------------------------------------
__global__ void rope_kernel(const float* __restrict__ cosb,
                            const float* __restrict__ sinb)
{
    const int total = S_LEN * (NH + NHK) * HD;
    int idx = blockIdx.x * blockDim.x + threadIdx.x;
    if (idx >= total) return;
    int d = idx % HD;
    int h = (idx / HD) % (NH + NHK);
    int s = idx / (HD * (NH + NHK));
    const float* row = g_qkv + (size_t)s * OP;
    float c  = cosb[s * HD + d];
    float sn = sinb[s * HD + d];
    if (h < NH) {
        int base = h * HD;
        float x = row[base + d];
        float r = (d < HD / 2) ? -row[base + d + HD / 2] : row[base + d - HD / 2];
        g_q[(size_t)s * (NH * HD) + h * HD + d] = x * c + r * sn;
    } else {
        int hk = h - NH;
        int base = KOFF + hk * HD;
        float x = row[base + d];
        float r = (d < HD / 2) ? -row[base + d + HD / 2] : row[base + d - HD / 2];
        float kv = x * c + r * sn;
        uint16_t kh, kl;
        split1(kv, kh, kl);
        size_t o = ((size_t)hk * S_LEN + s) * HD + d;
        g_kbh[o] = kh;
        g_kbl[o] = kl;
    }
}

// ---------------------------------------------------------------------------
// Pooling / gates / mask (unchanged)
// ---------------------------------------------------------------------------
__global__ void pool_kernel()
{
    int nb = blockIdx.x, hk = blockIdx.y, d = threadIdx.x;
    float ksum = 0.f, kmax = -3.0e38f, qsum = 0.f;
#pragma unroll 4
    for (int t = 0; t < BLK; t++) {
        const float* row = g_qkv + (size_t)(nb * BLK + t) * OP;
        float kv = row[KOFF + hk * HD + d];
        ksum += kv;
        kmax = fmaxf(kmax, kv);
#pragma unroll
        for (int g = 0; g < GQ; g++) qsum += row[(hk * GQ + g) * HD + d];
    }
    int bh = nb * NHK + hk;
    g_kpool[bh * (2 * HD) + d]      = ksum * (1.f / BLK);
    g_kpool[bh * (2 * HD) + HD + d] = kmax;
    g_qpool[bh * HD + d]            = qsum * (1.f / (BLK * GQ));
}

__global__ void gate_kernel(const float* __restrict__ gate_wq,
                            const float* __restrict__ gate_wk)
{
    int nb = blockIdx.x, hk = blockIdx.y, g = threadIdx.x;
    int bh = nb * NHK + hk;
    float qa = 0.f;
#pragma unroll 8
    for (int d = 0; d < HD; d++)
        qa += g_qpool[bh * HD + d] * gate_wq[d * GH + g];
    float ka = 0.f;
#pragma unroll 8
    for (int e = 0; e < 2 * HD; e++)
        ka += g_kpool[bh * (2 * HD) + e] * gate_wk[e * GH + g];
    g_qgate[bh * GH + g] = qa;
    g_kgate[bh * GH + g] = ka;
}

__global__ void mask_kernel()
{
    int qb = blockIdx.x, hk = blockIdx.y, kb = threadIdx.x;
    float l = -1e30f;
    if (kb <= qb) {
        float dot = 0.f;
#pragma unroll 8
        for (int g = 0; g < GH; g++)
            dot += g_qgate[(size_t)(qb * NHK + hk) * GH + g]
                 * g_kgate[(size_t)(kb * NHK + hk) * GH + g];
        l = dot * rsqrtf((float)GH);
    }
    float mx = l;
#pragma unroll
    for (int o = 16; o > 0; o >>= 1) mx = fmaxf(mx, __shfl_xor_sync(0xffffffffu, mx, o));
    float e = expf(l - mx);
    float sm = e;
#pragma unroll
    for (int o = 16; o > 0; o >>= 1) sm += __shfl_xor_sync(0xffffffffu, sm, o);
    float p = e / sm;
    int keep = ((p >= 0.03f) && (kb <= qb)) || (kb == qb);
    g_maskbuf[(hk * NB + qb) * NB + kb] = keep;
}

// ---------------------------------------------------------------------------
// Block-sparse flash attention v3 (unchanged from R12)
// ---------------------------------------------------------------------------
#define QSTR 104
#define VSTR 72

#define OFF_QH  0
#define OFF_QL  13312
#define OFF_KH  26624
#define OFF_KL  39936
#define OFF_VH  53248
#define OFF_VL  67072
#define OFF_PM  80896
#define OFF_PS  81408
#define OFF_BL  81920
#define OFF_OB  0
#define ATTN_SMEM 82176

#define LDSM4(R0, R1, R2, R3, ADDR)                                            \
    asm volatile("ldmatrix.sync.aligned.m8n8.x4.shared.b16 {%0,%1,%2,%3}, [%4];" \
                 : "=r"(R0), "=r"(R1), "=r"(R2), "=r"(R3) : "r"(ADDR))

#define MMAB(CC, A, B0, B1)                                                    \
    asm volatile(                                                              \
        "mma.sync.aligned.m16n8k16.row.col.f32.bf16.bf16.f32 "                 \
        "{%0,%1,%2,%3}, {%4,%5,%6,%7}, {%8,%9}, {%0,%1,%2,%3};"                \
        : "+f"((CC)[0]), "+f"((CC)[1]), "+f"((CC)[2]), "+f"((CC)[3])           \
        : "r"((A)[0]), "r"((A)[1]), "r"((A)[2]), "r"((A)[3]), "r"(B0), "r"(B1))

#define CPA16(DST, SRC) \
    asm volatile("cp.async.cg.shared.global [%0], [%1], 16;" :: "r"(DST), "l"(SRC))
#define CPA_COMMIT() asm volatile("cp.async.commit_group;" ::: "memory")

__device__ __forceinline__ void kv_issue(uint32_t sb, int kb,
                                         const uint16_t* __restrict__ Khg,
                                         const uint16_t* __restrict__ Klg,
                                         const uint16_t* __restrict__ Vhg,
                                         const uint16_t* __restrict__ Vlg,
                                         int tid)
{
#pragma unroll
    for (int it = 0; it < 3; it++) {
        int idx = tid + it * 256;
        int c = idx / 12, ck = idx % 12;
        const char* sh = (const char*)(Khg + (size_t)(kb * BLK + c) * HD) + ck * 16;
        const char* sl = (const char*)(Klg + (size_t)(kb * BLK + c) * HD) + ck * 16;
        uint32_t d = (uint32_t)(c * QSTR + ck * 8) * 2;
        CPA16(sb + OFF_KH + d, sh);
        CPA16(sb + OFF_KL + d, sl);
    }
#pragma unroll
    for (int it = 0; it < 3; it++) {
        int idx = tid + it * 256;
        int dr = idx / 8, ck = idx % 8;
        const char* sh = (const char*)(Vhg + (size_t)dr * S_LEN + kb * BLK) + ck * 16;
        const char* sl = (const char*)(Vlg + (size_t)dr * S_LEN + kb * BLK) + ck * 16;
        uint32_t d = (uint32_t)(dr * VSTR + ck * 8) * 2;
        CPA16(sb + OFF_VH + d, sh);
        CPA16(sb + OFF_VL + d, sl);
    }
}

__global__ __launch_bounds__(256, 2)
void attn_mma_kernel()
{
    extern __shared__ char smem[];
    const int qb = NB - 1 - blockIdx.x;
    const int h = blockIdx.y, hk = h >> 2;
    const int tid = threadIdx.x;
    int* blist = (int*)(smem + OFF_BL);

    if (tid < 32) {
        int kb = tid;
        const int* mrow = g_maskbuf + (hk * NB + qb) * NB;
        int keep = (kb <= qb) && mrow[kb];
        unsigned bm = __ballot_sync(0xffffffffu, keep);
        if (keep) blist[__popc(bm & ((1u << kb) - 1u))] = kb;
        if (tid == 0) blist[32] = __popc(bm);
    }

    {
        const float scale = rsqrtf((float)HD);
        uint16_t* Qh = (uint16_t*)(smem + OFF_QH);
        uint16_t* Ql = (uint16_t*)(smem + OFF_QL);
        for (int i = tid; i < 64 * 24; i += 256) {
            int r = i / 24, d4 = (i % 24) * 4;
            float4 v = *(const float4*)&g_q[(size_t)(qb * BLK + r) * (NH * HD) + h * HD + d4];
            v.x *= scale; v.y *= scale; v.z *= scale; v.w *= scale;
            ushort4 hi, lo;
            split1(v.x, hi.x, lo.x); split1(v.y, hi.y, lo.y);
            split1(v.z, hi.z, lo.z); split1(v.w, hi.w, lo.w);
            *(ushort4*)&Qh[r * QSTR + d4] = hi;
            *(ushort4*)&Ql[r * QSTR + d4] = lo;
        }
    }
    __syncthreads();

    const int nblk = blist[32];
    const int lane = tid & 31, warp = tid >> 5;
    const int wr = warp & 3;
    const int ch = warp >> 2;
    const int row0 = wr * 16;
    const int g    = lane & 7, quad = lane >> 3;
    const int gid  = lane >> 2, tig = lane & 3;
    const uint32_t sb = (uint32_t)__cvta_generic_to_shared(smem);

    const uint16_t* Khg = g_kbh + (size_t)hk * S_LEN * HD;
    const uint16_t* Klg = g_kbl + (size_t)hk * S_LEN * HD;
    const uint16_t* Vhg = g_vth + (size_t)hk * HD * S_LEN;
    const uint16_t* Vlg = g_vtl + (size_t)hk * HD * S_LEN;

    float* pm = (float*)(smem + OFF_PM);
    float* ps = (float*)(smem + OFF_PS);

    float o[12][4];
#pragma unroll
    for (int dt = 0; dt < 12; dt++)
#pragma unroll
        for (int e = 0; e < 4; e++) o[dt][e] = 0.f;
    float m0 = -1e30f, m1 = -1e30f, l0 = 0.f, l1 = 0.f;

    const int kr = g + ((quad >> 1) << 3);
    const int kd = (quad & 1) << 3;
    const int qar = row0 + g + ((quad & 1) << 3);
    const int qad = (quad & 2) << 2;

    kv_issue(sb, blist[0], Khg, Klg, Vhg, Vlg, tid);
    CPA_COMMIT();

    for (int i = 0; i < nblk; i++) {
        const int kb = blist[i];
        asm volatile("cp.async.wait_group 0;" ::: "memory");
        __syncthreads();

        const uint32_t khb = sb + OFF_KH, klb = sb + OFF_KL;
        const uint32_t vhb = sb + OFF_VH, vlb = sb + OFF_VL;

        float st[4][4];
#pragma unroll
        for (int nt = 0; nt < 4; nt++)
#pragma unroll
            for (int e = 0; e < 4; e++) st[nt][e] = 0.f;

#pragma unroll
        for (int ks = 0; ks < 6; ks++) {
            uint32_t qh[4], ql[4];
            {
                uint32_t qoff = (uint32_t)(qar * QSTR + ks * 16 + qad) * 2u;
                LDSM4(qh[0], qh[1], qh[2], qh[3], sb + OFF_QH + qoff);
                LDSM4(ql[0], ql[1], ql[2], ql[3], sb + OFF_QL + qoff);
            }
#pragma unroll
            for (int j = 0; j < 2; j++) {
                const int ng = ch * 2 + j;
                uint32_t off = (uint32_t)((ng * 16 + kr) * QSTR + ks * 16 + kd) * 2u;
                uint32_t b0, b1, b2, b3, c0, c1, c2, c3;
                LDSM4(b0, b1, b2, b3, khb + off);
                LDSM4(c0, c1, c2, c3, klb + off);
                MMAB(st[2 * j],     qh, b0, b1);
                MMAB(st[2 * j + 1], qh, b2, b3);
                MMAB(st[2 * j],     qh, c0, c1);
                MMAB(st[2 * j + 1], qh, c2, c3);
                MMAB(st[2 * j],     ql, b0, b1);
                MMAB(st[2 * j + 1], ql, b2, b3);
            }
        }

        if (kb == qb) {
            const int rA = row0 + gid, rB = rA + 8;
#pragma unroll
            for (int nt = 0; nt < 4; nt++) {
                int cb = ch * 32 + nt * 8 + tig * 2;
                if (cb     > rA) st[nt][0] = -1e30f;
                if (cb + 1 > rA) st[nt][1] = -1e30f;
                if (cb     > rB) st[nt][2] = -1e30f;
                if (cb + 1 > rB) st[nt][3] = -1e30f;
            }
        }

        float mA = -1e30f, mB = -1e30f;
#pragma unroll
        for (int nt = 0; nt < 4; nt++) {
            mA = fmaxf(mA, fmaxf(st[nt][0], st[nt][1]));
            mB = fmaxf(mB, fmaxf(st[nt][2], st[nt][3]));
        }
        mA = fmaxf(mA, __shfl_xor_sync(0xffffffffu, mA, 1));
        mA = fmaxf(mA, __shfl_xor_sync(0xffffffffu, mA, 2));
        mB = fmaxf(mB, __shfl_xor_sync(0xffffffffu, mB, 1));
        mB = fmaxf(mB, __shfl_xor_sync(0xffffffffu, mB, 2));

        float nmA = fmaxf(m0, mA), nmB = fmaxf(m1, mB);
        float cA = __expf(m0 - nmA), cB = __expf(m1 - nmB);
        float sA = 0.f, sB = 0.f;
#pragma unroll
        for (int nt = 0; nt < 4; nt++) {
            st[nt][0] = __expf(st[nt][0] - nmA); sA += st[nt][0];
            st[nt][1] = __expf(st[nt][1] - nmA); sA += st[nt][1];
            st[nt][2] = __expf(st[nt][2] - nmB); sB += st[nt][2];
            st[nt][3] = __expf(st[nt][3] - nmB); sB += st[nt][3];
        }
        sA += __shfl_xor_sync(0xffffffffu, sA, 1);
        sA += __shfl_xor_sync(0xffffffffu, sA, 2);
        sB += __shfl_xor_sync(0xffffffffu, sB, 1);
        sB += __shfl_xor_sync(0xffffffffu, sB, 2);
        l0 = l0 * cA + sA; m0 = nmA;
        l1 = l1 * cB + sB; m1 = nmB;
#pragma unroll
        for (int dt = 0; dt < 12; dt++) {
            o[dt][0] *= cA; o[dt][1] *= cA;
            o[dt][2] *= cB; o[dt][3] *= cB;
        }

        uint32_t ph[2][4], pl[2][4];
#pragma unroll
        for (int j = 0; j < 2; j++) {
            ph[j][0] = split2(st[2 * j][0],     st[2 * j][1],     pl[j][0]);
            ph[j][1] = split2(st[2 * j][2],     st[2 * j][3],     pl[j][1]);
            ph[j][2] = split2(st[2 * j + 1][0], st[2 * j + 1][1], pl[j][2]);
            ph[j][3] = split2(st[2 * j + 1][2], st[2 * j + 1][3], pl[j][3]);
        }

#pragma unroll
        for (int dt = 0; dt < 12; dt++) {
            uint32_t off = (uint32_t)((dt * 8 + g) * VSTR + ch * 32 + quad * 8) * 2u;
            uint32_t v0, v1, v2, v3, w0, w1, w2, w3;
            LDSM4(v0, v1, v2, v3, vhb + off);
            LDSM4(w0, w1, w2, w3, vlb + off);
            MMAB(o[dt], ph[0], v0, v1);
            MMAB(o[dt], ph[0], w0, w1);
            MMAB(o[dt], pl[0], v0, v1);
            MMAB(o[dt], ph[1], v2, v3);
            MMAB(o[dt], ph[1], w2, w3);
            MMAB(o[dt], pl[1], v2, v3);
        }

        __syncthreads();
        if (i + 1 < nblk) {
            kv_issue(sb, blist[i + 1], Khg, Klg, Vhg, Vlg, tid);
            CPA_COMMIT();
        }
    }

    if (tig == 0) {
        pm[ch * 64 + row0 + gid]     = m0;
        pm[ch * 64 + row0 + gid + 8] = m1;
        ps[ch * 64 + row0 + gid]     = l0;
        ps[ch * 64 + row0 + gid + 8] = l1;
    }
    __syncthreads();
    float mo0 = pm[(ch ^ 1) * 64 + row0 + gid];
    float mo1 = pm[(ch ^ 1) * 64 + row0 + gid + 8];
    float lo0 = ps[(ch ^ 1) * 64 + row0 + gid];
    float lo1 = ps[(ch ^ 1) * 64 + row0 + gid + 8];
    float M0 = fmaxf(m0, mo0), M1 = fmaxf(m1, mo1);
    float sc0 = __expf(m0 - M0), sc1 = __expf(m1 - M1);
    float L0 = l0 * sc0 + lo0 * __expf(mo0 - M0);
    float L1 = l1 * sc1 + lo1 * __expf(mo1 - M1);
#pragma unroll
    for (int dt = 0; dt < 12; dt++) {
        o[dt][0] *= sc0; o[dt][1] *= sc0;
        o[dt][2] *= sc1; o[dt][3] *= sc1;
    }

    float* Obuf = (float*)(smem + OFF_OB);
    __syncthreads();
    if (ch == 1) {
#pragma unroll
        for (int dt = 0; dt < 12; dt++) {
            int col = dt * 8 + tig * 2;
            *(float2*)&Obuf[(row0 + gid) * 100 + col] =
                make_float2(o[dt][0], o[dt][1]);
            *(float2*)&Obuf[(row0 + gid + 8) * 100 + col] =
                make_float2(o[dt][2], o[dt][3]);
        }
    }
    __syncthreads();
    if (ch == 0) {
        const float iA = 1.f / L0, iB = 1.f / L1;
        const int rA = qb * BLK + row0 + gid;
#pragma unroll
        for (int dt = 0; dt < 12; dt++) {
            int col = dt * 8 + tig * 2;
            float2 oa = *(float2*)&Obuf[(row0 + gid) * 100 + col];
            float2 ob = *(float2*)&Obuf[(row0 + gid + 8) * 100 + col];
            float x0 = (o[dt][0] + oa.x) * iA;
            float x1 = (o[dt][1] + oa.y) * iA;
            float x2 = (o[dt][2] + ob.x) * iB;
            float x3 = (o[dt][3] + ob.y) * iB;
            int k2 = (h * HD + col) >> 1;
            uint32_t loA, loB;
            uint32_t hiA = split2(x0, x1, loA);
            uint32_t hiB = split2(x2, x3, loB);
            g_ah[(size_t)rA * K2H + k2]       = hiA;
            g_al[(size_t)rA * K2H + k2]       = loA;
            g_ah[(size_t)(rA + 8) * K2H + k2] = hiB;
            g_al[(size_t)(rA + 8) * K2H + k2] = loB;
        }
    }
}

// ---------------------------------------------------------------------------
// Launch
// ---------------------------------------------------------------------------
extern "C" void kernel_launch(void* const* d_in, const int* in_sizes, int n_in,
                              void* d_out, int out_size)
{
    const float* hs      = (const float*)d_in[0];
    const float* cosb    = (const float*)d_in[1];
    const float* sinb    = (const float*)d_in[2];
    const float* qkv_w   = (const float*)d_in[3];
    const float* o_w     = (const float*)d_in[4];
    const float* gate_wq = (const float*)d_in[5];
    const float* gate_wk = (const float*)d_in[6];
    float* out = (float*)d_out;

    void *p_qkv, *p_ah, *p_al, *p_wqh, *p_wql, *p_woh, *p_wol;
    cudaGetSymbolAddress(&p_qkv, g_qkv);
    cudaGetSymbolAddress(&p_ah, g_ah);
    cudaGetSymbolAddress(&p_al, g_al);
    cudaGetSymbolAddress(&p_wqh, g_wqh);
    cudaGetSymbolAddress(&p_wql, g_wql);
    cudaGetSymbolAddress(&p_woh, g_woh);
    cudaGetSymbolAddress(&p_wol, g_wol);

    // 0. Pack GEMM operands into bf16 hi/lo
    {
        int totW1 = K2H * OP;
        packB_kernel<<<(totW1 + 255) / 256, 256>>>(
            qkv_w, (uint32_t*)p_wqh, (uint32_t*)p_wql, OP, totW1);
        int totW2 = K2H * HIDDEN;
        packB_kernel<<<(totW2 + 255) / 256, 256>>>(
            o_w, (uint32_t*)p_woh, (uint32_t*)p_wol, HIDDEN, totW2);
        int totA = S_LEN * K2H;
        packA_kernel<<<(totA + 255) / 256, 256>>>(
            hs, (uint32_t*)p_ah, (uint32_t*)p_al, totA);
    }

    cudaFuncSetAttribute(bf16x3_gemm,
                         cudaFuncAttributeMaxDynamicSharedMemorySize, GEMM_SMEM);

    // 1. QKV projection (bf16x3 tensor cores, cp.async 3-stage, 3-pass MMA)
    bf16x3_gemm<<<dim3(OP / 128, S_LEN / 128), 256, GEMM_SMEM>>>(
        (const uint32_t*)p_ah, (const uint32_t*)p_al,
        (const uint32_t*)p_wqh, (const uint32_t*)p_wql,
        (float*)p_qkv, S_LEN, OP, K2H);

    // 2. RoPE (Q fp32; K directly to bf16 hi/lo)
    {
        int total = S_LEN * (NH + NHK) * HD;
        rope_kernel<<<(total + 255) / 256, 256>>>(cosb, sinb);
    }

    // 2b. Pre-convert V^T to bf16 hi/lo
    convV_kernel<<<dim3(S_LEN / 32, HD / 32, NHK), 256>>>();

    // 3. Pool + gate + mask
    pool_kernel<<<dim3(NB, NHK), HD>>>();
    gate_kernel<<<dim3(NB, NHK), GH>>>(gate_wq, gate_wk);
    mask_kernel<<<dim3(NB, NHK), 32>>>();

    // 4. Block-sparse flash attention v3 (split-softmax, occ 2)
    cudaFuncSetAttribute(attn_mma_kernel,
                         cudaFuncAttributeMaxDynamicSharedMemorySize, ATTN_SMEM);
    attn_mma_kernel<<<dim3(NB, NH), 256, ATTN_SMEM>>>();

    // 5. Output projection (bf16x3 tensor cores, cp.async 3-stage, 3-pass MMA)
    bf16x3_gemm<<<dim3(HIDDEN / 128, S_LEN / 128), 256, GEMM_SMEM>>>(
        (const uint32_t*)p_ah, (const uint32_t*)p_al,
        (const uint32_t*)p_woh, (const uint32_t*)p_wol,
        out, S_LEN, HIDDEN, HIDDEN / 2);
}

// round 16
// speedup vs baseline: 1.7709x; 1.0101x over previous
#include <cuda_runtime.h>
#include <cuda_bf16.h>
#include <cstdint>
#include <math.h>

// ---------------------------------------------------------------------------
// Problem constants
// ---------------------------------------------------------------------------
#define S_LEN   2048
#define HIDDEN  3072
#define NH      32
#define NHK     8
#define GQ      4
#define HD      96
#define BLK     64
#define NB      32
#define GH      128
#define OP      4608
#define KOFF    3072
#define VOFF    3840
#define K2H     (HIDDEN / 2)

// ---------------------------------------------------------------------------
// Scratch (device globals; no allocation allowed)
// ---------------------------------------------------------------------------
__device__ float g_qkv [S_LEN * OP];
__device__ float g_q   [S_LEN * NH  * HD];
__device__ float g_qgate[NB * NHK * GH];
__device__ float g_kgate[NB * NHK * GH];
__device__ int   g_maskbuf[NHK * NB * NB];

// bf16 hi/lo packed GEMM operands (k-pairs packed into one uint32)
__device__ uint32_t g_ah [S_LEN * K2H];       // A hi (hs, then attn out)
__device__ uint32_t g_al [S_LEN * K2H];       // A lo
__device__ uint32_t g_wqh[K2H * OP];
__device__ uint32_t g_wql[K2H * OP];
__device__ uint32_t g_woh[K2H * HIDDEN];
__device__ uint32_t g_wol[K2H * HIDDEN];

// Pre-converted attention operands (bf16 hi/lo)
__device__ uint16_t g_kbh[NHK * S_LEN * HD];  // K  [hk][t][d]  (roped)
__device__ uint16_t g_kbl[NHK * S_LEN * HD];
__device__ uint16_t g_vth[NHK * HD * S_LEN];  // V^T [hk][d][t]
__device__ uint16_t g_vtl[NHK * HD * S_LEN];

// ---------------------------------------------------------------------------
// bf16 hi/lo split helpers
// ---------------------------------------------------------------------------
__device__ __forceinline__ void bsplit(float x, uint32_t& h, uint32_t& l)
{
    __nv_bfloat16 hb = __float2bfloat16(x);
    float hf = __bfloat162float(hb);
    __nv_bfloat16 lb = __float2bfloat16(x - hf);
    h = (uint32_t)__bfloat16_as_ushort(hb);
    l = (uint32_t)__bfloat16_as_ushort(lb);
}

__device__ __forceinline__ void split1(float x, uint16_t& h, uint16_t& l)
{
    __nv_bfloat16 hb = __float2bfloat16(x);
    h = __bfloat16_as_ushort(hb);
    l = __bfloat16_as_ushort(__float2bfloat16(x - __bfloat162float(hb)));
}

__device__ __forceinline__ uint32_t split2(float x, float y, uint32_t& lo)
{
    __nv_bfloat16 hx = __float2bfloat16(x), hy = __float2bfloat16(y);
    float rx = x - __bfloat162float(hx), ry = y - __bfloat162float(hy);
    __nv_bfloat16 lx = __float2bfloat16(rx), ly = __float2bfloat16(ry);
    lo = (uint32_t)__bfloat16_as_ushort(lx) | ((uint32_t)__bfloat16_as_ushort(ly) << 16);
    return (uint32_t)__bfloat16_as_ushort(hx) | ((uint32_t)__bfloat16_as_ushort(hy) << 16);
}

// Pack A (row-major M x K): word i = (x[2i], x[2i+1]) along k
__global__ void packA_kernel(const float* __restrict__ in,
                             uint32_t* __restrict__ hi, uint32_t* __restrict__ lo,
                             int total2)
{
    int i = blockIdx.x * blockDim.x + threadIdx.x;
    if (i >= total2) return;
    float2 v = ((const float2*)in)[i];
    uint32_t h0, l0, h1, l1;
    bsplit(v.x, h0, l0);
    bsplit(v.y, h1, l1);
    hi[i] = h0 | (h1 << 16);
    lo[i] = l0 | (l1 << 16);
}

// Pack B (row-major K x N): out[k2][n] = (B[2k2][n], B[2k2+1][n])
__global__ void packB_kernel(const float* __restrict__ in,
                             uint32_t* __restrict__ hi, uint32_t* __restrict__ lo,
                             int N, int total)
{
    int i = blockIdx.x * blockDim.x + threadIdx.x;
    if (i >= total) return;
    int k2 = i / N, n = i - k2 * N;
    float x0 = in[(size_t)(2 * k2) * N + n];
    float x1 = in[(size_t)(2 * k2 + 1) * N + n];
    uint32_t h0, l0, h1, l1;
    bsplit(x0, h0, l0);
    bsplit(x1, h1, l1);
    hi[i] = h0 | (h1 << 16);
    lo[i] = l0 | (l1 << 16);
}

// V pre-convert + transpose: g_qkv [s][VOFF+hk*HD+d] -> g_vth/g_vtl [hk][d][s]
__global__ void convV_kernel()
{
    __shared__ float t[32][33];
    const int s0 = blockIdx.x * 32, d0 = blockIdx.y * 32, hk = blockIdx.z;
    const int tx = threadIdx.x & 31, ty = threadIdx.x >> 5;
#pragma unroll
    for (int i = 0; i < 32; i += 8)
        t[ty + i][tx] = g_qkv[(size_t)(s0 + ty + i) * OP + VOFF + hk * HD + d0 + tx];
    __syncthreads();
#pragma unroll
    for (int i = 0; i < 32; i += 8) {
        float v = t[tx][ty + i];
        uint16_t h, l;
        split1(v, h, l);
        size_t o = ((size_t)hk * HD + d0 + ty + i) * S_LEN + s0 + tx;
        g_vth[o] = h;
        g_vtl[o] = l;
    }
}

// ---------------------------------------------------------------------------
// bf16x3 tensor-core GEMM, BK=32 / 2-stage cp.async / issue-before-compute.
// Stage = 16 packed words (k32) = two k16 substeps; per substep 3 passes
// (hh -> hl -> lh, 16 independent MMAs each). Per-accumulator accumulation
// order identical to the BK=16 version (bit-exact results).
// A smem rows padded to 20 words (conflict-free: gid*20 mod 32 all distinct).
// ---------------------------------------------------------------------------
#define ASTRW 20
#define BSTRW 136
#define GOFF_AH(s) ((s) * 10240)
#define GOFF_AL(s) (20480 + (s) * 10240)
#define GOFF_BH(s) (40960 + (s) * 8704)
#define GOFF_BL(s) (58368 + (s) * 8704)
#define GEMM_SMEM 75776

#define MMA_BF16(CC, A0, A1, A2, A3, B0, B1)                                   \
    asm volatile(                                                              \
        "mma.sync.aligned.m16n8k16.row.col.f32.bf16.bf16.f32 "                 \
        "{%0,%1,%2,%3}, {%4,%5,%6,%7}, {%8,%9}, {%0,%1,%2,%3};"                \
        : "+f"(CC[0]), "+f"(CC[1]), "+f"(CC[2]), "+f"(CC[3])                   \
        : "r"(A0), "r"(A1), "r"(A2), "r"(A3), "r"(B0), "r"(B1))

#define GCPA16(DST, SRC) \
    asm volatile("cp.async.cg.shared.global [%0], [%1], 16;" :: "r"(DST), "l"(SRC))
#define GCPA_COMMIT() asm volatile("cp.async.commit_group;" ::: "memory")

__global__ __launch_bounds__(256, 2)
void bf16x3_gemm(const uint32_t* __restrict__ Agh, const uint32_t* __restrict__ Agl,
                 const uint32_t* __restrict__ Bgh, const uint32_t* __restrict__ Bgl,
                 float* __restrict__ C, int M, int N, int K2)
{
    extern __shared__ uint32_t gsm[];

    const int tid  = threadIdx.x;
    const int bn   = blockIdx.x, bm = blockIdx.y;
    const int warp = tid >> 5,  lane = tid & 31;
    const int wm   = warp >> 2, wn   = warp & 3;
    const int gid  = lane >> 2, tig  = lane & 3;
    const uint32_t sb = (uint32_t)__cvta_generic_to_shared(gsm);

    // cp.async mapping (per stage, per array): A 512 chunks (2/thread),
    // B 512 chunks (2/thread).
    const int ar0 = tid >> 2, ac = (tid & 3) * 4;       // A rows ar0, ar0+64
    const int br0 = tid >> 5, bc = (tid & 31) * 4;      // B rows br0, br0+8

    const uint32_t* ApH = Agh + (size_t)(bm * 128 + ar0) * K2 + ac;
    const uint32_t* ApL = Agl + (size_t)(bm * 128 + ar0) * K2 + ac;
    const uint32_t* BpH = Bgh + (size_t)br0 * N + bn * 128 + bc;
    const uint32_t* BpL = Bgl + (size_t)br0 * N + bn * 128 + bc;
    const uint32_t aD0 = (uint32_t)(ar0 * ASTRW + ac) * 4;
    const uint32_t aD1 = aD0 + (uint32_t)(64 * ASTRW) * 4;
    const uint32_t bD0 = (uint32_t)(br0 * BSTRW + bc) * 4;
    const uint32_t bD1 = bD0 + (uint32_t)(8 * BSTRW) * 4;
    const size_t aRow2 = (size_t)64 * K2;
    const size_t bRow2 = (size_t)8 * N;

    const int nst = K2 >> 4;   // k32 stages

#define GEMM_ISSUE(S)                                                          \
    do {                                                                       \
        const int _b = (S) & 1;                                                \
        const int _ko = (S) * 16;                                              \
        GCPA16(sb + GOFF_AH(_b) + aD0, ApH + _ko);                             \
        GCPA16(sb + GOFF_AH(_b) + aD1, ApH + aRow2 + _ko);                     \
        GCPA16(sb + GOFF_AL(_b) + aD0, ApL + _ko);                             \
        GCPA16(sb + GOFF_AL(_b) + aD1, ApL + aRow2 + _ko);                     \
        GCPA16(sb + GOFF_BH(_b) + bD0, BpH + (size_t)_ko * N);                 \
        GCPA16(sb + GOFF_BH(_b) + bD1, BpH + (size_t)_ko * N + bRow2);         \
        GCPA16(sb + GOFF_BL(_b) + bD0, BpL + (size_t)_ko * N);                 \
        GCPA16(sb + GOFF_BL(_b) + bD1, BpL + (size_t)_ko * N + bRow2);         \
        GCPA_COMMIT();                                                         \
    } while (0)

    GEMM_ISSUE(0);

    float acc[4][4][4];
#pragma unroll
    for (int mt = 0; mt < 4; mt++)
#pragma unroll
        for (int nt = 0; nt < 4; nt++)
#pragma unroll
            for (int r = 0; r < 4; r++) acc[mt][nt][r] = 0.f;

    for (int st = 0; st < nst; st++) {
        asm volatile("cp.async.wait_group 0;" ::: "memory");
        __syncthreads();
        if (st + 1 < nst) GEMM_ISSUE(st + 1);   // overlaps this stage's compute

        const int b = st & 1;
        const uint32_t* Ah = gsm + GOFF_AH(b) / 4;
        const uint32_t* Al = gsm + GOFF_AL(b) / 4;
        const uint32_t* Bh = gsm + GOFF_BH(b) / 4;
        const uint32_t* Bl = gsm + GOFF_BL(b) / 4;

#pragma unroll
        for (int ks2 = 0; ks2 < 2; ks2++) {
            const int ko = ks2 * 8;

            uint32_t bhf[4][2], blf[4][2];
#pragma unroll
            for (int nt = 0; nt < 4; nt++) {
                const int n0 = wn * 32 + nt * 8;
                bhf[nt][0] = Bh[(ko + tig) * BSTRW + n0 + gid];
                bhf[nt][1] = Bh[(ko + tig + 4) * BSTRW + n0 + gid];
                blf[nt][0] = Bl[(ko + tig) * BSTRW + n0 + gid];
                blf[nt][1] = Bl[(ko + tig + 4) * BSTRW + n0 + gid];
            }

            // Pass 1: hi*hi
#pragma unroll
            for (int mt = 0; mt < 4; mt++) {
                const int m0 = wm * 64 + mt * 16;
                uint32_t a0 = Ah[(m0 + gid) * ASTRW + ko + tig];
                uint32_t a1 = Ah[(m0 + gid + 8) * ASTRW + ko + tig];
                uint32_t a2 = Ah[(m0 + gid) * ASTRW + ko + tig + 4];
                uint32_t a3 = Ah[(m0 + gid + 8) * ASTRW + ko + tig + 4];
#pragma unroll
                for (int nt = 0; nt < 4; nt++)
                    MMA_BF16(acc[mt][nt], a0, a1, a2, a3, bhf[nt][0], bhf[nt][1]);
            }
            // Pass 2: hi*lo
#pragma unroll
            for (int mt = 0; mt < 4; mt++) {
                const int m0 = wm * 64 + mt * 16;
                uint32_t a0 = Ah[(m0 + gid) * ASTRW + ko + tig];
                uint32_t a1 = Ah[(m0 + gid + 8) * ASTRW + ko + tig];
                uint32_t a2 = Ah[(m0 + gid) * ASTRW + ko + tig + 4];
                uint32_t a3 = Ah[(m0 + gid + 8) * ASTRW + ko + tig + 4];
#pragma unroll
                for (int nt = 0; nt < 4; nt++)
                    MMA_BF16(acc[mt][nt], a0, a1, a2, a3, blf[nt][0], blf[nt][1]);
            }
            // Pass 3: lo*hi
#pragma unroll
            for (int mt = 0; mt < 4; mt++) {
                const int m0 = wm * 64 + mt * 16;
                uint32_t a0 = Al[(m0 + gid) * ASTRW + ko + tig];
                uint32_t a1 = Al[(m0 + gid + 8) * ASTRW + ko + tig];
                uint32_t a2 = Al[(m0 + gid) * ASTRW + ko + tig + 4];
                uint32_t a3 = Al[(m0 + gid + 8) * ASTRW + ko + tig + 4];
#pragma unroll
                for (int nt = 0; nt < 4; nt++)
                    MMA_BF16(acc[mt][nt], a0, a1, a2, a3, bhf[nt][0], bhf[nt][1]);
            }
        }
    }
#undef GEMM_ISSUE

#pragma unroll
    for (int mt = 0; mt < 4; mt++) {
        const int row = bm * 128 + wm * 64 + mt * 16 + gid;
#pragma unroll
        for (int nt = 0; nt < 4; nt++) {
            const int col = bn * 128 + wn * 32 + nt * 8 + tig * 2;
            *(float2*)&C[(size_t)row * N + col] =
                make_float2(acc[mt][nt][0], acc[mt][nt][1]);
            *(float2*)&C[(size_t)(row + 8) * N + col] =
                make_float2(acc[mt][nt][2], acc[mt][nt][3]);
        }
    }
}

// ---------------------------------------------------------------------------
// RoPE: q -> g_q (fp32); k -> g_kbh/g_kbl (bf16 hi/lo, [hk][s][d]) directly.
// ---------------------------------------------------------------------------
__global__ void rope_kernel(const float* __restrict__ cosb,
                            const float* __restrict__ sinb)
{
    const int total = S_LEN * (NH + NHK) * HD;
    int idx = blockIdx.x * blockDim.x + threadIdx.x;
    if (idx >= total) return;
    int d = idx % HD;
    int h = (idx / HD) % (NH + NHK);
    int s = idx / (HD * (NH + NHK));
    const float* row = g_qkv + (size_t)s * OP;
    float c  = cosb[s * HD + d];
    float sn = sinb[s * HD + d];
    if (h < NH) {
        int base = h * HD;
        float x = row[base + d];
        float r = (d < HD / 2) ? -row[base + d + HD / 2] : row[base + d - HD / 2];
        g_q[(size_t)s * (NH * HD) + h * HD + d] = x * c + r * sn;
    } else {
        int hk = h - NH;
        int base = KOFF + hk * HD;
        float x = row[base + d];
        float r = (d < HD / 2) ? -row[base + d + HD / 2] : row[base + d - HD / 2];
        float kv = x * c + r * sn;
        uint16_t kh, kl;
        split1(kv, kh, kl);
        size_t o = ((size_t)hk * S_LEN + s) * HD + d;
        g_kbh[o] = kh;
        g_kbl[o] = kl;
    }
}

// ---------------------------------------------------------------------------
// Fused pool + gate: grid (NB, NHK), 128 threads.
// Threads 0-95 pool (mean/max K, mean Q) into smem; all 128 do the gate GEMV.
// ---------------------------------------------------------------------------
__global__ void poolgate_kernel(const float* __restrict__ gate_wq,
                                const float* __restrict__ gate_wk)
{
    __shared__ float qp[HD], kp[2 * HD];
    const int nb = blockIdx.x, hk = blockIdx.y, tid = threadIdx.x;

    if (tid < HD) {
        float ksum = 0.f, kmax = -3.0e38f, qsum = 0.f;
#pragma unroll 4
        for (int t = 0; t < BLK; t++) {
            const float* row = g_qkv + (size_t)(nb * BLK + t) * OP;
            float kv = row[KOFF + hk * HD + tid];
            ksum += kv;
            kmax = fmaxf(kmax, kv);
#pragma unroll
            for (int g = 0; g < GQ; g++) qsum += row[(hk * GQ + g) * HD + tid];
        }
        kp[tid]      = ksum * (1.f / BLK);
        kp[HD + tid] = kmax;
        qp[tid]      = qsum * (1.f / (BLK * GQ));
    }
    __syncthreads();

    const int g = tid;
    float qa = 0.f;
#pragma unroll 8
    for (int d = 0; d < HD; d++)
        qa += qp[d] * gate_wq[d * GH + g];
    float ka = 0.f;
#pragma unroll 8
    for (int e = 0; e < 2 * HD; e++)
        ka += kp[e] * gate_wk[e * GH + g];
    int bh = nb * NHK + hk;
    g_qgate[bh * GH + g] = qa;
    g_kgate[bh * GH + g] = ka;
}

__global__ void mask_kernel()
{
    int qb = blockIdx.x, hk = blockIdx.y, kb = threadIdx.x;
    float l = -1e30f;
    if (kb <= qb) {
        float dot = 0.f;
#pragma unroll 8
        for (int g = 0; g < GH; g++)
            dot += g_qgate[(size_t)(qb * NHK + hk) * GH + g]
                 * g_kgate[(size_t)(kb * NHK + hk) * GH + g];
        l = dot * rsqrtf((float)GH);
    }
    float mx = l;
#pragma unroll
    for (int o = 16; o > 0; o >>= 1) mx = fmaxf(mx, __shfl_xor_sync(0xffffffffu, mx, o));
    float e = expf(l - mx);
    float sm = e;
#pragma unroll
    for (int o = 16; o > 0; o >>= 1) sm += __shfl_xor_sync(0xffffffffu, sm, o);
    float p = e / sm;
    int keep = ((p >= 0.03f) && (kb <= qb)) || (kb == qb);
    g_maskbuf[(hk * NB + qb) * NB + kb] = keep;
}

// ---------------------------------------------------------------------------
// Block-sparse flash attention v3 (unchanged from R15)
// ---------------------------------------------------------------------------
#define QSTR 104
#define VSTR 72

#define OFF_QH  0
#define OFF_QL  13312
#define OFF_KH  26624
#define OFF_KL  39936
#define OFF_VH  53248
#define OFF_VL  67072
#define OFF_PM  80896
#define OFF_PS  81408
#define OFF_BL  81920
#define OFF_OB  0
#define ATTN_SMEM 82176

#define LDSM4(R0, R1, R2, R3, ADDR)                                            \
    asm volatile("ldmatrix.sync.aligned.m8n8.x4.shared.b16 {%0,%1,%2,%3}, [%4];" \
                 : "=r"(R0), "=r"(R1), "=r"(R2), "=r"(R3) : "r"(ADDR))

#define MMAB(CC, A, B0, B1)                                                    \
    asm volatile(                                                              \
        "mma.sync.aligned.m16n8k16.row.col.f32.bf16.bf16.f32 "                 \
        "{%0,%1,%2,%3}, {%4,%5,%6,%7}, {%8,%9}, {%0,%1,%2,%3};"                \
        : "+f"((CC)[0]), "+f"((CC)[1]), "+f"((CC)[2]), "+f"((CC)[3])           \
        : "r"((A)[0]), "r"((A)[1]), "r"((A)[2]), "r"((A)[3]), "r"(B0), "r"(B1))

#define CPA16(DST, SRC) \
    asm volatile("cp.async.cg.shared.global [%0], [%1], 16;" :: "r"(DST), "l"(SRC))
#define CPA_COMMIT() asm volatile("cp.async.commit_group;" ::: "memory")

__device__ __forceinline__ void kv_issue(uint32_t sb, int kb,
                                         const uint16_t* __restrict__ Khg,
                                         const uint16_t* __restrict__ Klg,
                                         const uint16_t* __restrict__ Vhg,
                                         const uint16_t* __restrict__ Vlg,
                                         int tid)
{
#pragma unroll
    for (int it = 0; it < 3; it++) {
        int idx = tid + it * 256;
        int c = idx / 12, ck = idx % 12;
        const char* sh = (const char*)(Khg + (size_t)(kb * BLK + c) * HD) + ck * 16;
        const char* sl = (const char*)(Klg + (size_t)(kb * BLK + c) * HD) + ck * 16;
        uint32_t d = (uint32_t)(c * QSTR + ck * 8) * 2;
        CPA16(sb + OFF_KH + d, sh);
        CPA16(sb + OFF_KL + d, sl);
    }
#pragma unroll
    for (int it = 0; it < 3; it++) {
        int idx = tid + it * 256;
        int dr = idx / 8, ck = idx % 8;
        const char* sh = (const char*)(Vhg + (size_t)dr * S_LEN + kb * BLK) + ck * 16;
        const char* sl = (const char*)(Vlg + (size_t)dr * S_LEN + kb * BLK) + ck * 16;
        uint32_t d = (uint32_t)(dr * VSTR + ck * 8) * 2;
        CPA16(sb + OFF_VH + d, sh);
        CPA16(sb + OFF_VL + d, sl);
    }
}

__global__ __launch_bounds__(256, 2)
void attn_mma_kernel()
{
    extern __shared__ char smem[];
    const int qb = NB - 1 - blockIdx.x;
    const int h = blockIdx.y, hk = h >> 2;
    const int tid = threadIdx.x;
    int* blist = (int*)(smem + OFF_BL);

    if (tid < 32) {
        int kb = tid;
        const int* mrow = g_maskbuf + (hk * NB + qb) * NB;
        int keep = (kb <= qb) && mrow[kb];
        unsigned bm = __ballot_sync(0xffffffffu, keep);
        if (keep) blist[__popc(bm & ((1u << kb) - 1u))] = kb;
        if (tid == 0) blist[32] = __popc(bm);
    }

    {
        const float scale = rsqrtf((float)HD);
        uint16_t* Qh = (uint16_t*)(smem + OFF_QH);
        uint16_t* Ql = (uint16_t*)(smem + OFF_QL);
        for (int i = tid; i < 64 * 24; i += 256) {
            int r = i / 24, d4 = (i % 24) * 4;
            float4 v = *(const float4*)&g_q[(size_t)(qb * BLK + r) * (NH * HD) + h * HD + d4];
            v.x *= scale; v.y *= scale; v.z *= scale; v.w *= scale;
            ushort4 hi, lo;
            split1(v.x, hi.x, lo.x); split1(v.y, hi.y, lo.y);
            split1(v.z, hi.z, lo.z); split1(v.w, hi.w, lo.w);
            *(ushort4*)&Qh[r * QSTR + d4] = hi;
            *(ushort4*)&Ql[r * QSTR + d4] = lo;
        }
    }
    __syncthreads();

    const int nblk = blist[32];
    const int lane = tid & 31, warp = tid >> 5;
    const int wr = warp & 3;
    const int ch = warp >> 2;
    const int row0 = wr * 16;
    const int g    = lane & 7, quad = lane >> 3;
    const int gid  = lane >> 2, tig = lane & 3;
    const uint32_t sb = (uint32_t)__cvta_generic_to_shared(smem);

    const uint16_t* Khg = g_kbh + (size_t)hk * S_LEN * HD;
    const uint16_t* Klg = g_kbl + (size_t)hk * S_LEN * HD;
    const uint16_t* Vhg = g_vth + (size_t)hk * HD * S_LEN;
    const uint16_t* Vlg = g_vtl + (size_t)hk * HD * S_LEN;

    float* pm = (float*)(smem + OFF_PM);
    float* ps = (float*)(smem + OFF_PS);

    float o[12][4];
#pragma unroll
    for (int dt = 0; dt < 12; dt++)
#pragma unroll
        for (int e = 0; e < 4; e++) o[dt][e] = 0.f;
    float m0 = -1e30f, m1 = -1e30f, l0 = 0.f, l1 = 0.f;

    const int kr = g + ((quad >> 1) << 3);
    const int kd = (quad & 1) << 3;
    const int qar = row0 + g + ((quad & 1) << 3);
    const int qad = (quad & 2) << 2;

    kv_issue(sb, blist[0], Khg, Klg, Vhg, Vlg, tid);
    CPA_COMMIT();

    for (int i = 0; i < nblk; i++) {
        const int kb = blist[i];
        asm volatile("cp.async.wait_group 0;" ::: "memory");
        __syncthreads();

        const uint32_t khb = sb + OFF_KH, klb = sb + OFF_KL;
        const uint32_t vhb = sb + OFF_VH, vlb = sb + OFF_VL;

        float st[4][4];
#pragma unroll
        for (int nt = 0; nt < 4; nt++)
#pragma unroll
            for (int e = 0; e < 4; e++) st[nt][e] = 0.f;

#pragma unroll
        for (int ks = 0; ks < 6; ks++) {
            uint32_t qh[4], ql[4];
            {
                uint32_t qoff = (uint32_t)(qar * QSTR + ks * 16 + qad) * 2u;
                LDSM4(qh[0], qh[1], qh[2], qh[3], sb + OFF_QH + qoff);
                LDSM4(ql[0], ql[1], ql[2], ql[3], sb + OFF_QL + qoff);
            }
#pragma unroll
            for (int j = 0; j < 2; j++) {
                const int ng = ch * 2 + j;
                uint32_t off = (uint32_t)((ng * 16 + kr) * QSTR + ks * 16 + kd) * 2u;
                uint32_t b0, b1, b2, b3, c0, c1, c2, c3;
                LDSM4(b0, b1, b2, b3, khb + off);
                LDSM4(c0, c1, c2, c3, klb + off);
                MMAB(st[2 * j],     qh, b0, b1);
                MMAB(st[2 * j + 1], qh, b2, b3);
                MMAB(st[2 * j],     qh, c0, c1);
                MMAB(st[2 * j + 1], qh, c2, c3);
                MMAB(st[2 * j],     ql, b0, b1);
                MMAB(st[2 * j + 1], ql, b2, b3);
            }
        }

        if (kb == qb) {
            const int rA = row0 + gid, rB = rA + 8;
#pragma unroll
            for (int nt = 0; nt < 4; nt++) {
                int cb = ch * 32 + nt * 8 + tig * 2;
                if (cb     > rA) st[nt][0] = -1e30f;
                if (cb + 1 > rA) st[nt][1] = -1e30f;
                if (cb     > rB) st[nt][2] = -1e30f;
                if (cb + 1 > rB) st[nt][3] = -1e30f;
            }
        }

        float mA = -1e30f, mB = -1e30f;
#pragma unroll
        for (int nt = 0; nt < 4; nt++) {
            mA = fmaxf(mA, fmaxf(st[nt][0], st[nt][1]));
            mB = fmaxf(mB, fmaxf(st[nt][2], st[nt][3]));
        }
        mA = fmaxf(mA, __shfl_xor_sync(0xffffffffu, mA, 1));
        mA = fmaxf(mA, __shfl_xor_sync(0xffffffffu, mA, 2));
        mB = fmaxf(mB, __shfl_xor_sync(0xffffffffu, mB, 1));
        mB = fmaxf(mB, __shfl_xor_sync(0xffffffffu, mB, 2));

        float nmA = fmaxf(m0, mA), nmB = fmaxf(m1, mB);
        float cA = __expf(m0 - nmA), cB = __expf(m1 - nmB);
        float sA = 0.f, sB = 0.f;
#pragma unroll
        for (int nt = 0; nt < 4; nt++) {
            st[nt][0] = __expf(st[nt][0] - nmA); sA += st[nt][0];
            st[nt][1] = __expf(st[nt][1] - nmA); sA += st[nt][1];
            st[nt][2] = __expf(st[nt][2] - nmB); sB += st[nt][2];
            st[nt][3] = __expf(st[nt][3] - nmB); sB += st[nt][3];
        }
        sA += __shfl_xor_sync(0xffffffffu, sA, 1);
        sA += __shfl_xor_sync(0xffffffffu, sA, 2);
        sB += __shfl_xor_sync(0xffffffffu, sB, 1);
        sB += __shfl_xor_sync(0xffffffffu, sB, 2);
        l0 = l0 * cA + sA; m0 = nmA;
        l1 = l1 * cB + sB; m1 = nmB;
#pragma unroll
        for (int dt = 0; dt < 12; dt++) {
            o[dt][0] *= cA; o[dt][1] *= cA;
            o[dt][2] *= cB; o[dt][3] *= cB;
        }

        uint32_t ph[2][4], pl[2][4];
#pragma unroll
        for (int j = 0; j < 2; j++) {
            ph[j][0] = split2(st[2 * j][0],     st[2 * j][1],     pl[j][0]);
            ph[j][1] = split2(st[2 * j][2],     st[2 * j][3],     pl[j][1]);
            ph[j][2] = split2(st[2 * j + 1][0], st[2 * j + 1][1], pl[j][2]);
            ph[j][3] = split2(st[2 * j + 1][2], st[2 * j + 1][3], pl[j][3]);
        }

#pragma unroll
        for (int dt = 0; dt < 12; dt++) {
            uint32_t off = (uint32_t)((dt * 8 + g) * VSTR + ch * 32 + quad * 8) * 2u;
            uint32_t v0, v1, v2, v3, w0, w1, w2, w3;
            LDSM4(v0, v1, v2, v3, vhb + off);
            LDSM4(w0, w1, w2, w3, vlb + off);
            MMAB(o[dt], ph[0], v0, v1);
            MMAB(o[dt], ph[0], w0, w1);
            MMAB(o[dt], pl[0], v0, v1);
            MMAB(o[dt], ph[1], v2, v3);
            MMAB(o[dt], ph[1], w2, w3);
            MMAB(o[dt], pl[1], v2, v3);
        }

        __syncthreads();
        if (i + 1 < nblk) {
            kv_issue(sb, blist[i + 1], Khg, Klg, Vhg, Vlg, tid);
            CPA_COMMIT();
        }
    }

    if (tig == 0) {
        pm[ch * 64 + row0 + gid]     = m0;
        pm[ch * 64 + row0 + gid + 8] = m1;
        ps[ch * 64 + row0 + gid]     = l0;
        ps[ch * 64 + row0 + gid + 8] = l1;
    }
    __syncthreads();
    float mo0 = pm[(ch ^ 1) * 64 + row0 + gid];
    float mo1 = pm[(ch ^ 1) * 64 + row0 + gid + 8];
    float lo0 = ps[(ch ^ 1) * 64 + row0 + gid];
    float lo1 = ps[(ch ^ 1) * 64 + row0 + gid + 8];
    float M0 = fmaxf(m0, mo0), M1 = fmaxf(m1, mo1);
    float sc0 = __expf(m0 - M0), sc1 = __expf(m1 - M1);
    float L0 = l0 * sc0 + lo0 * __expf(mo0 - M0);
    float L1 = l1 * sc1 + lo1 * __expf(mo1 - M1);
#pragma unroll
    for (int dt = 0; dt < 12; dt++) {
        o[dt][0] *= sc0; o[dt][1] *= sc0;
        o[dt][2] *= sc1; o[dt][3] *= sc1;
    }

    float* Obuf = (float*)(smem + OFF_OB);
    __syncthreads();
    if (ch == 1) {
#pragma unroll
        for (int dt = 0; dt < 12; dt++) {
            int col = dt * 8 + tig * 2;
            *(float2*)&Obuf[(row0 + gid) * 100 + col] =
                make_float2(o[dt][0], o[dt][1]);
            *(float2*)&Obuf[(row0 + gid + 8) * 100 + col] =
                make_float2(o[dt][2], o[dt][3]);
        }
    }
    __syncthreads();
    if (ch == 0) {
        const float iA = 1.f / L0, iB = 1.f / L1;
        const int rA = qb * BLK + row0 + gid;
#pragma unroll
        for (int dt = 0; dt < 12; dt++) {
            int col = dt * 8 + tig * 2;
            float2 oa = *(float2*)&Obuf[(row0 + gid) * 100 + col];
            float2 ob = *(float2*)&Obuf[(row0 + gid + 8) * 100 + col];
            float x0 = (o[dt][0] + oa.x) * iA;
            float x1 = (o[dt][1] + oa.y) * iA;
            float x2 = (o[dt][2] + ob.x) * iB;
            float x3 = (o[dt][3] + ob.y) * iB;
            int k2 = (h * HD + col) >> 1;
            uint32_t loA, loB;
            uint32_t hiA = split2(x0, x1, loA);
            uint32_t hiB = split2(x2, x3, loB);
            g_ah[(size_t)rA * K2H + k2]       = hiA;
            g_al[(size_t)rA * K2H + k2]       = loA;
            g_ah[(size_t)(rA + 8) * K2H + k2] = hiB;
            g_al[(size_t)(rA + 8) * K2H + k2] = loB;
        }
    }
}

// ---------------------------------------------------------------------------
// Launch
// ---------------------------------------------------------------------------
extern "C" void kernel_launch(void* const* d_in, const int* in_sizes, int n_in,
                              void* d_out, int out_size)
{
    const float* hs      = (const float*)d_in[0];
    const float* cosb    = (const float*)d_in[1];
    const float* sinb    = (const float*)d_in[2];
    const float* qkv_w   = (const float*)d_in[3];
    const float* o_w     = (const float*)d_in[4];
    const float* gate_wq = (const float*)d_in[5];
    const float* gate_wk = (const float*)d_in[6];
    float* out = (float*)d_out;

    void *p_qkv, *p_ah, *p_al, *p_wqh, *p_wql, *p_woh, *p_wol;
    cudaGetSymbolAddress(&p_qkv, g_qkv);
    cudaGetSymbolAddress(&p_ah, g_ah);
    cudaGetSymbolAddress(&p_al, g_al);
    cudaGetSymbolAddress(&p_wqh, g_wqh);
    cudaGetSymbolAddress(&p_wql, g_wql);
    cudaGetSymbolAddress(&p_woh, g_woh);
    cudaGetSymbolAddress(&p_wol, g_wol);

    // 0. Pack GEMM operands into bf16 hi/lo
    {
        int totW1 = K2H * OP;
        packB_kernel<<<(totW1 + 255) / 256, 256>>>(
            qkv_w, (uint32_t*)p_wqh, (uint32_t*)p_wql, OP, totW1);
        int totW2 = K2H * HIDDEN;
        packB_kernel<<<(totW2 + 255) / 256, 256>>>(
            o_w, (uint32_t*)p_woh, (uint32_t*)p_wol, HIDDEN, totW2);
        int totA = S_LEN * K2H;
        packA_kernel<<<(totA + 255) / 256, 256>>>(
            hs, (uint32_t*)p_ah, (uint32_t*)p_al, totA);
    }

    cudaFuncSetAttribute(bf16x3_gemm,
                         cudaFuncAttributeMaxDynamicSharedMemorySize, GEMM_SMEM);

    // 1. QKV projection (bf16x3, BK=32, 2-stage cp.async)
    bf16x3_gemm<<<dim3(OP / 128, S_LEN / 128), 256, GEMM_SMEM>>>(
        (const uint32_t*)p_ah, (const uint32_t*)p_al,
        (const uint32_t*)p_wqh, (const uint32_t*)p_wql,
        (float*)p_qkv, S_LEN, OP, K2H);

    // 2. RoPE (Q fp32; K directly to bf16 hi/lo)
    {
        int total = S_LEN * (NH + NHK) * HD;
        rope_kernel<<<(total + 255) / 256, 256>>>(cosb, sinb);
    }

    // 2b. Pre-convert V^T to bf16 hi/lo
    convV_kernel<<<dim3(S_LEN / 32, HD / 32, NHK), 256>>>();

    // 3. Fused pool+gate, then mask
    poolgate_kernel<<<dim3(NB, NHK), GH>>>(gate_wq, gate_wk);
    mask_kernel<<<dim3(NB, NHK), 32>>>();

    // 4. Block-sparse flash attention v3 (split-softmax, occ 2)
    cudaFuncSetAttribute(attn_mma_kernel,
                         cudaFuncAttributeMaxDynamicSharedMemorySize, ATTN_SMEM);
    attn_mma_kernel<<<dim3(NB, NH), 256, ATTN_SMEM>>>();

    // 5. Output projection (bf16x3, BK=32, 2-stage cp.async)
    bf16x3_gemm<<<dim3(HIDDEN / 128, S_LEN / 128), 256, GEMM_SMEM>>>(
        (const uint32_t*)p_ah, (const uint32_t*)p_al,
        (const uint32_t*)p_woh, (const uint32_t*)p_wol,
        out, S_LEN, HIDDEN, HIDDEN / 2);
}

// round 17
// speedup vs baseline: 1.7826x; 1.0066x over previous
#include <cuda_runtime.h>
#include <cuda_bf16.h>
#include <cstdint>
#include <math.h>

// ---------------------------------------------------------------------------
// Problem constants
// ---------------------------------------------------------------------------
#define S_LEN   2048
#define HIDDEN  3072
#define NH      32
#define NHK     8
#define GQ      4
#define HD      96
#define BLK     64
#define NB      32
#define GH      128
#define OP      4608
#define KOFF    3072
#define VOFF    3840
#define K2H     (HIDDEN / 2)

// ---------------------------------------------------------------------------
// Scratch (device globals; no allocation allowed)
// ---------------------------------------------------------------------------
__device__ float g_qkv [S_LEN * OP];
__device__ float g_q   [S_LEN * NH  * HD];
__device__ float g_qgate[NB * NHK * GH];
__device__ float g_kgate[NB * NHK * GH];
__device__ int   g_maskbuf[NHK * NB * NB];

// bf16 hi/lo packed GEMM operands (k-pairs packed into one uint32)
__device__ uint32_t g_ah [S_LEN * K2H];       // A hi (hs, then attn out)
__device__ uint32_t g_al [S_LEN * K2H];       // A lo
__device__ uint32_t g_wqh[K2H * OP];
__device__ uint32_t g_wql[K2H * OP];
__device__ uint32_t g_woh[K2H * HIDDEN];
__device__ uint32_t g_wol[K2H * HIDDEN];

// Pre-converted attention operands (bf16 hi/lo)
__device__ uint16_t g_kbh[NHK * S_LEN * HD];  // K  [hk][t][d]  (roped)
__device__ uint16_t g_kbl[NHK * S_LEN * HD];
__device__ uint16_t g_vth[NHK * HD * S_LEN];  // V^T [hk][d][t]
__device__ uint16_t g_vtl[NHK * HD * S_LEN];

// ---------------------------------------------------------------------------
// bf16 hi/lo split helpers
// ---------------------------------------------------------------------------
__device__ __forceinline__ void bsplit(float x, uint32_t& h, uint32_t& l)
{
    __nv_bfloat16 hb = __float2bfloat16(x);
    float hf = __bfloat162float(hb);
    __nv_bfloat16 lb = __float2bfloat16(x - hf);
    h = (uint32_t)__bfloat16_as_ushort(hb);
    l = (uint32_t)__bfloat16_as_ushort(lb);
}

__device__ __forceinline__ void split1(float x, uint16_t& h, uint16_t& l)
{
    __nv_bfloat16 hb = __float2bfloat16(x);
    h = __bfloat16_as_ushort(hb);
    l = __bfloat16_as_ushort(__float2bfloat16(x - __bfloat162float(hb)));
}

__device__ __forceinline__ uint32_t split2(float x, float y, uint32_t& lo)
{
    __nv_bfloat16 hx = __float2bfloat16(x), hy = __float2bfloat16(y);
    float rx = x - __bfloat162float(hx), ry = y - __bfloat162float(hy);
    __nv_bfloat16 lx = __float2bfloat16(rx), ly = __float2bfloat16(ry);
    lo = (uint32_t)__bfloat16_as_ushort(lx) | ((uint32_t)__bfloat16_as_ushort(ly) << 16);
    return (uint32_t)__bfloat16_as_ushort(hx) | ((uint32_t)__bfloat16_as_ushort(hy) << 16);
}

// Pack A (row-major M x K): word i = (x[2i], x[2i+1]) along k
__global__ void packA_kernel(const float* __restrict__ in,
                             uint32_t* __restrict__ hi, uint32_t* __restrict__ lo,
                             int total2)
{
    int i = blockIdx.x * blockDim.x + threadIdx.x;
    if (i >= total2) return;
    float2 v = ((const float2*)in)[i];
    uint32_t h0, l0, h1, l1;
    bsplit(v.x, h0, l0);
    bsplit(v.y, h1, l1);
    hi[i] = h0 | (h1 << 16);
    lo[i] = l0 | (l1 << 16);
}

// Pack B (row-major K x N): out[k2][n] = (B[2k2][n], B[2k2+1][n])
__global__ void packB_kernel(const float* __restrict__ in,
                             uint32_t* __restrict__ hi, uint32_t* __restrict__ lo,
                             int N, int total)
{
    int i = blockIdx.x * blockDim.x + threadIdx.x;
    if (i >= total) return;
    int k2 = i / N, n = i - k2 * N;
    float x0 = in[(size_t)(2 * k2) * N + n];
    float x1 = in[(size_t)(2 * k2 + 1) * N + n];
    uint32_t h0, l0, h1, l1;
    bsplit(x0, h0, l0);
    bsplit(x1, h1, l1);
    hi[i] = h0 | (h1 << 16);
    lo[i] = l0 | (l1 << 16);
}

// V pre-convert + transpose: g_qkv [s][VOFF+hk*HD+d] -> g_vth/g_vtl [hk][d][s]
__global__ void convV_kernel()
{
    __shared__ float t[32][33];
    const int s0 = blockIdx.x * 32, d0 = blockIdx.y * 32, hk = blockIdx.z;
    const int tx = threadIdx.x & 31, ty = threadIdx.x >> 5;
#pragma unroll
    for (int i = 0; i < 32; i += 8)
        t[ty + i][tx] = g_qkv[(size_t)(s0 + ty + i) * OP + VOFF + hk * HD + d0 + tx];
    __syncthreads();
#pragma unroll
    for (int i = 0; i < 32; i += 8) {
        float v = t[tx][ty + i];
        uint16_t h, l;
        split1(v, h, l);
        size_t o = ((size_t)hk * HD + d0 + ty + i) * S_LEN + s0 + tx;
        g_vth[o] = h;
        g_vtl[o] = l;
    }
}

// ---------------------------------------------------------------------------
// bf16x3 tensor-core GEMM, cp.async 3-stage, BK=16, 3-pass MMA ordering.
// (R15 configuration — measured optimum: 451.8us QKV, tensor 63.2%.)
// ---------------------------------------------------------------------------
#define ASTRW 12
#define BSTRW 136
#define GOFF_AH(s) ((s) * 6144)
#define GOFF_AL(s) (18432 + (s) * 6144)
#define GOFF_BH(s) (36864 + (s) * 4352)
#define GOFF_BL(s) (49920 + (s) * 4352)
#define GEMM_SMEM 62976

#define MMA_BF16(CC, A0, A1, A2, A3, B0, B1)                                   \
    asm volatile(                                                              \
        "mma.sync.aligned.m16n8k16.row.col.f32.bf16.bf16.f32 "                 \
        "{%0,%1,%2,%3}, {%4,%5,%6,%7}, {%8,%9}, {%0,%1,%2,%3};"                \
        : "+f"(CC[0]), "+f"(CC[1]), "+f"(CC[2]), "+f"(CC[3])                   \
        : "r"(A0), "r"(A1), "r"(A2), "r"(A3), "r"(B0), "r"(B1))

#define GCPA16(DST, SRC) \
    asm volatile("cp.async.cg.shared.global [%0], [%1], 16;" :: "r"(DST), "l"(SRC))
#define GCPA_COMMIT() asm volatile("cp.async.commit_group;" ::: "memory")

__global__ __launch_bounds__(256, 2)
void bf16x3_gemm(const uint32_t* __restrict__ Agh, const uint32_t* __restrict__ Agl,
                 const uint32_t* __restrict__ Bgh, const uint32_t* __restrict__ Bgl,
                 float* __restrict__ C, int M, int N, int K2)
{
    extern __shared__ uint32_t gsm[];

    const int tid  = threadIdx.x;
    const int bn   = blockIdx.x, bm = blockIdx.y;
    const int warp = tid >> 5,  lane = tid & 31;
    const int wm   = warp >> 2, wn   = warp & 3;
    const int gid  = lane >> 2, tig  = lane & 3;
    const uint32_t sb = (uint32_t)__cvta_generic_to_shared(gsm);

    const int a_r = tid >> 1, a_h = (tid & 1) * 4;
    const int b_r = tid >> 5, b_c = (tid & 31) * 4;

    const uint32_t* ApH = Agh + (size_t)(bm * 128 + a_r) * K2 + a_h;
    const uint32_t* ApL = Agl + (size_t)(bm * 128 + a_r) * K2 + a_h;
    const uint32_t* BpH = Bgh + (size_t)b_r * N + bn * 128 + b_c;
    const uint32_t* BpL = Bgl + (size_t)b_r * N + bn * 128 + b_c;
    const uint32_t a_dst = (uint32_t)(a_r * ASTRW + a_h) * 4;
    const uint32_t b_dst = (uint32_t)(b_r * BSTRW + b_c) * 4;

    const int nst = K2 >> 3;

#define GEMM_ISSUE(S)                                                          \
    do {                                                                       \
        const int _b = (S) % 3;                                                \
        GCPA16(sb + GOFF_AH(_b) + a_dst, ApH + (S) * 8);                       \
        GCPA16(sb + GOFF_AL(_b) + a_dst, ApL + (S) * 8);                       \
        GCPA16(sb + GOFF_BH(_b) + b_dst, BpH + (size_t)(S) * 8 * N);           \
        GCPA16(sb + GOFF_BL(_b) + b_dst, BpL + (size_t)(S) * 8 * N);           \
        GCPA_COMMIT();                                                         \
    } while (0)

    GEMM_ISSUE(0);
    if (nst > 1) GEMM_ISSUE(1);

    float acc[4][4][4];
#pragma unroll
    for (int mt = 0; mt < 4; mt++)
#pragma unroll
        for (int nt = 0; nt < 4; nt++)
#pragma unroll
            for (int r = 0; r < 4; r++) acc[mt][nt][r] = 0.f;

    for (int st = 0; st < nst; st++) {
        const int b = st % 3;
        if (st + 1 < nst) asm volatile("cp.async.wait_group 1;" ::: "memory");
        else              asm volatile("cp.async.wait_group 0;" ::: "memory");
        __syncthreads();

        const uint32_t* Ah = gsm + GOFF_AH(b) / 4;
        const uint32_t* Al = gsm + GOFF_AL(b) / 4;
        const uint32_t* Bh = gsm + GOFF_BH(b) / 4;
        const uint32_t* Bl = gsm + GOFF_BL(b) / 4;

        uint32_t bhf[4][2], blf[4][2];
#pragma unroll
        for (int nt = 0; nt < 4; nt++) {
            const int n0 = wn * 32 + nt * 8;
            bhf[nt][0] = Bh[tig * BSTRW + n0 + gid];
            bhf[nt][1] = Bh[(tig + 4) * BSTRW + n0 + gid];
            blf[nt][0] = Bl[tig * BSTRW + n0 + gid];
            blf[nt][1] = Bl[(tig + 4) * BSTRW + n0 + gid];
        }

        // Pass 1: hi*hi
#pragma unroll
        for (int mt = 0; mt < 4; mt++) {
            const int m0 = wm * 64 + mt * 16;
            uint32_t a0 = Ah[(m0 + gid) * ASTRW + tig];
            uint32_t a1 = Ah[(m0 + gid + 8) * ASTRW + tig];
            uint32_t a2 = Ah[(m0 + gid) * ASTRW + tig + 4];
            uint32_t a3 = Ah[(m0 + gid + 8) * ASTRW + tig + 4];
#pragma unroll
            for (int nt = 0; nt < 4; nt++)
                MMA_BF16(acc[mt][nt], a0, a1, a2, a3, bhf[nt][0], bhf[nt][1]);
        }
        // Pass 2: hi*lo
#pragma unroll
        for (int mt = 0; mt < 4; mt++) {
            const int m0 = wm * 64 + mt * 16;
            uint32_t a0 = Ah[(m0 + gid) * ASTRW + tig];
            uint32_t a1 = Ah[(m0 + gid + 8) * ASTRW + tig];
            uint32_t a2 = Ah[(m0 + gid) * ASTRW + tig + 4];
            uint32_t a3 = Ah[(m0 + gid + 8) * ASTRW + tig + 4];
#pragma unroll
            for (int nt = 0; nt < 4; nt++)
                MMA_BF16(acc[mt][nt], a0, a1, a2, a3, blf[nt][0], blf[nt][1]);
        }
        // Pass 3: lo*hi
#pragma unroll
        for (int mt = 0; mt < 4; mt++) {
            const int m0 = wm * 64 + mt * 16;
            uint32_t a0 = Al[(m0 + gid) * ASTRW + tig];
            uint32_t a1 = Al[(m0 + gid + 8) * ASTRW + tig];
            uint32_t a2 = Al[(m0 + gid) * ASTRW + tig + 4];
            uint32_t a3 = Al[(m0 + gid + 8) * ASTRW + tig + 4];
#pragma unroll
            for (int nt = 0; nt < 4; nt++)
                MMA_BF16(acc[mt][nt], a0, a1, a2, a3, bhf[nt][0], bhf[nt][1]);
        }

        if (st + 2 < nst) GEMM_ISSUE(st + 2);
    }
#undef GEMM_ISSUE

#pragma unroll
    for (int mt = 0; mt < 4; mt++) {
        const int row = bm * 128 + wm * 64 + mt * 16 + gid;
#pragma unroll
        for (int nt = 0; nt < 4; nt++) {
            const int col = bn * 128 + wn * 32 + nt * 8 + tig * 2;
            *(float2*)&C[(size_t)row * N + col] =
                make_float2(acc[mt][nt][0], acc[mt][nt][1]);
            *(float2*)&C[(size_t)(row + 8) * N + col] =
                make_float2(acc[mt][nt][2], acc[mt][nt][3]);
        }
    }
}

// ---------------------------------------------------------------------------
// RoPE: q -> g_q (fp32); k -> g_kbh/g_kbl (bf16 hi/lo, [hk][s][d]) directly.
// ---------------------------------------------------------------------------
__global__ void rope_kernel(const float* __restrict__ cosb,
                            const float* __restrict__ sinb)
{
    const int total = S_LEN * (NH + NHK) * HD;
    int idx = blockIdx.x * blockDim.x + threadIdx.x;
    if (idx >= total) return;
    int d = idx % HD;
    int h = (idx / HD) % (NH + NHK);
    int s = idx / (HD * (NH + NHK));
    const float* row = g_qkv + (size_t)s * OP;
    float c  = cosb[s * HD + d];
    float sn = sinb[s * HD + d];
    if (h < NH) {
        int base = h * HD;
        float x = row[base + d];
        float r = (d < HD / 2) ? -row[base + d + HD / 2] : row[base + d - HD / 2];
        g_q[(size_t)s * (NH * HD) + h * HD + d] = x * c + r * sn;
    } else {
        int hk = h - NH;
        int base = KOFF + hk * HD;
        float x = row[base + d];
        float r = (d < HD / 2) ? -row[base + d + HD / 2] : row[base + d - HD / 2];
        float kv = x * c + r * sn;
        uint16_t kh, kl;
        split1(kv, kh, kl);
        size_t o = ((size_t)hk * S_LEN + s) * HD + d;
        g_kbh[o] = kh;
        g_kbl[o] = kl;
    }
}

// ---------------------------------------------------------------------------
// Fused pool + gate: grid (NB, NHK), 128 threads.
// ---------------------------------------------------------------------------
__global__ void poolgate_kernel(const float* __restrict__ gate_wq,
                                const float* __restrict__ gate_wk)
{
    __shared__ float qp[HD], kp[2 * HD];
    const int nb = blockIdx.x, hk = blockIdx.y, tid = threadIdx.x;

    if (tid < HD) {
        float ksum = 0.f, kmax = -3.0e38f, qsum = 0.f;
#pragma unroll 4
        for (int t = 0; t < BLK; t++) {
            const float* row = g_qkv + (size_t)(nb * BLK + t) * OP;
            float kv = row[KOFF + hk * HD + tid];
            ksum += kv;
            kmax = fmaxf(kmax, kv);
#pragma unroll
            for (int g = 0; g < GQ; g++) qsum += row[(hk * GQ + g) * HD + tid];
        }
        kp[tid]      = ksum * (1.f / BLK);
        kp[HD + tid] = kmax;
        qp[tid]      = qsum * (1.f / (BLK * GQ));
    }
    __syncthreads();

    const int g = tid;
    float qa = 0.f;
#pragma unroll 8
    for (int d = 0; d < HD; d++)
        qa += qp[d] * gate_wq[d * GH + g];
    float ka = 0.f;
#pragma unroll 8
    for (int e = 0; e < 2 * HD; e++)
        ka += kp[e] * gate_wk[e * GH + g];
    int bh = nb * NHK + hk;
    g_qgate[bh * GH + g] = qa;
    g_kgate[bh * GH + g] = ka;
}

__global__ void mask_kernel()
{
    int qb = blockIdx.x, hk = blockIdx.y, kb = threadIdx.x;
    float l = -1e30f;
    if (kb <= qb) {
        float dot = 0.f;
#pragma unroll 8
        for (int g = 0; g < GH; g++)
            dot += g_qgate[(size_t)(qb * NHK + hk) * GH + g]
                 * g_kgate[(size_t)(kb * NHK + hk) * GH + g];
        l = dot * rsqrtf((float)GH);
    }
    float mx = l;
#pragma unroll
    for (int o = 16; o > 0; o >>= 1) mx = fmaxf(mx, __shfl_xor_sync(0xffffffffu, mx, o));
    float e = expf(l - mx);
    float sm = e;
#pragma unroll
    for (int o = 16; o > 0; o >>= 1) sm += __shfl_xor_sync(0xffffffffu, sm, o);
    float p = e / sm;
    int keep = ((p >= 0.03f) && (kb <= qb)) || (kb == qb);
    g_maskbuf[(hk * NB + qb) * NB + kb] = keep;
}

// ---------------------------------------------------------------------------
// Block-sparse flash attention v3 (unchanged)
// ---------------------------------------------------------------------------
#define QSTR 104
#define VSTR 72

#define OFF_QH  0
#define OFF_QL  13312
#define OFF_KH  26624
#define OFF_KL  39936
#define OFF_VH  53248
#define OFF_VL  67072
#define OFF_PM  80896
#define OFF_PS  81408
#define OFF_BL  81920
#define OFF_OB  0
#define ATTN_SMEM 82176

#define LDSM4(R0, R1, R2, R3, ADDR)                                            \
    asm volatile("ldmatrix.sync.aligned.m8n8.x4.shared.b16 {%0,%1,%2,%3}, [%4];" \
                 : "=r"(R0), "=r"(R1), "=r"(R2), "=r"(R3) : "r"(ADDR))

#define MMAB(CC, A, B0, B1)                                                    \
    asm volatile(                                                              \
        "mma.sync.aligned.m16n8k16.row.col.f32.bf16.bf16.f32 "                 \
        "{%0,%1,%2,%3}, {%4,%5,%6,%7}, {%8,%9}, {%0,%1,%2,%3};"                \
        : "+f"((CC)[0]), "+f"((CC)[1]), "+f"((CC)[2]), "+f"((CC)[3])           \
        : "r"((A)[0]), "r"((A)[1]), "r"((A)[2]), "r"((A)[3]), "r"(B0), "r"(B1))

#define CPA16(DST, SRC) \
    asm volatile("cp.async.cg.shared.global [%0], [%1], 16;" :: "r"(DST), "l"(SRC))
#define CPA_COMMIT() asm volatile("cp.async.commit_group;" ::: "memory")

__device__ __forceinline__ void kv_issue(uint32_t sb, int kb,
                                         const uint16_t* __restrict__ Khg,
                                         const uint16_t* __restrict__ Klg,
                                         const uint16_t* __restrict__ Vhg,
                                         const uint16_t* __restrict__ Vlg,
                                         int tid)
{
#pragma unroll
    for (int it = 0; it < 3; it++) {
        int idx = tid + it * 256;
        int c = idx / 12, ck = idx % 12;
        const char* sh = (const char*)(Khg + (size_t)(kb * BLK + c) * HD) + ck * 16;
        const char* sl = (const char*)(Klg + (size_t)(kb * BLK + c) * HD) + ck * 16;
        uint32_t d = (uint32_t)(c * QSTR + ck * 8) * 2;
        CPA16(sb + OFF_KH + d, sh);
        CPA16(sb + OFF_KL + d, sl);
    }
#pragma unroll
    for (int it = 0; it < 3; it++) {
        int idx = tid + it * 256;
        int dr = idx / 8, ck = idx % 8;
        const char* sh = (const char*)(Vhg + (size_t)dr * S_LEN + kb * BLK) + ck * 16;
        const char* sl = (const char*)(Vlg + (size_t)dr * S_LEN + kb * BLK) + ck * 16;
        uint32_t d = (uint32_t)(dr * VSTR + ck * 8) * 2;
        CPA16(sb + OFF_VH + d, sh);
        CPA16(sb + OFF_VL + d, sl);
    }
}

__global__ __launch_bounds__(256, 2)
void attn_mma_kernel()
{
    extern __shared__ char smem[];
    const int qb = NB - 1 - blockIdx.x;
    const int h = blockIdx.y, hk = h >> 2;
    const int tid = threadIdx.x;
    int* blist = (int*)(smem + OFF_BL);

    if (tid < 32) {
        int kb = tid;
        const int* mrow = g_maskbuf + (hk * NB + qb) * NB;
        int keep = (kb <= qb) && mrow[kb];
        unsigned bm = __ballot_sync(0xffffffffu, keep);
        if (keep) blist[__popc(bm & ((1u << kb) - 1u))] = kb;
        if (tid == 0) blist[32] = __popc(bm);
    }

    {
        const float scale = rsqrtf((float)HD);
        uint16_t* Qh = (uint16_t*)(smem + OFF_QH);
        uint16_t* Ql = (uint16_t*)(smem + OFF_QL);
        for (int i = tid; i < 64 * 24; i += 256) {
            int r = i / 24, d4 = (i % 24) * 4;
            float4 v = *(const float4*)&g_q[(size_t)(qb * BLK + r) * (NH * HD) + h * HD + d4];
            v.x *= scale; v.y *= scale; v.z *= scale; v.w *= scale;
            ushort4 hi, lo;
            split1(v.x, hi.x, lo.x); split1(v.y, hi.y, lo.y);
            split1(v.z, hi.z, lo.z); split1(v.w, hi.w, lo.w);
            *(ushort4*)&Qh[r * QSTR + d4] = hi;
            *(ushort4*)&Ql[r * QSTR + d4] = lo;
        }
    }
    __syncthreads();

    const int nblk = blist[32];
    const int lane = tid & 31, warp = tid >> 5;
    const int wr = warp & 3;
    const int ch = warp >> 2;
    const int row0 = wr * 16;
    const int g    = lane & 7, quad = lane >> 3;
    const int gid  = lane >> 2, tig = lane & 3;
    const uint32_t sb = (uint32_t)__cvta_generic_to_shared(smem);

    const uint16_t* Khg = g_kbh + (size_t)hk * S_LEN * HD;
    const uint16_t* Klg = g_kbl + (size_t)hk * S_LEN * HD;
    const uint16_t* Vhg = g_vth + (size_t)hk * HD * S_LEN;
    const uint16_t* Vlg = g_vtl + (size_t)hk * HD * S_LEN;

    float* pm = (float*)(smem + OFF_PM);
    float* ps = (float*)(smem + OFF_PS);

    float o[12][4];
#pragma unroll
    for (int dt = 0; dt < 12; dt++)
#pragma unroll
        for (int e = 0; e < 4; e++) o[dt][e] = 0.f;
    float m0 = -1e30f, m1 = -1e30f, l0 = 0.f, l1 = 0.f;

    const int kr = g + ((quad >> 1) << 3);
    const int kd = (quad & 1) << 3;
    const int qar = row0 + g + ((quad & 1) << 3);
    const int qad = (quad & 2) << 2;

    kv_issue(sb, blist[0], Khg, Klg, Vhg, Vlg, tid);
    CPA_COMMIT();

    for (int i = 0; i < nblk; i++) {
        const int kb = blist[i];
        asm volatile("cp.async.wait_group 0;" ::: "memory");
        __syncthreads();

        const uint32_t khb = sb + OFF_KH, klb = sb + OFF_KL;
        const uint32_t vhb = sb + OFF_VH, vlb = sb + OFF_VL;

        float st[4][4];
#pragma unroll
        for (int nt = 0; nt < 4; nt++)
#pragma unroll
            for (int e = 0; e < 4; e++) st[nt][e] = 0.f;

#pragma unroll
        for (int ks = 0; ks < 6; ks++) {
            uint32_t qh[4], ql[4];
            {
                uint32_t qoff = (uint32_t)(qar * QSTR + ks * 16 + qad) * 2u;
                LDSM4(qh[0], qh[1], qh[2], qh[3], sb + OFF_QH + qoff);
                LDSM4(ql[0], ql[1], ql[2], ql[3], sb + OFF_QL + qoff);
            }
#pragma unroll
            for (int j = 0; j < 2; j++) {
                const int ng = ch * 2 + j;
                uint32_t off = (uint32_t)((ng * 16 + kr) * QSTR + ks * 16 + kd) * 2u;
                uint32_t b0, b1, b2, b3, c0, c1, c2, c3;
                LDSM4(b0, b1, b2, b3, khb + off);
                LDSM4(c0, c1, c2, c3, klb + off);
                MMAB(st[2 * j],     qh, b0, b1);
                MMAB(st[2 * j + 1], qh, b2, b3);
                MMAB(st[2 * j],     qh, c0, c1);
                MMAB(st[2 * j + 1], qh, c2, c3);
                MMAB(st[2 * j],     ql, b0, b1);
                MMAB(st[2 * j + 1], ql, b2, b3);
            }
        }

        if (kb == qb) {
            const int rA = row0 + gid, rB = rA + 8;
#pragma unroll
            for (int nt = 0; nt < 4; nt++) {
                int cb = ch * 32 + nt * 8 + tig * 2;
                if (cb     > rA) st[nt][0] = -1e30f;
                if (cb + 1 > rA) st[nt][1] = -1e30f;
                if (cb     > rB) st[nt][2] = -1e30f;
                if (cb + 1 > rB) st[nt][3] = -1e30f;
            }
        }

        float mA = -1e30f, mB = -1e30f;
#pragma unroll
        for (int nt = 0; nt < 4; nt++) {
            mA = fmaxf(mA, fmaxf(st[nt][0], st[nt][1]));
            mB = fmaxf(mB, fmaxf(st[nt][2], st[nt][3]));
        }
        mA = fmaxf(mA, __shfl_xor_sync(0xffffffffu, mA, 1));
        mA = fmaxf(mA, __shfl_xor_sync(0xffffffffu, mA, 2));
        mB = fmaxf(mB, __shfl_xor_sync(0xffffffffu, mB, 1));
        mB = fmaxf(mB, __shfl_xor_sync(0xffffffffu, mB, 2));

        float nmA = fmaxf(m0, mA), nmB = fmaxf(m1, mB);
        float cA = __expf(m0 - nmA), cB = __expf(m1 - nmB);
        float sA = 0.f, sB = 0.f;
#pragma unroll
        for (int nt = 0; nt < 4; nt++) {
            st[nt][0] = __expf(st[nt][0] - nmA); sA += st[nt][0];
            st[nt][1] = __expf(st[nt][1] - nmA); sA += st[nt][1];
            st[nt][2] = __expf(st[nt][2] - nmB); sB += st[nt][2];
            st[nt][3] = __expf(st[nt][3] - nmB); sB += st[nt][3];
        }
        sA += __shfl_xor_sync(0xffffffffu, sA, 1);
        sA += __shfl_xor_sync(0xffffffffu, sA, 2);
        sB += __shfl_xor_sync(0xffffffffu, sB, 1);
        sB += __shfl_xor_sync(0xffffffffu, sB, 2);
        l0 = l0 * cA + sA; m0 = nmA;
        l1 = l1 * cB + sB; m1 = nmB;
#pragma unroll
        for (int dt = 0; dt < 12; dt++) {
            o[dt][0] *= cA; o[dt][1] *= cA;
            o[dt][2] *= cB; o[dt][3] *= cB;
        }

        uint32_t ph[2][4], pl[2][4];
#pragma unroll
        for (int j = 0; j < 2; j++) {
            ph[j][0] = split2(st[2 * j][0],     st[2 * j][1],     pl[j][0]);
            ph[j][1] = split2(st[2 * j][2],     st[2 * j][3],     pl[j][1]);
            ph[j][2] = split2(st[2 * j + 1][0], st[2 * j + 1][1], pl[j][2]);
            ph[j][3] = split2(st[2 * j + 1][2], st[2 * j + 1][3], pl[j][3]);
        }

#pragma unroll
        for (int dt = 0; dt < 12; dt++) {
            uint32_t off = (uint32_t)((dt * 8 + g) * VSTR + ch * 32 + quad * 8) * 2u;
            uint32_t v0, v1, v2, v3, w0, w1, w2, w3;
            LDSM4(v0, v1, v2, v3, vhb + off);
            LDSM4(w0, w1, w2, w3, vlb + off);
            MMAB(o[dt], ph[0], v0, v1);
            MMAB(o[dt], ph[0], w0, w1);
            MMAB(o[dt], pl[0], v0, v1);
            MMAB(o[dt], ph[1], v2, v3);
            MMAB(o[dt], ph[1], w2, w3);
            MMAB(o[dt], pl[1], v2, v3);
        }

        __syncthreads();
        if (i + 1 < nblk) {
            kv_issue(sb, blist[i + 1], Khg, Klg, Vhg, Vlg, tid);
            CPA_COMMIT();
        }
    }

    if (tig == 0) {
        pm[ch * 64 + row0 + gid]     = m0;
        pm[ch * 64 + row0 + gid + 8] = m1;
        ps[ch * 64 + row0 + gid]     = l0;
        ps[ch * 64 + row0 + gid + 8] = l1;
    }
    __syncthreads();
    float mo0 = pm[(ch ^ 1) * 64 + row0 + gid];
    float mo1 = pm[(ch ^ 1) * 64 + row0 + gid + 8];
    float lo0 = ps[(ch ^ 1) * 64 + row0 + gid];
    float lo1 = ps[(ch ^ 1) * 64 + row0 + gid + 8];
    float M0 = fmaxf(m0, mo0), M1 = fmaxf(m1, mo1);
    float sc0 = __expf(m0 - M0), sc1 = __expf(m1 - M1);
    float L0 = l0 * sc0 + lo0 * __expf(mo0 - M0);
    float L1 = l1 * sc1 + lo1 * __expf(mo1 - M1);
#pragma unroll
    for (int dt = 0; dt < 12; dt++) {
        o[dt][0] *= sc0; o[dt][1] *= sc0;
        o[dt][2] *= sc1; o[dt][3] *= sc1;
    }

    float* Obuf = (float*)(smem + OFF_OB);
    __syncthreads();
    if (ch == 1) {
#pragma unroll
        for (int dt = 0; dt < 12; dt++) {
            int col = dt * 8 + tig * 2;
            *(float2*)&Obuf[(row0 + gid) * 100 + col] =
                make_float2(o[dt][0], o[dt][1]);
            *(float2*)&Obuf[(row0 + gid + 8) * 100 + col] =
                make_float2(o[dt][2], o[dt][3]);
        }
    }
    __syncthreads();
    if (ch == 0) {
        const float iA = 1.f / L0, iB = 1.f / L1;
        const int rA = qb * BLK + row0 + gid;
#pragma unroll
        for (int dt = 0; dt < 12; dt++) {
            int col = dt * 8 + tig * 2;
            float2 oa = *(float2*)&Obuf[(row0 + gid) * 100 + col];
            float2 ob = *(float2*)&Obuf[(row0 + gid + 8) * 100 + col];
            float x0 = (o[dt][0] + oa.x) * iA;
            float x1 = (o[dt][1] + oa.y) * iA;
            float x2 = (o[dt][2] + ob.x) * iB;
            float x3 = (o[dt][3] + ob.y) * iB;
            int k2 = (h * HD + col) >> 1;
            uint32_t loA, loB;
            uint32_t hiA = split2(x0, x1, loA);
            uint32_t hiB = split2(x2, x3, loB);
            g_ah[(size_t)rA * K2H + k2]       = hiA;
            g_al[(size_t)rA * K2H + k2]       = loA;
            g_ah[(size_t)(rA + 8) * K2H + k2] = hiB;
            g_al[(size_t)(rA + 8) * K2H + k2] = loB;
        }
    }
}

// ---------------------------------------------------------------------------
// Launch
// ---------------------------------------------------------------------------
extern "C" void kernel_launch(void* const* d_in, const int* in_sizes, int n_in,
                              void* d_out, int out_size)
{
    const float* hs      = (const float*)d_in[0];
    const float* cosb    = (const float*)d_in[1];
    const float* sinb    = (const float*)d_in[2];
    const float* qkv_w   = (const float*)d_in[3];
    const float* o_w     = (const float*)d_in[4];
    const float* gate_wq = (const float*)d_in[5];
    const float* gate_wk = (const float*)d_in[6];
    float* out = (float*)d_out;

    void *p_qkv, *p_ah, *p_al, *p_wqh, *p_wql, *p_woh, *p_wol;
    cudaGetSymbolAddress(&p_qkv, g_qkv);
    cudaGetSymbolAddress(&p_ah, g_ah);
    cudaGetSymbolAddress(&p_al, g_al);
    cudaGetSymbolAddress(&p_wqh, g_wqh);
    cudaGetSymbolAddress(&p_wql, g_wql);
    cudaGetSymbolAddress(&p_woh, g_woh);
    cudaGetSymbolAddress(&p_wol, g_wol);

    // 0. Pack GEMM operands into bf16 hi/lo
    {
        int totW1 = K2H * OP;
        packB_kernel<<<(totW1 + 255) / 256, 256>>>(
            qkv_w, (uint32_t*)p_wqh, (uint32_t*)p_wql, OP, totW1);
        int totW2 = K2H * HIDDEN;
        packB_kernel<<<(totW2 + 255) / 256, 256>>>(
            o_w, (uint32_t*)p_woh, (uint32_t*)p_wol, HIDDEN, totW2);
        int totA = S_LEN * K2H;
        packA_kernel<<<(totA + 255) / 256, 256>>>(
            hs, (uint32_t*)p_ah, (uint32_t*)p_al, totA);
    }

    cudaFuncSetAttribute(bf16x3_gemm,
                         cudaFuncAttributeMaxDynamicSharedMemorySize, GEMM_SMEM);

    // 1. QKV projection (bf16x3, BK=16, 3-stage cp.async, 3-pass MMA)
    bf16x3_gemm<<<dim3(OP / 128, S_LEN / 128), 256, GEMM_SMEM>>>(
        (const uint32_t*)p_ah, (const uint32_t*)p_al,
        (const uint32_t*)p_wqh, (const uint32_t*)p_wql,
        (float*)p_qkv, S_LEN, OP, K2H);

    // 2. RoPE (Q fp32; K directly to bf16 hi/lo)
    {
        int total = S_LEN * (NH + NHK) * HD;
        rope_kernel<<<(total + 255) / 256, 256>>>(cosb, sinb);
    }

    // 2b. Pre-convert V^T to bf16 hi/lo
    convV_kernel<<<dim3(S_LEN / 32, HD / 32, NHK), 256>>>();

    // 3. Fused pool+gate, then mask
    poolgate_kernel<<<dim3(NB, NHK), GH>>>(gate_wq, gate_wk);
    mask_kernel<<<dim3(NB, NHK), 32>>>();

    // 4. Block-sparse flash attention v3 (split-softmax, occ 2)
    cudaFuncSetAttribute(attn_mma_kernel,
                         cudaFuncAttributeMaxDynamicSharedMemorySize, ATTN_SMEM);
    attn_mma_kernel<<<dim3(NB, NH), 256, ATTN_SMEM>>>();

    // 5. Output projection (bf16x3, BK=16, 3-stage cp.async, 3-pass MMA)
    bf16x3_gemm<<<dim3(HIDDEN / 128, S_LEN / 128), 256, GEMM_SMEM>>>(
        (const uint32_t*)p_ah, (const uint32_t*)p_al,
        (const uint32_t*)p_woh, (const uint32_t*)p_wol,
        out, S_LEN, HIDDEN, HIDDEN / 2);
}